// round 7
// baseline (speedup 1.0000x reference)
#include <cuda_runtime.h>
#include <cuda_bf16.h>
#include <cstdint>

// ---------------------------------------------------------------------------
// SphereViT forward — split-bf16 HMMA everywhere (GEMMs + attention).
// R7: fix qk_mma tile loader (was loading only half of each Q/K tile -> NaN).
// ---------------------------------------------------------------------------

#define BATCH     32
#define NTOK      128
#define ROWS      4096
#define DIMV      1024
#define PATCHDIM  3072
#define NHEADS    16
#define DHEAD     64
#define DEPTH     12
#define LN_EPS    1e-5f

// -------------------- scratch (device globals; no allocs) ------------------
__device__ float g_big[ROWS * PATCHDIM];                 // expand output
__device__ float g_x  [ROWS * DIMV];                     // residual stream
__device__ float g_w  [BATCH * NHEADS * NTOK * NTOK];    // attention scores fp32

// split-bf16 activations
__device__ __nv_bfloat16 g_Xph[ROWS * PATCHDIM], g_Xpl[ROWS * PATCHDIM];
__device__ __nv_bfloat16 g_qkvh[ROWS * PATCHDIM], g_qkvl[ROWS * PATCHDIM];
__device__ __nv_bfloat16 g_hh [ROWS * DIMV],     g_hl [ROWS * DIMV];
__device__ __nv_bfloat16 g_oh [ROWS * DIMV],     g_ol [ROWS * DIMV];
__device__ __nv_bfloat16 g_ph [BATCH*NHEADS*NTOK*NTOK], g_pl [BATCH*NHEADS*NTOK*NTOK];

// split-bf16 transposed weights ([N,K] K-major)
__device__ __nv_bfloat16 g_cwh[DIMV * PATCHDIM],          g_cwl[DIMV * PATCHDIM];
__device__ __nv_bfloat16 g_nlwh[DIMV * DIMV],             g_nlwl[DIMV * DIMV];
__device__ __nv_bfloat16 g_qwh[DEPTH * PATCHDIM * DIMV],  g_qwl[DEPTH * PATCHDIM * DIMV];
__device__ __nv_bfloat16 g_owh[DEPTH * DIMV * DIMV],      g_owl[DEPTH * DIMV * DIMV];
__device__ __nv_bfloat16 g_ewh[PATCHDIM * DIMV],          g_ewl[PATCHDIM * DIMV];

// ---------------------------------------------------------------------------
// PTX helpers
// ---------------------------------------------------------------------------
__device__ __forceinline__ uint32_t smem_u32(const void* p) {
    uint32_t a;
    asm("{ .reg .u64 t; cvta.to.shared.u64 t, %1; cvt.u32.u64 %0, t; }"
        : "=r"(a) : "l"(p));
    return a;
}
__device__ __forceinline__ void cpa16(uint32_t dst, const void* src) {
    asm volatile("cp.async.cg.shared.global [%0], [%1], 16;" :: "r"(dst), "l"(src));
}
__device__ __forceinline__ void cp_commit() { asm volatile("cp.async.commit_group;"); }
template <int NN>
__device__ __forceinline__ void cp_wait() {
    asm volatile("cp.async.wait_group %0;" :: "n"(NN));
}
__device__ __forceinline__ void ldsm4(uint32_t* r, uint32_t addr) {
    asm volatile("ldmatrix.sync.aligned.m8n8.x4.shared.b16 {%0,%1,%2,%3}, [%4];"
                 : "=r"(r[0]), "=r"(r[1]), "=r"(r[2]), "=r"(r[3]) : "r"(addr));
}
__device__ __forceinline__ void mma16816(float* c, const uint32_t* a,
                                         const uint32_t* b) {
    asm volatile(
        "mma.sync.aligned.m16n8k16.row.col.f32.bf16.bf16.f32 "
        "{%0,%1,%2,%3}, {%4,%5,%6,%7}, {%8,%9}, {%0,%1,%2,%3};"
        : "+f"(c[0]), "+f"(c[1]), "+f"(c[2]), "+f"(c[3])
        : "r"(a[0]), "r"(a[1]), "r"(a[2]), "r"(a[3]), "r"(b[0]), "r"(b[1]));
}
__device__ __forceinline__ void split2(float v, __nv_bfloat16& h, __nv_bfloat16& l) {
    h = __float2bfloat16(v);
    l = __float2bfloat16(v - __bfloat162float(h));
}

// ---------------------------------------------------------------------------
// Split-bf16 HMMA GEMM: C = (Ah+Al)[M,K] @ (Bh+Bl)[N,K]^T (+bias)(+res)
// OUTSPLIT: write split-bf16 (Ch,Cl) instead of fp32 C.
// ---------------------------------------------------------------------------
#define GPAD 8
#define GLDS (32 + GPAD)
#define OPND_ELEMS (128 * GLDS)
#define STAGE_ELEMS (4 * OPND_ELEMS)
#define HG_SMEM (2 * STAGE_ELEMS * 2)    // 81920 bytes

template <bool OUTSPLIT>
__global__ __launch_bounds__(256, 2) void hmma_gemm_kernel(
    const __nv_bfloat16* __restrict__ Ah, const __nv_bfloat16* __restrict__ Al,
    const __nv_bfloat16* __restrict__ Bh, const __nv_bfloat16* __restrict__ Bl,
    const float* __restrict__ bias, const float* __restrict__ res,
    float* __restrict__ C, __nv_bfloat16* __restrict__ Ch,
    __nv_bfloat16* __restrict__ Cl, int M, int N, int K)
{
    extern __shared__ __nv_bfloat16 smem[];
    const uint32_t sbase = smem_u32(smem);
    const int tid  = threadIdx.x;
    const int lane = tid & 31, warp = tid >> 5;
    const int wm = warp & 1, wn = warp >> 1;
    const int m0 = blockIdx.y << 7, n0 = blockIdx.x << 7;

    const __nv_bfloat16* g[4] = {
        Ah + (size_t)m0 * K, Al + (size_t)m0 * K,
        Bh + (size_t)n0 * K, Bl + (size_t)n0 * K };

    const int r0c = tid >> 2;
    const int c0c = tid & 3;

    auto issue = [&](int stage, int k0) {
#pragma unroll
        for (int op = 0; op < 4; op++) {
            uint32_t sdst = sbase + (uint32_t)(stage * STAGE_ELEMS + op * OPND_ELEMS) * 2;
            const __nv_bfloat16* gs = g[op];
#pragma unroll
            for (int half = 0; half < 2; half++) {
                int r = r0c + half * 64;
                cpa16(sdst + (uint32_t)(r * GLDS + c0c * 8) * 2,
                      gs + (size_t)r * K + k0 + c0c * 8);
            }
        }
    };

    float acc[4][4][4];
#pragma unroll
    for (int i = 0; i < 4; i++)
#pragma unroll
        for (int j = 0; j < 4; j++)
#pragma unroll
            for (int q = 0; q < 4; q++) acc[i][j][q] = 0.f;

    const int nk = K >> 5;
    issue(0, 0);
    cp_commit();

    const int arow = wm * 64 + (lane & 15);
    const int acolb = (lane >> 4) * 8;
    const int brow = wn * 32 + ((lane >> 4) * 8) + (lane & 7);
    const int bcolb = ((lane >> 3) & 1) * 8;

    for (int it = 0; it < nk; ++it) {
        const int s = it & 1;
        if (it + 1 < nk) {
            issue(s ^ 1, (it + 1) << 5);
            cp_commit();
            cp_wait<1>();
        } else {
            cp_wait<0>();
        }
        __syncthreads();

        uint32_t sA  = sbase + (uint32_t)(s * STAGE_ELEMS) * 2;
        uint32_t sAl = sA + OPND_ELEMS * 2;
        uint32_t sB  = sA + 2 * OPND_ELEMS * 2;
        uint32_t sBl = sA + 3 * OPND_ELEMS * 2;

#pragma unroll
        for (int ks = 0; ks < 2; ks++) {
            const int acol = ks * 16 + acolb;
            const int bcol = ks * 16 + bcolb;
            uint32_t ah[4][4], bh[4][2];
#pragma unroll
            for (int mi = 0; mi < 4; mi++)
                ldsm4(ah[mi], sA + (uint32_t)((arow + mi * 16) * GLDS + acol) * 2);
#pragma unroll
            for (int gp = 0; gp < 2; gp++) {
                uint32_t rh[4];
                ldsm4(rh, sB + (uint32_t)((brow + gp * 16) * GLDS + bcol) * 2);
                bh[gp*2][0] = rh[0]; bh[gp*2][1] = rh[1];
                bh[gp*2+1][0] = rh[2]; bh[gp*2+1][1] = rh[3];
            }
#pragma unroll
            for (int mi = 0; mi < 4; mi++)
#pragma unroll
                for (int nj = 0; nj < 4; nj++)
                    mma16816(acc[mi][nj], ah[mi], bh[nj]);

            uint32_t bl[4][2];
#pragma unroll
            for (int gp = 0; gp < 2; gp++) {
                uint32_t rl[4];
                ldsm4(rl, sBl + (uint32_t)((brow + gp * 16) * GLDS + bcol) * 2);
                bl[gp*2][0] = rl[0]; bl[gp*2][1] = rl[1];
                bl[gp*2+1][0] = rl[2]; bl[gp*2+1][1] = rl[3];
            }
#pragma unroll
            for (int mi = 0; mi < 4; mi++)
#pragma unroll
                for (int nj = 0; nj < 4; nj++)
                    mma16816(acc[mi][nj], ah[mi], bl[nj]);

            uint32_t al[4][4];
#pragma unroll
            for (int mi = 0; mi < 4; mi++)
                ldsm4(al[mi], sAl + (uint32_t)((arow + mi * 16) * GLDS + acol) * 2);
#pragma unroll
            for (int mi = 0; mi < 4; mi++)
#pragma unroll
                for (int nj = 0; nj < 4; nj++)
                    mma16816(acc[mi][nj], al[mi], bh[nj]);
        }
        __syncthreads();
    }

    // epilogue
#pragma unroll
    for (int mi = 0; mi < 4; mi++) {
        int r0 = m0 + wm * 64 + mi * 16 + (lane >> 2);
#pragma unroll
        for (int nj = 0; nj < 4; nj++) {
            int c = n0 + wn * 32 + nj * 8 + (lane & 3) * 2;
            float v0x = acc[mi][nj][0], v0y = acc[mi][nj][1];
            float v1x = acc[mi][nj][2], v1y = acc[mi][nj][3];
            size_t o0 = (size_t)r0 * N + c;
            size_t o1 = o0 + (size_t)8 * N;
            if (OUTSPLIT) {
                __nv_bfloat16 h0, l0, h1, l1;
                __nv_bfloat162 hp, lp;
                split2(v0x, h0, l0); split2(v0y, h1, l1);
                hp.x = h0; hp.y = h1; lp.x = l0; lp.y = l1;
                *(__nv_bfloat162*)(Ch + o0) = hp;
                *(__nv_bfloat162*)(Cl + o0) = lp;
                split2(v1x, h0, l0); split2(v1y, h1, l1);
                hp.x = h0; hp.y = h1; lp.x = l0; lp.y = l1;
                *(__nv_bfloat162*)(Ch + o1) = hp;
                *(__nv_bfloat162*)(Cl + o1) = lp;
            } else {
                if (bias) {
                    float bx = bias[c], by = bias[c + 1];
                    v0x += bx; v0y += by; v1x += bx; v1y += by;
                }
                if (res) {
                    float2 ra = *(const float2*)(res + o0);
                    float2 rb = *(const float2*)(res + o1);
                    v0x += ra.x; v0y += ra.y; v1x += rb.x; v1y += rb.y;
                }
                *(float2*)(C + o0) = make_float2(v0x, v0y);
                *(float2*)(C + o1) = make_float2(v1x, v1y);
            }
        }
    }
}

// ---------------------------------------------------------------------------
// qk via HMMA: W[b,h,i,j] = (q_i.k_j)*0.125*(1+dist). One CTA per (b,h).
// A=q split [128][64], B=k split [128][64].  SMEM tiles 128x(64+8).
// ---------------------------------------------------------------------------
#define QKLD 72
#define QK_TILE (128 * QKLD)             // 9216 elems
#define QK_SMEM (4 * QK_TILE * 2)        // 73728 bytes

__global__ __launch_bounds__(256, 2) void qk_mma_kernel(
    const __nv_bfloat16* __restrict__ qkvh, const __nv_bfloat16* __restrict__ qkvl,
    const float* __restrict__ dist, float* __restrict__ W)
{
    extern __shared__ __nv_bfloat16 smem[];
    const uint32_t sbase = smem_u32(smem);
    const int tid = threadIdx.x, lane = tid & 31, warp = tid >> 5;
    const int wm = warp & 1, wn = warp >> 1;
    const int b = blockIdx.x >> 4, h = blockIdx.x & 15;
    const size_t rowbase = (size_t)b * NTOK * PATCHDIM + h * DHEAD;

    // tiles: 0=Qh 1=Ql 2=Kh 3=Kl.  Each tile: 128 rows x 64 bf16 = 1024 chunks.
    const __nv_bfloat16* srcs[4] = { qkvh, qkvl, qkvh, qkvl };
    const int offs[4] = { 0, 0, DIMV, DIMV };
#pragma unroll
    for (int t = 0; t < 4; t++) {
        uint32_t dbase = sbase + (uint32_t)(t * QK_TILE) * 2;
#pragma unroll
        for (int p = 0; p < 4; p++) {
            int q = tid + p * 256;       // 0..1023
            int r = q >> 3, c = q & 7;   // row, 8-elem chunk
            cpa16(dbase + (uint32_t)(r * QKLD + c * 8) * 2,
                  srcs[t] + rowbase + (size_t)r * PATCHDIM + offs[t] + c * 8);
        }
    }
    cp_commit();
    cp_wait<0>();
    __syncthreads();

    float acc[4][4][4];
#pragma unroll
    for (int i = 0; i < 4; i++)
#pragma unroll
        for (int j = 0; j < 4; j++)
#pragma unroll
            for (int q = 0; q < 4; q++) acc[i][j][q] = 0.f;

    uint32_t sA  = sbase;
    uint32_t sAl = sbase + (uint32_t)QK_TILE * 2;
    uint32_t sB  = sbase + (uint32_t)(2 * QK_TILE) * 2;
    uint32_t sBl = sbase + (uint32_t)(3 * QK_TILE) * 2;
    const int arow = wm * 64 + (lane & 15);
    const int acolb = (lane >> 4) * 8;
    const int brow = wn * 32 + ((lane >> 4) * 8) + (lane & 7);
    const int bcolb = ((lane >> 3) & 1) * 8;

#pragma unroll
    for (int ks = 0; ks < 4; ks++) {
        const int acol = ks * 16 + acolb;
        const int bcol = ks * 16 + bcolb;
        uint32_t ah[4][4], bh[4][2];
#pragma unroll
        for (int mi = 0; mi < 4; mi++)
            ldsm4(ah[mi], sA + (uint32_t)((arow + mi * 16) * QKLD + acol) * 2);
#pragma unroll
        for (int gp = 0; gp < 2; gp++) {
            uint32_t rh[4];
            ldsm4(rh, sB + (uint32_t)((brow + gp * 16) * QKLD + bcol) * 2);
            bh[gp*2][0] = rh[0]; bh[gp*2][1] = rh[1];
            bh[gp*2+1][0] = rh[2]; bh[gp*2+1][1] = rh[3];
        }
#pragma unroll
        for (int mi = 0; mi < 4; mi++)
#pragma unroll
            for (int nj = 0; nj < 4; nj++)
                mma16816(acc[mi][nj], ah[mi], bh[nj]);

        uint32_t bl[4][2];
#pragma unroll
        for (int gp = 0; gp < 2; gp++) {
            uint32_t rl[4];
            ldsm4(rl, sBl + (uint32_t)((brow + gp * 16) * QKLD + bcol) * 2);
            bl[gp*2][0] = rl[0]; bl[gp*2][1] = rl[1];
            bl[gp*2+1][0] = rl[2]; bl[gp*2+1][1] = rl[3];
        }
#pragma unroll
        for (int mi = 0; mi < 4; mi++)
#pragma unroll
            for (int nj = 0; nj < 4; nj++)
                mma16816(acc[mi][nj], ah[mi], bl[nj]);

        uint32_t al[4][4];
#pragma unroll
        for (int mi = 0; mi < 4; mi++)
            ldsm4(al[mi], sAl + (uint32_t)((arow + mi * 16) * QKLD + acol) * 2);
#pragma unroll
        for (int mi = 0; mi < 4; mi++)
#pragma unroll
            for (int nj = 0; nj < 4; nj++)
                mma16816(acc[mi][nj], al[mi], bh[nj]);
    }

    float* Wb = W + (size_t)blockIdx.x * (NTOK * NTOK);
#pragma unroll
    for (int mi = 0; mi < 4; mi++) {
        int i0 = wm * 64 + mi * 16 + (lane >> 2);
#pragma unroll
        for (int nj = 0; nj < 4; nj++) {
            int j0 = wn * 32 + nj * 8 + (lane & 3) * 2;
#pragma unroll
            for (int rr = 0; rr < 2; rr++) {
                int i = i0 + rr * 8;
                float vx = acc[mi][nj][rr*2], vy = acc[mi][nj][rr*2+1];
                Wb[i * 128 + j0]     = vx * 0.125f * (1.0f + dist[i * 128 + j0]);
                Wb[i * 128 + j0 + 1] = vy * 0.125f * (1.0f + dist[i * 128 + j0 + 1]);
            }
        }
    }
}

// ---------------------------------------------------------------------------
// Cross-head standardize (ddof=1) + softmax; emits split-bf16 P.
// ---------------------------------------------------------------------------
__global__ __launch_bounds__(128) void std_softmax_kernel(
    const float* __restrict__ W,
    __nv_bfloat16* __restrict__ Ph, __nv_bfloat16* __restrict__ Pl)
{
    int b = blockIdx.x >> 7, i = blockIdx.x & 127;
    int j = threadIdx.x;
    __shared__ float sm[NHEADS][128];

    size_t base = (size_t)b * (NHEADS * NTOK * NTOK) + (size_t)i * 128 + j;
    float vals[NHEADS];
    float s = 0.f;
#pragma unroll
    for (int h = 0; h < NHEADS; h++) {
        float v = W[base + (size_t)h * (NTOK * NTOK)];
        vals[h] = v; s += v;
    }
    float mu = s * (1.0f / 16.0f);
    float d2 = 0.f;
#pragma unroll
    for (int h = 0; h < NHEADS; h++) {
        float d = vals[h] - mu;
        d2 += d * d;
    }
    float inv = rsqrtf(d2 * (1.0f / 15.0f));
#pragma unroll
    for (int h = 0; h < NHEADS; h++) sm[h][j] = (vals[h] - mu) * inv;
    __syncthreads();

    int warp = j >> 5, lane = j & 31;
#pragma unroll
    for (int r = 0; r < 4; r++) {
        int h = warp * 4 + r;
        float v0 = sm[h][lane], v1 = sm[h][lane + 32];
        float v2 = sm[h][lane + 64], v3 = sm[h][lane + 96];
        float m = fmaxf(fmaxf(v0, v1), fmaxf(v2, v3));
#pragma unroll
        for (int o = 16; o; o >>= 1) m = fmaxf(m, __shfl_xor_sync(0xffffffffu, m, o));
        float e0 = expf(v0 - m), e1 = expf(v1 - m);
        float e2 = expf(v2 - m), e3 = expf(v3 - m);
        float sum = e0 + e1 + e2 + e3;
#pragma unroll
        for (int o = 16; o; o >>= 1) sum += __shfl_xor_sync(0xffffffffu, sum, o);
        float rs = 1.0f / sum;
        size_t wb = (size_t)b * (NHEADS * NTOK * NTOK) + (size_t)h * (NTOK * NTOK)
                  + (size_t)i * 128;
        float p0 = e0 * rs, p1 = e1 * rs, p2 = e2 * rs, p3 = e3 * rs;
        __nv_bfloat16 hh, ll;
        split2(p0, hh, ll); Ph[wb + lane]      = hh; Pl[wb + lane]      = ll;
        split2(p1, hh, ll); Ph[wb + lane + 32] = hh; Pl[wb + lane + 32] = ll;
        split2(p2, hh, ll); Ph[wb + lane + 64] = hh; Pl[wb + lane + 64] = ll;
        split2(p3, hh, ll); Ph[wb + lane + 96] = hh; Pl[wb + lane + 96] = ll;
    }
}

// ---------------------------------------------------------------------------
// av via HMMA: O[i, h*64+d] = sum_j P[i,j] * V[j,d].  One CTA per (b,h).
// A = P split [128 i][128 j]; B = V^T split [64 d][128 j] (transposed in smem).
// ---------------------------------------------------------------------------
#define AVPLD 136
#define AVP_TILE (128 * AVPLD)           // 17408 elems
#define AVV_TILE (64 * AVPLD)            // 8704 elems
#define AV_SMEM ((2 * AVP_TILE + 2 * AVV_TILE) * 2)   // 104448 bytes

__global__ __launch_bounds__(256, 2) void av_mma_kernel(
    const __nv_bfloat16* __restrict__ Ph, const __nv_bfloat16* __restrict__ Pl,
    const __nv_bfloat16* __restrict__ qkvh, const __nv_bfloat16* __restrict__ qkvl,
    __nv_bfloat16* __restrict__ Oh, __nv_bfloat16* __restrict__ Ol)
{
    extern __shared__ __nv_bfloat16 smem[];
    const uint32_t sbase = smem_u32(smem);
    const int tid = threadIdx.x, lane = tid & 31, warp = tid >> 5;
    const int wm = warp & 3, wn = warp >> 2;
    const int b = blockIdx.x >> 4, h = blockIdx.x & 15;
    const size_t pbase = (size_t)blockIdx.x * (NTOK * NTOK);
    const size_t vbase = (size_t)b * NTOK * PATCHDIM + 2 * DIMV + h * DHEAD;

    // load P hi/lo via cp.async, [i][128] -> [i][AVPLD]
    const __nv_bfloat16* psrc[2] = { Ph, Pl };
#pragma unroll
    for (int t = 0; t < 2; t++) {
        uint32_t dbase = sbase + (uint32_t)(t * AVP_TILE) * 2;
#pragma unroll
        for (int p = 0; p < 8; p++) {
            int q = tid + p * 256;       // 0..2047
            int r = q >> 4, c = q & 15;
            cpa16(dbase + (uint32_t)(r * AVPLD + c * 8) * 2,
                  psrc[t] + pbase + (size_t)r * 128 + c * 8);
        }
    }
    cp_commit();

    // load V hi/lo transposed: [j][64] -> Vt[d][AVPLD] at j
    const __nv_bfloat16* vsrc[2] = { qkvh, qkvl };
#pragma unroll
    for (int t = 0; t < 2; t++) {
        __nv_bfloat16* vt = smem + 2 * AVP_TILE + t * AVV_TILE;
#pragma unroll
        for (int p = 0; p < 4; p++) {
            int q = tid + p * 256;       // 0..1023
            int j = q >> 3, c = q & 7;
            uint4 u = *(const uint4*)(vsrc[t] + vbase + (size_t)j * PATCHDIM + c * 8);
            const __nv_bfloat16* vv = (const __nv_bfloat16*)&u;
#pragma unroll
            for (int e = 0; e < 8; e++)
                vt[(c * 8 + e) * AVPLD + j] = vv[e];
        }
    }
    cp_wait<0>();
    __syncthreads();

    float acc[2][4][4];
#pragma unroll
    for (int i = 0; i < 2; i++)
#pragma unroll
        for (int j = 0; j < 4; j++)
#pragma unroll
            for (int q = 0; q < 4; q++) acc[i][j][q] = 0.f;

    uint32_t sA  = sbase;
    uint32_t sAl = sbase + (uint32_t)AVP_TILE * 2;
    uint32_t sB  = sbase + (uint32_t)(2 * AVP_TILE) * 2;
    uint32_t sBl = sB + (uint32_t)AVV_TILE * 2;
    const int arow = wm * 32 + (lane & 15);
    const int acolb = (lane >> 4) * 8;
    const int brow = wn * 32 + ((lane >> 4) * 8) + (lane & 7);
    const int bcolb = ((lane >> 3) & 1) * 8;

#pragma unroll
    for (int kc = 0; kc < 8; kc++) {
        const int acol = kc * 16 + acolb;
        const int bcol = kc * 16 + bcolb;
        uint32_t ah[2][4], bh[4][2];
#pragma unroll
        for (int mi = 0; mi < 2; mi++)
            ldsm4(ah[mi], sA + (uint32_t)((arow + mi * 16) * AVPLD + acol) * 2);
#pragma unroll
        for (int gp = 0; gp < 2; gp++) {
            uint32_t rh[4];
            ldsm4(rh, sB + (uint32_t)((brow + gp * 16) * AVPLD + bcol) * 2);
            bh[gp*2][0] = rh[0]; bh[gp*2][1] = rh[1];
            bh[gp*2+1][0] = rh[2]; bh[gp*2+1][1] = rh[3];
        }
#pragma unroll
        for (int mi = 0; mi < 2; mi++)
#pragma unroll
            for (int nj = 0; nj < 4; nj++)
                mma16816(acc[mi][nj], ah[mi], bh[nj]);

        uint32_t bl[4][2];
#pragma unroll
        for (int gp = 0; gp < 2; gp++) {
            uint32_t rl[4];
            ldsm4(rl, sBl + (uint32_t)((brow + gp * 16) * AVPLD + bcol) * 2);
            bl[gp*2][0] = rl[0]; bl[gp*2][1] = rl[1];
            bl[gp*2+1][0] = rl[2]; bl[gp*2+1][1] = rl[3];
        }
#pragma unroll
        for (int mi = 0; mi < 2; mi++)
#pragma unroll
            for (int nj = 0; nj < 4; nj++)
                mma16816(acc[mi][nj], ah[mi], bl[nj]);

        uint32_t al[2][4];
#pragma unroll
        for (int mi = 0; mi < 2; mi++)
            ldsm4(al[mi], sAl + (uint32_t)((arow + mi * 16) * AVPLD + acol) * 2);
#pragma unroll
        for (int mi = 0; mi < 2; mi++)
#pragma unroll
            for (int nj = 0; nj < 4; nj++)
                mma16816(acc[mi][nj], al[mi], bh[nj]);
    }

#pragma unroll
    for (int mi = 0; mi < 2; mi++) {
        int i0 = wm * 32 + mi * 16 + (lane >> 2);
#pragma unroll
        for (int nj = 0; nj < 4; nj++) {
            int d0 = wn * 32 + nj * 8 + (lane & 3) * 2;
#pragma unroll
            for (int rr = 0; rr < 2; rr++) {
                int i = i0 + rr * 8;
                size_t o = (size_t)(b * 128 + i) * DIMV + h * DHEAD + d0;
                __nv_bfloat16 h0, l0, h1, l1;
                __nv_bfloat162 hp, lp;
                split2(acc[mi][nj][rr*2],     h0, l0);
                split2(acc[mi][nj][rr*2 + 1], h1, l1);
                hp.x = h0; hp.y = h1; lp.x = l0; lp.y = l1;
                *(__nv_bfloat162*)(Oh + o) = hp;
                *(__nv_bfloat162*)(Ol + o) = lp;
            }
        }
    }
}

// ---------------------------------------------------------------------------
// Weight prep
// ---------------------------------------------------------------------------
__global__ void split_kernel(const float* __restrict__ X,
                             __nv_bfloat16* __restrict__ H,
                             __nv_bfloat16* __restrict__ L) {
    size_t i = (size_t)blockIdx.x * 256 + threadIdx.x;
    split2(X[i], H[i], L[i]);
}

__global__ void wtrans_split_kernel(const float* __restrict__ W,
                                    __nv_bfloat16* __restrict__ Th,
                                    __nv_bfloat16* __restrict__ Tl,
                                    int K, int N) {
    __shared__ float t[32][33];
    const float* Wl = W + (size_t)blockIdx.z * K * N;
    size_t ob = (size_t)blockIdx.z * K * N;
    int x = blockIdx.x * 32 + threadIdx.x;
    int y = blockIdx.y * 32 + threadIdx.y;
#pragma unroll
    for (int j = 0; j < 32; j += 8)
        t[threadIdx.y + j][threadIdx.x] = Wl[(size_t)(y + j) * N + x];
    __syncthreads();
    int n = blockIdx.x * 32 + threadIdx.y;
    int k = blockIdx.y * 32 + threadIdx.x;
#pragma unroll
    for (int j = 0; j < 32; j += 8) {
        size_t o = ob + (size_t)(n + j) * K + k;
        split2(t[threadIdx.x][threadIdx.y + j], Th[o], Tl[o]);
    }
}

__global__ void extract_patches_kernel(const float* __restrict__ img,
                                       __nv_bfloat16* __restrict__ H,
                                       __nv_bfloat16* __restrict__ L) {
    int idx = blockIdx.x * 256 + threadIdx.x;
    int col = idx % PATCHDIM;
    int row = idx / PATCHDIM;
    int b = row >> 7, t = row & 127;
    int h = t >> 4, w = t & 15;
    int c = col >> 10, r = col & 1023;
    int p = r >> 5, q = r & 31;
    float v = img[(((size_t)b * 3 + c) * 256 + h * 32 + p) * 512 + w * 32 + q];
    split2(v, H[idx], L[idx]);
}

// ---------------------------------------------------------------------------
// LayerNorm
// ---------------------------------------------------------------------------
__device__ __forceinline__ void ln_stats(const float* __restrict__ x, size_t base,
                                         int D, float& mu, float& rstd) {
    float s = 0.f, ss = 0.f;
    for (int i = threadIdx.x; i < D; i += 256) {
        float v = x[base + i];
        s += v; ss += v * v;
    }
#pragma unroll
    for (int o = 16; o; o >>= 1) {
        s  += __shfl_xor_sync(0xffffffffu, s, o);
        ss += __shfl_xor_sync(0xffffffffu, ss, o);
    }
    __shared__ float sh[2][8];
    int w = threadIdx.x >> 5;
    if ((threadIdx.x & 31) == 0) { sh[0][w] = s; sh[1][w] = ss; }
    __syncthreads();
    if (threadIdx.x < 32) {
        s  = (threadIdx.x < 8) ? sh[0][threadIdx.x] : 0.f;
        ss = (threadIdx.x < 8) ? sh[1][threadIdx.x] : 0.f;
#pragma unroll
        for (int o = 4; o; o >>= 1) {
            s  += __shfl_xor_sync(0xffffffffu, s, o);
            ss += __shfl_xor_sync(0xffffffffu, ss, o);
        }
        if (threadIdx.x == 0) { sh[0][0] = s; sh[1][0] = ss; }
    }
    __syncthreads();
    s = sh[0][0]; ss = sh[1][0];
    float invD = 1.0f / (float)D;
    mu = s * invD;
    float var = ss * invD - mu * mu;
    rstd = rsqrtf(var + LN_EPS);
}

__global__ void ln_kernel(const float* __restrict__ x, const float* __restrict__ g,
                          const float* __restrict__ beta, float* __restrict__ y, int D) {
    size_t base = (size_t)blockIdx.x * D;
    float mu, rstd;
    ln_stats(x, base, D, mu, rstd);
    for (int i = threadIdx.x; i < D; i += 256)
        y[base + i] = (x[base + i] - mu) * rstd * g[i] + beta[i];
}

__global__ void ln_split_kernel(const float* __restrict__ x, const float* __restrict__ g,
                                const float* __restrict__ beta,
                                __nv_bfloat16* __restrict__ H,
                                __nv_bfloat16* __restrict__ L, int D) {
    size_t base = (size_t)blockIdx.x * D;
    float mu, rstd;
    ln_stats(x, base, D, mu, rstd);
    for (int i = threadIdx.x; i < D; i += 256) {
        float v = (x[base + i] - mu) * rstd * g[i] + beta[i];
        split2(v, H[base + i], L[base + i]);
    }
}

__global__ void add_pos_kernel(float* __restrict__ x, const float* __restrict__ sph_pos,
                               const float* __restrict__ pos_w,
                               const float* __restrict__ pos_b) {
    int idx = blockIdx.x * 256 + threadIdx.x;
    int d = idx & 1023;
    int i = (idx >> 10) & 127;
    x[idx] += sph_pos[i * 2] * pos_w[d] + sph_pos[i * 2 + 1] * pos_w[1024 + d] + pos_b[d];
}

__global__ void reassemble_kernel(const float* __restrict__ Y, float* __restrict__ out) {
    int idx = blockIdx.x * 256 + threadIdx.x;
    int xq = idx & 511;
    int rest = idx >> 9;
    int yr = rest & 255;
    rest >>= 8;
    int c = rest % 3;
    int b = rest / 3;
    int h = yr >> 5, p1 = yr & 31, w = xq >> 5, p2 = xq & 31;
    out[idx] = Y[(size_t)(b * 128 + h * 16 + w) * PATCHDIM + (p1 * 32 + p2) * 3 + c];
}

// ---------------------------------------------------------------------------
// Host launcher
// ---------------------------------------------------------------------------
extern "C" void kernel_launch(void* const* d_in, const int* in_sizes, int n_in,
                              void* d_out, int out_size)
{
    const float* img      = (const float*)d_in[0];
    const float* sph_pos  = (const float*)d_in[1];
    const float* sph_dist = (const float*)d_in[2];
    const float* conv_w   = (const float*)d_in[3];
    const float* conv_b   = (const float*)d_in[4];
    const float* nl_ln1_g = (const float*)d_in[5];
    const float* nl_ln1_b = (const float*)d_in[6];
    const float* nl_w     = (const float*)d_in[7];
    const float* nl_b     = (const float*)d_in[8];
    const float* nl_ln2_g = (const float*)d_in[9];
    const float* nl_ln2_b = (const float*)d_in[10];
    const float* pos_w    = (const float*)d_in[11];
    const float* pos_b    = (const float*)d_in[12];
    const float* ln_g     = (const float*)d_in[13];
    const float* ln_b     = (const float*)d_in[14];
    const float* wqkv     = (const float*)d_in[15];
    const float* wo       = (const float*)d_in[16];
    const float* wo_b     = (const float*)d_in[17];
    const float* tr_ln_g  = (const float*)d_in[18];
    const float* tr_ln_b  = (const float*)d_in[19];
    const float* exp_w    = (const float*)d_in[20];
    const float* exp_b    = (const float*)d_in[21];
    const float* out_ln_g = (const float*)d_in[22];
    const float* out_ln_b = (const float*)d_in[23];

    float *big, *x, *w;
    cudaGetSymbolAddress((void**)&big, g_big);
    cudaGetSymbolAddress((void**)&x,   g_x);
    cudaGetSymbolAddress((void**)&w,   g_w);
    __nv_bfloat16 *Xph, *Xpl, *qkvh, *qkvl, *hh, *hl, *oh, *ol, *ph, *pl;
    __nv_bfloat16 *cwh, *cwl, *nlwh, *nlwl, *qwh, *qwl, *owh, *owl, *ewh, *ewl;
    cudaGetSymbolAddress((void**)&Xph, g_Xph);   cudaGetSymbolAddress((void**)&Xpl, g_Xpl);
    cudaGetSymbolAddress((void**)&qkvh, g_qkvh); cudaGetSymbolAddress((void**)&qkvl, g_qkvl);
    cudaGetSymbolAddress((void**)&hh,  g_hh);    cudaGetSymbolAddress((void**)&hl,  g_hl);
    cudaGetSymbolAddress((void**)&oh,  g_oh);    cudaGetSymbolAddress((void**)&ol,  g_ol);
    cudaGetSymbolAddress((void**)&ph,  g_ph);    cudaGetSymbolAddress((void**)&pl,  g_pl);
    cudaGetSymbolAddress((void**)&cwh, g_cwh);   cudaGetSymbolAddress((void**)&cwl, g_cwl);
    cudaGetSymbolAddress((void**)&nlwh,g_nlwh);  cudaGetSymbolAddress((void**)&nlwl,g_nlwl);
    cudaGetSymbolAddress((void**)&qwh, g_qwh);   cudaGetSymbolAddress((void**)&qwl, g_qwl);
    cudaGetSymbolAddress((void**)&owh, g_owh);   cudaGetSymbolAddress((void**)&owl, g_owl);
    cudaGetSymbolAddress((void**)&ewh, g_ewh);   cudaGetSymbolAddress((void**)&ewl, g_ewl);

    cudaFuncSetAttribute(hmma_gemm_kernel<false>,
                         cudaFuncAttributeMaxDynamicSharedMemorySize, HG_SMEM);
    cudaFuncSetAttribute(hmma_gemm_kernel<true>,
                         cudaFuncAttributeMaxDynamicSharedMemorySize, HG_SMEM);
    cudaFuncSetAttribute(qk_mma_kernel,
                         cudaFuncAttributeMaxDynamicSharedMemorySize, QK_SMEM);
    cudaFuncSetAttribute(av_mma_kernel,
                         cudaFuncAttributeMaxDynamicSharedMemorySize, AV_SMEM);

    // ---- prep + patch embedding (hmma at launch #3/#4 for the profiler) ----
    split_kernel<<<DIMV * PATCHDIM / 256, 256>>>(conv_w, cwh, cwl);        // 1
    extract_patches_kernel<<<ROWS * PATCHDIM / 256, 256>>>(img, Xph, Xpl); // 2
    hmma_gemm_kernel<false><<<dim3(DIMV/128, 16), 256, HG_SMEM>>>(         // 3
        Xph, Xpl, cwh, cwl, conv_b, nullptr, x, nullptr, nullptr,
        ROWS, DIMV, PATCHDIM);
    hmma_gemm_kernel<false><<<dim3(DIMV/128, 16), 256, HG_SMEM>>>(         // 4
        Xph + (size_t)2048 * PATCHDIM, Xpl + (size_t)2048 * PATCHDIM,
        cwh, cwl, conv_b, nullptr, x + (size_t)2048 * DIMV, nullptr, nullptr,
        ROWS, DIMV, PATCHDIM);
    wtrans_split_kernel<<<dim3(DIMV/32, DIMV/32, 1),     dim3(32,8)>>>(nl_w,  nlwh, nlwl, DIMV, DIMV);
    wtrans_split_kernel<<<dim3(PATCHDIM/32, DIMV/32, DEPTH), dim3(32,8)>>>(wqkv, qwh, qwl, DIMV, PATCHDIM);
    wtrans_split_kernel<<<dim3(DIMV/32, DIMV/32, DEPTH), dim3(32,8)>>>(wo,    owh,  owl,  DIMV, DIMV);
    wtrans_split_kernel<<<dim3(PATCHDIM/32, DIMV/32, 1), dim3(32,8)>>>(exp_w, ewh,  ewl,  DIMV, PATCHDIM);

    // ---- norm_linear + positional embedding ----
    ln_split_kernel<<<ROWS, 256>>>(x, nl_ln1_g, nl_ln1_b, hh, hl, DIMV);
    hmma_gemm_kernel<false><<<dim3(DIMV/128, ROWS/128), 256, HG_SMEM>>>(
        hh, hl, nlwh, nlwl, nl_b, nullptr, x, nullptr, nullptr, ROWS, DIMV, DIMV);
    ln_kernel<<<ROWS, 256>>>(x, nl_ln2_g, nl_ln2_b, x, DIMV);
    add_pos_kernel<<<ROWS * DIMV / 256, 256>>>(x, sph_pos, pos_w, pos_b);

    // ---- transformer layers ----
    for (int l = 0; l < DEPTH; l++) {
        ln_split_kernel<<<ROWS, 256>>>(x, ln_g + l * DIMV, ln_b + l * DIMV, hh, hl, DIMV);
        hmma_gemm_kernel<true><<<dim3(PATCHDIM/128, ROWS/128), 256, HG_SMEM>>>(
            hh, hl, qwh + (size_t)l * PATCHDIM * DIMV, qwl + (size_t)l * PATCHDIM * DIMV,
            nullptr, nullptr, nullptr, qkvh, qkvl, ROWS, PATCHDIM, DIMV);
        qk_mma_kernel<<<BATCH * NHEADS, 256, QK_SMEM>>>(qkvh, qkvl, sph_dist, w);
        std_softmax_kernel<<<BATCH * NTOK, 128>>>(w, ph, pl);
        av_mma_kernel<<<BATCH * NHEADS, 256, AV_SMEM>>>(ph, pl, qkvh, qkvl, oh, ol);
        hmma_gemm_kernel<false><<<dim3(DIMV/128, ROWS/128), 256, HG_SMEM>>>(
            oh, ol, owh + (size_t)l * DIMV * DIMV, owl + (size_t)l * DIMV * DIMV,
            wo_b + l * DIMV, x, x, nullptr, nullptr, ROWS, DIMV, DIMV);
    }

    // ---- final LN + expand + output LN + reassembly ----
    ln_split_kernel<<<ROWS, 256>>>(x, tr_ln_g, tr_ln_b, hh, hl, DIMV);
    hmma_gemm_kernel<false><<<dim3(PATCHDIM/128, ROWS/128), 256, HG_SMEM>>>(
        hh, hl, ewh, ewl, exp_b, nullptr, big, nullptr, nullptr, ROWS, PATCHDIM, DIMV);
    ln_kernel<<<ROWS, 256>>>(big, out_ln_g, out_ln_b, big, PATCHDIM);
    reassemble_kernel<<<ROWS * PATCHDIM / 256, 256>>>(big, (float*)d_out);
}

// round 8
// speedup vs baseline: 1.5610x; 1.5610x over previous
#include <cuda_runtime.h>
#include <cuda_bf16.h>
#include <cstdint>

// ---------------------------------------------------------------------------
// SphereViT forward — split-bf16 HMMA everywhere (GEMMs + attention).
// R8: conv GEMM unsplit (full grid); av_mma loads V directly and uses
//     ldmatrix.trans for B (no scalar smem transpose).
// ---------------------------------------------------------------------------

#define BATCH     32
#define NTOK      128
#define ROWS      4096
#define DIMV      1024
#define PATCHDIM  3072
#define NHEADS    16
#define DHEAD     64
#define DEPTH     12
#define LN_EPS    1e-5f

// -------------------- scratch (device globals; no allocs) ------------------
__device__ float g_big[ROWS * PATCHDIM];                 // expand output
__device__ float g_x  [ROWS * DIMV];                     // residual stream
__device__ float g_w  [BATCH * NHEADS * NTOK * NTOK];    // attention scores fp32

// split-bf16 activations
__device__ __nv_bfloat16 g_Xph[ROWS * PATCHDIM], g_Xpl[ROWS * PATCHDIM];
__device__ __nv_bfloat16 g_qkvh[ROWS * PATCHDIM], g_qkvl[ROWS * PATCHDIM];
__device__ __nv_bfloat16 g_hh [ROWS * DIMV],     g_hl [ROWS * DIMV];
__device__ __nv_bfloat16 g_oh [ROWS * DIMV],     g_ol [ROWS * DIMV];
__device__ __nv_bfloat16 g_ph [BATCH*NHEADS*NTOK*NTOK], g_pl [BATCH*NHEADS*NTOK*NTOK];

// split-bf16 transposed weights ([N,K] K-major)
__device__ __nv_bfloat16 g_cwh[DIMV * PATCHDIM],          g_cwl[DIMV * PATCHDIM];
__device__ __nv_bfloat16 g_nlwh[DIMV * DIMV],             g_nlwl[DIMV * DIMV];
__device__ __nv_bfloat16 g_qwh[DEPTH * PATCHDIM * DIMV],  g_qwl[DEPTH * PATCHDIM * DIMV];
__device__ __nv_bfloat16 g_owh[DEPTH * DIMV * DIMV],      g_owl[DEPTH * DIMV * DIMV];
__device__ __nv_bfloat16 g_ewh[PATCHDIM * DIMV],          g_ewl[PATCHDIM * DIMV];

// ---------------------------------------------------------------------------
// PTX helpers
// ---------------------------------------------------------------------------
__device__ __forceinline__ uint32_t smem_u32(const void* p) {
    uint32_t a;
    asm("{ .reg .u64 t; cvta.to.shared.u64 t, %1; cvt.u32.u64 %0, t; }"
        : "=r"(a) : "l"(p));
    return a;
}
__device__ __forceinline__ void cpa16(uint32_t dst, const void* src) {
    asm volatile("cp.async.cg.shared.global [%0], [%1], 16;" :: "r"(dst), "l"(src));
}
__device__ __forceinline__ void cp_commit() { asm volatile("cp.async.commit_group;"); }
template <int NN>
__device__ __forceinline__ void cp_wait() {
    asm volatile("cp.async.wait_group %0;" :: "n"(NN));
}
__device__ __forceinline__ void ldsm4(uint32_t* r, uint32_t addr) {
    asm volatile("ldmatrix.sync.aligned.m8n8.x4.shared.b16 {%0,%1,%2,%3}, [%4];"
                 : "=r"(r[0]), "=r"(r[1]), "=r"(r[2]), "=r"(r[3]) : "r"(addr));
}
__device__ __forceinline__ void ldsm4t(uint32_t* r, uint32_t addr) {
    asm volatile("ldmatrix.sync.aligned.m8n8.x4.trans.shared.b16 {%0,%1,%2,%3}, [%4];"
                 : "=r"(r[0]), "=r"(r[1]), "=r"(r[2]), "=r"(r[3]) : "r"(addr));
}
__device__ __forceinline__ void mma16816(float* c, const uint32_t* a,
                                         const uint32_t* b) {
    asm volatile(
        "mma.sync.aligned.m16n8k16.row.col.f32.bf16.bf16.f32 "
        "{%0,%1,%2,%3}, {%4,%5,%6,%7}, {%8,%9}, {%0,%1,%2,%3};"
        : "+f"(c[0]), "+f"(c[1]), "+f"(c[2]), "+f"(c[3])
        : "r"(a[0]), "r"(a[1]), "r"(a[2]), "r"(a[3]), "r"(b[0]), "r"(b[1]));
}
__device__ __forceinline__ void split2(float v, __nv_bfloat16& h, __nv_bfloat16& l) {
    h = __float2bfloat16(v);
    l = __float2bfloat16(v - __bfloat162float(h));
}

// ---------------------------------------------------------------------------
// Split-bf16 HMMA GEMM: C = (Ah+Al)[M,K] @ (Bh+Bl)[N,K]^T (+bias)(+res)
// OUTSPLIT: write split-bf16 (Ch,Cl) instead of fp32 C.
// ---------------------------------------------------------------------------
#define GPAD 8
#define GLDS (32 + GPAD)
#define OPND_ELEMS (128 * GLDS)
#define STAGE_ELEMS (4 * OPND_ELEMS)
#define HG_SMEM (2 * STAGE_ELEMS * 2)    // 81920 bytes

template <bool OUTSPLIT>
__global__ __launch_bounds__(256, 2) void hmma_gemm_kernel(
    const __nv_bfloat16* __restrict__ Ah, const __nv_bfloat16* __restrict__ Al,
    const __nv_bfloat16* __restrict__ Bh, const __nv_bfloat16* __restrict__ Bl,
    const float* __restrict__ bias, const float* __restrict__ res,
    float* __restrict__ C, __nv_bfloat16* __restrict__ Ch,
    __nv_bfloat16* __restrict__ Cl, int M, int N, int K)
{
    extern __shared__ __nv_bfloat16 smem[];
    const uint32_t sbase = smem_u32(smem);
    const int tid  = threadIdx.x;
    const int lane = tid & 31, warp = tid >> 5;
    const int wm = warp & 1, wn = warp >> 1;
    const int m0 = blockIdx.y << 7, n0 = blockIdx.x << 7;

    const __nv_bfloat16* g[4] = {
        Ah + (size_t)m0 * K, Al + (size_t)m0 * K,
        Bh + (size_t)n0 * K, Bl + (size_t)n0 * K };

    const int r0c = tid >> 2;
    const int c0c = tid & 3;

    auto issue = [&](int stage, int k0) {
#pragma unroll
        for (int op = 0; op < 4; op++) {
            uint32_t sdst = sbase + (uint32_t)(stage * STAGE_ELEMS + op * OPND_ELEMS) * 2;
            const __nv_bfloat16* gs = g[op];
#pragma unroll
            for (int half = 0; half < 2; half++) {
                int r = r0c + half * 64;
                cpa16(sdst + (uint32_t)(r * GLDS + c0c * 8) * 2,
                      gs + (size_t)r * K + k0 + c0c * 8);
            }
        }
    };

    float acc[4][4][4];
#pragma unroll
    for (int i = 0; i < 4; i++)
#pragma unroll
        for (int j = 0; j < 4; j++)
#pragma unroll
            for (int q = 0; q < 4; q++) acc[i][j][q] = 0.f;

    const int nk = K >> 5;
    issue(0, 0);
    cp_commit();

    const int arow = wm * 64 + (lane & 15);
    const int acolb = (lane >> 4) * 8;
    const int brow = wn * 32 + ((lane >> 4) * 8) + (lane & 7);
    const int bcolb = ((lane >> 3) & 1) * 8;

    for (int it = 0; it < nk; ++it) {
        const int s = it & 1;
        if (it + 1 < nk) {
            issue(s ^ 1, (it + 1) << 5);
            cp_commit();
            cp_wait<1>();
        } else {
            cp_wait<0>();
        }
        __syncthreads();

        uint32_t sA  = sbase + (uint32_t)(s * STAGE_ELEMS) * 2;
        uint32_t sAl = sA + OPND_ELEMS * 2;
        uint32_t sB  = sA + 2 * OPND_ELEMS * 2;
        uint32_t sBl = sA + 3 * OPND_ELEMS * 2;

#pragma unroll
        for (int ks = 0; ks < 2; ks++) {
            const int acol = ks * 16 + acolb;
            const int bcol = ks * 16 + bcolb;
            uint32_t ah[4][4], bh[4][2];
#pragma unroll
            for (int mi = 0; mi < 4; mi++)
                ldsm4(ah[mi], sA + (uint32_t)((arow + mi * 16) * GLDS + acol) * 2);
#pragma unroll
            for (int gp = 0; gp < 2; gp++) {
                uint32_t rh[4];
                ldsm4(rh, sB + (uint32_t)((brow + gp * 16) * GLDS + bcol) * 2);
                bh[gp*2][0] = rh[0]; bh[gp*2][1] = rh[1];
                bh[gp*2+1][0] = rh[2]; bh[gp*2+1][1] = rh[3];
            }
#pragma unroll
            for (int mi = 0; mi < 4; mi++)
#pragma unroll
                for (int nj = 0; nj < 4; nj++)
                    mma16816(acc[mi][nj], ah[mi], bh[nj]);

            uint32_t bl[4][2];
#pragma unroll
            for (int gp = 0; gp < 2; gp++) {
                uint32_t rl[4];
                ldsm4(rl, sBl + (uint32_t)((brow + gp * 16) * GLDS + bcol) * 2);
                bl[gp*2][0] = rl[0]; bl[gp*2][1] = rl[1];
                bl[gp*2+1][0] = rl[2]; bl[gp*2+1][1] = rl[3];
            }
#pragma unroll
            for (int mi = 0; mi < 4; mi++)
#pragma unroll
                for (int nj = 0; nj < 4; nj++)
                    mma16816(acc[mi][nj], ah[mi], bl[nj]);

            uint32_t al[4][4];
#pragma unroll
            for (int mi = 0; mi < 4; mi++)
                ldsm4(al[mi], sAl + (uint32_t)((arow + mi * 16) * GLDS + acol) * 2);
#pragma unroll
            for (int mi = 0; mi < 4; mi++)
#pragma unroll
                for (int nj = 0; nj < 4; nj++)
                    mma16816(acc[mi][nj], al[mi], bh[nj]);
        }
        __syncthreads();
    }

    // epilogue
#pragma unroll
    for (int mi = 0; mi < 4; mi++) {
        int r0 = m0 + wm * 64 + mi * 16 + (lane >> 2);
#pragma unroll
        for (int nj = 0; nj < 4; nj++) {
            int c = n0 + wn * 32 + nj * 8 + (lane & 3) * 2;
            float v0x = acc[mi][nj][0], v0y = acc[mi][nj][1];
            float v1x = acc[mi][nj][2], v1y = acc[mi][nj][3];
            size_t o0 = (size_t)r0 * N + c;
            size_t o1 = o0 + (size_t)8 * N;
            if (OUTSPLIT) {
                __nv_bfloat16 h0, l0, h1, l1;
                __nv_bfloat162 hp, lp;
                split2(v0x, h0, l0); split2(v0y, h1, l1);
                hp.x = h0; hp.y = h1; lp.x = l0; lp.y = l1;
                *(__nv_bfloat162*)(Ch + o0) = hp;
                *(__nv_bfloat162*)(Cl + o0) = lp;
                split2(v1x, h0, l0); split2(v1y, h1, l1);
                hp.x = h0; hp.y = h1; lp.x = l0; lp.y = l1;
                *(__nv_bfloat162*)(Ch + o1) = hp;
                *(__nv_bfloat162*)(Cl + o1) = lp;
            } else {
                if (bias) {
                    float bx = bias[c], by = bias[c + 1];
                    v0x += bx; v0y += by; v1x += bx; v1y += by;
                }
                if (res) {
                    float2 ra = *(const float2*)(res + o0);
                    float2 rb = *(const float2*)(res + o1);
                    v0x += ra.x; v0y += ra.y; v1x += rb.x; v1y += rb.y;
                }
                *(float2*)(C + o0) = make_float2(v0x, v0y);
                *(float2*)(C + o1) = make_float2(v1x, v1y);
            }
        }
    }
}

// ---------------------------------------------------------------------------
// qk via HMMA: W[b,h,i,j] = (q_i.k_j)*0.125*(1+dist). One CTA per (b,h).
// ---------------------------------------------------------------------------
#define QKLD 72
#define QK_TILE (128 * QKLD)             // 9216 elems
#define QK_SMEM (4 * QK_TILE * 2)        // 73728 bytes

__global__ __launch_bounds__(256, 2) void qk_mma_kernel(
    const __nv_bfloat16* __restrict__ qkvh, const __nv_bfloat16* __restrict__ qkvl,
    const float* __restrict__ dist, float* __restrict__ W)
{
    extern __shared__ __nv_bfloat16 smem[];
    const uint32_t sbase = smem_u32(smem);
    const int tid = threadIdx.x, lane = tid & 31, warp = tid >> 5;
    const int wm = warp & 1, wn = warp >> 1;
    const int b = blockIdx.x >> 4, h = blockIdx.x & 15;
    const size_t rowbase = (size_t)b * NTOK * PATCHDIM + h * DHEAD;

    // tiles: 0=Qh 1=Ql 2=Kh 3=Kl.  Each tile: 128 rows x 64 bf16 = 1024 chunks.
    const __nv_bfloat16* srcs[4] = { qkvh, qkvl, qkvh, qkvl };
    const int offs[4] = { 0, 0, DIMV, DIMV };
#pragma unroll
    for (int t = 0; t < 4; t++) {
        uint32_t dbase = sbase + (uint32_t)(t * QK_TILE) * 2;
#pragma unroll
        for (int p = 0; p < 4; p++) {
            int q = tid + p * 256;       // 0..1023
            int r = q >> 3, c = q & 7;   // row, 8-elem chunk
            cpa16(dbase + (uint32_t)(r * QKLD + c * 8) * 2,
                  srcs[t] + rowbase + (size_t)r * PATCHDIM + offs[t] + c * 8);
        }
    }
    cp_commit();
    cp_wait<0>();
    __syncthreads();

    float acc[4][4][4];
#pragma unroll
    for (int i = 0; i < 4; i++)
#pragma unroll
        for (int j = 0; j < 4; j++)
#pragma unroll
            for (int q = 0; q < 4; q++) acc[i][j][q] = 0.f;

    uint32_t sA  = sbase;
    uint32_t sAl = sbase + (uint32_t)QK_TILE * 2;
    uint32_t sB  = sbase + (uint32_t)(2 * QK_TILE) * 2;
    uint32_t sBl = sbase + (uint32_t)(3 * QK_TILE) * 2;
    const int arow = wm * 64 + (lane & 15);
    const int acolb = (lane >> 4) * 8;
    const int brow = wn * 32 + ((lane >> 4) * 8) + (lane & 7);
    const int bcolb = ((lane >> 3) & 1) * 8;

#pragma unroll
    for (int ks = 0; ks < 4; ks++) {
        const int acol = ks * 16 + acolb;
        const int bcol = ks * 16 + bcolb;
        uint32_t ah[4][4], bh[4][2];
#pragma unroll
        for (int mi = 0; mi < 4; mi++)
            ldsm4(ah[mi], sA + (uint32_t)((arow + mi * 16) * QKLD + acol) * 2);
#pragma unroll
        for (int gp = 0; gp < 2; gp++) {
            uint32_t rh[4];
            ldsm4(rh, sB + (uint32_t)((brow + gp * 16) * QKLD + bcol) * 2);
            bh[gp*2][0] = rh[0]; bh[gp*2][1] = rh[1];
            bh[gp*2+1][0] = rh[2]; bh[gp*2+1][1] = rh[3];
        }
#pragma unroll
        for (int mi = 0; mi < 4; mi++)
#pragma unroll
            for (int nj = 0; nj < 4; nj++)
                mma16816(acc[mi][nj], ah[mi], bh[nj]);

        uint32_t bl[4][2];
#pragma unroll
        for (int gp = 0; gp < 2; gp++) {
            uint32_t rl[4];
            ldsm4(rl, sBl + (uint32_t)((brow + gp * 16) * QKLD + bcol) * 2);
            bl[gp*2][0] = rl[0]; bl[gp*2][1] = rl[1];
            bl[gp*2+1][0] = rl[2]; bl[gp*2+1][1] = rl[3];
        }
#pragma unroll
        for (int mi = 0; mi < 4; mi++)
#pragma unroll
            for (int nj = 0; nj < 4; nj++)
                mma16816(acc[mi][nj], ah[mi], bl[nj]);

        uint32_t al[4][4];
#pragma unroll
        for (int mi = 0; mi < 4; mi++)
            ldsm4(al[mi], sAl + (uint32_t)((arow + mi * 16) * QKLD + acol) * 2);
#pragma unroll
        for (int mi = 0; mi < 4; mi++)
#pragma unroll
            for (int nj = 0; nj < 4; nj++)
                mma16816(acc[mi][nj], al[mi], bh[nj]);
    }

    float* Wb = W + (size_t)blockIdx.x * (NTOK * NTOK);
#pragma unroll
    for (int mi = 0; mi < 4; mi++) {
        int i0 = wm * 64 + mi * 16 + (lane >> 2);
#pragma unroll
        for (int nj = 0; nj < 4; nj++) {
            int j0 = wn * 32 + nj * 8 + (lane & 3) * 2;
#pragma unroll
            for (int rr = 0; rr < 2; rr++) {
                int i = i0 + rr * 8;
                float vx = acc[mi][nj][rr*2], vy = acc[mi][nj][rr*2+1];
                Wb[i * 128 + j0]     = vx * 0.125f * (1.0f + dist[i * 128 + j0]);
                Wb[i * 128 + j0 + 1] = vy * 0.125f * (1.0f + dist[i * 128 + j0 + 1]);
            }
        }
    }
}

// ---------------------------------------------------------------------------
// Cross-head standardize (ddof=1) + softmax; emits split-bf16 P.
// ---------------------------------------------------------------------------
__global__ __launch_bounds__(128) void std_softmax_kernel(
    const float* __restrict__ W,
    __nv_bfloat16* __restrict__ Ph, __nv_bfloat16* __restrict__ Pl)
{
    int b = blockIdx.x >> 7, i = blockIdx.x & 127;
    int j = threadIdx.x;
    __shared__ float sm[NHEADS][128];

    size_t base = (size_t)b * (NHEADS * NTOK * NTOK) + (size_t)i * 128 + j;
    float vals[NHEADS];
    float s = 0.f;
#pragma unroll
    for (int h = 0; h < NHEADS; h++) {
        float v = W[base + (size_t)h * (NTOK * NTOK)];
        vals[h] = v; s += v;
    }
    float mu = s * (1.0f / 16.0f);
    float d2 = 0.f;
#pragma unroll
    for (int h = 0; h < NHEADS; h++) {
        float d = vals[h] - mu;
        d2 += d * d;
    }
    float inv = rsqrtf(d2 * (1.0f / 15.0f));
#pragma unroll
    for (int h = 0; h < NHEADS; h++) sm[h][j] = (vals[h] - mu) * inv;
    __syncthreads();

    int warp = j >> 5, lane = j & 31;
#pragma unroll
    for (int r = 0; r < 4; r++) {
        int h = warp * 4 + r;
        float v0 = sm[h][lane], v1 = sm[h][lane + 32];
        float v2 = sm[h][lane + 64], v3 = sm[h][lane + 96];
        float m = fmaxf(fmaxf(v0, v1), fmaxf(v2, v3));
#pragma unroll
        for (int o = 16; o; o >>= 1) m = fmaxf(m, __shfl_xor_sync(0xffffffffu, m, o));
        float e0 = expf(v0 - m), e1 = expf(v1 - m);
        float e2 = expf(v2 - m), e3 = expf(v3 - m);
        float sum = e0 + e1 + e2 + e3;
#pragma unroll
        for (int o = 16; o; o >>= 1) sum += __shfl_xor_sync(0xffffffffu, sum, o);
        float rs = 1.0f / sum;
        size_t wb = (size_t)b * (NHEADS * NTOK * NTOK) + (size_t)h * (NTOK * NTOK)
                  + (size_t)i * 128;
        float p0 = e0 * rs, p1 = e1 * rs, p2 = e2 * rs, p3 = e3 * rs;
        __nv_bfloat16 hh, ll;
        split2(p0, hh, ll); Ph[wb + lane]      = hh; Pl[wb + lane]      = ll;
        split2(p1, hh, ll); Ph[wb + lane + 32] = hh; Pl[wb + lane + 32] = ll;
        split2(p2, hh, ll); Ph[wb + lane + 64] = hh; Pl[wb + lane + 64] = ll;
        split2(p3, hh, ll); Ph[wb + lane + 96] = hh; Pl[wb + lane + 96] = ll;
    }
}

// ---------------------------------------------------------------------------
// av via HMMA: O[i, h*64+d] = sum_j P[i,j] * V[j,d].  One CTA per (b,h).
// A = P split [128 i][128 j]; B = V split [128 j][64 d] read via ldmatrix.trans.
// ---------------------------------------------------------------------------
#define AVPLD 136
#define AVVLD 72
#define AVP_TILE (128 * AVPLD)           // 17408 elems
#define AVV_TILE (128 * AVVLD)           // 9216 elems
#define AV_SMEM ((2 * AVP_TILE + 2 * AVV_TILE) * 2)   // 106496 bytes

__global__ __launch_bounds__(256, 2) void av_mma_kernel(
    const __nv_bfloat16* __restrict__ Ph, const __nv_bfloat16* __restrict__ Pl,
    const __nv_bfloat16* __restrict__ qkvh, const __nv_bfloat16* __restrict__ qkvl,
    __nv_bfloat16* __restrict__ Oh, __nv_bfloat16* __restrict__ Ol)
{
    extern __shared__ __nv_bfloat16 smem[];
    const uint32_t sbase = smem_u32(smem);
    const int tid = threadIdx.x, lane = tid & 31, warp = tid >> 5;
    const int wm = warp & 3, wn = warp >> 2;
    const int b = blockIdx.x >> 4, h = blockIdx.x & 15;
    const size_t pbase = (size_t)blockIdx.x * (NTOK * NTOK);
    const size_t vbase = (size_t)b * NTOK * PATCHDIM + 2 * DIMV + h * DHEAD;

    // load P hi/lo via cp.async, [i][128] -> [i][AVPLD]
    const __nv_bfloat16* psrc[2] = { Ph, Pl };
#pragma unroll
    for (int t = 0; t < 2; t++) {
        uint32_t dbase = sbase + (uint32_t)(t * AVP_TILE) * 2;
#pragma unroll
        for (int p = 0; p < 8; p++) {
            int q = tid + p * 256;       // 0..2047
            int r = q >> 4, c = q & 15;
            cpa16(dbase + (uint32_t)(r * AVPLD + c * 8) * 2,
                  psrc[t] + pbase + (size_t)r * 128 + c * 8);
        }
    }
    // load V hi/lo via cp.async, [j][64] -> [j][AVVLD] (no transpose)
    const __nv_bfloat16* vsrc[2] = { qkvh, qkvl };
#pragma unroll
    for (int t = 0; t < 2; t++) {
        uint32_t dbase = sbase + (uint32_t)(2 * AVP_TILE + t * AVV_TILE) * 2;
#pragma unroll
        for (int p = 0; p < 4; p++) {
            int q = tid + p * 256;       // 0..1023
            int j = q >> 3, c = q & 7;
            cpa16(dbase + (uint32_t)(j * AVVLD + c * 8) * 2,
                  vsrc[t] + vbase + (size_t)j * PATCHDIM + c * 8);
        }
    }
    cp_commit();
    cp_wait<0>();
    __syncthreads();

    float acc[2][4][4];
#pragma unroll
    for (int i = 0; i < 2; i++)
#pragma unroll
        for (int j = 0; j < 4; j++)
#pragma unroll
            for (int q = 0; q < 4; q++) acc[i][j][q] = 0.f;

    uint32_t sA  = sbase;
    uint32_t sAl = sbase + (uint32_t)AVP_TILE * 2;
    uint32_t sB  = sbase + (uint32_t)(2 * AVP_TILE) * 2;
    uint32_t sBl = sB + (uint32_t)AVV_TILE * 2;
    const int arow = wm * 32 + (lane & 15);
    const int acolb = (lane >> 4) * 8;
    const int bjrow = lane & 15;             // k (j) row within 16
    const int bdcol = (lane >> 4) * 8;       // n (d) 8-col group

#pragma unroll
    for (int kc = 0; kc < 8; kc++) {
        const int acol = kc * 16 + acolb;
        uint32_t ah[2][4], bh[4][2];
#pragma unroll
        for (int mi = 0; mi < 2; mi++)
            ldsm4(ah[mi], sA + (uint32_t)((arow + mi * 16) * AVPLD + acol) * 2);
#pragma unroll
        for (int gp = 0; gp < 2; gp++) {
            uint32_t rh[4];
            uint32_t off = (uint32_t)((kc * 16 + bjrow) * AVVLD
                                      + wn * 32 + gp * 16 + bdcol) * 2;
            ldsm4t(rh, sB + off);
            bh[gp*2][0] = rh[0]; bh[gp*2][1] = rh[1];
            bh[gp*2+1][0] = rh[2]; bh[gp*2+1][1] = rh[3];
        }
#pragma unroll
        for (int mi = 0; mi < 2; mi++)
#pragma unroll
            for (int nj = 0; nj < 4; nj++)
                mma16816(acc[mi][nj], ah[mi], bh[nj]);

        uint32_t bl[4][2];
#pragma unroll
        for (int gp = 0; gp < 2; gp++) {
            uint32_t rl[4];
            uint32_t off = (uint32_t)((kc * 16 + bjrow) * AVVLD
                                      + wn * 32 + gp * 16 + bdcol) * 2;
            ldsm4t(rl, sBl + off);
            bl[gp*2][0] = rl[0]; bl[gp*2][1] = rl[1];
            bl[gp*2+1][0] = rl[2]; bl[gp*2+1][1] = rl[3];
        }
#pragma unroll
        for (int mi = 0; mi < 2; mi++)
#pragma unroll
            for (int nj = 0; nj < 4; nj++)
                mma16816(acc[mi][nj], ah[mi], bl[nj]);

        uint32_t al[2][4];
#pragma unroll
        for (int mi = 0; mi < 2; mi++)
            ldsm4(al[mi], sAl + (uint32_t)((arow + mi * 16) * AVPLD + acol) * 2);
#pragma unroll
        for (int mi = 0; mi < 2; mi++)
#pragma unroll
            for (int nj = 0; nj < 4; nj++)
                mma16816(acc[mi][nj], al[mi], bh[nj]);
    }

#pragma unroll
    for (int mi = 0; mi < 2; mi++) {
        int i0 = wm * 32 + mi * 16 + (lane >> 2);
#pragma unroll
        for (int nj = 0; nj < 4; nj++) {
            int d0 = wn * 32 + nj * 8 + (lane & 3) * 2;
#pragma unroll
            for (int rr = 0; rr < 2; rr++) {
                int i = i0 + rr * 8;
                size_t o = (size_t)(b * 128 + i) * DIMV + h * DHEAD + d0;
                __nv_bfloat16 h0, l0, h1, l1;
                __nv_bfloat162 hp, lp;
                split2(acc[mi][nj][rr*2],     h0, l0);
                split2(acc[mi][nj][rr*2 + 1], h1, l1);
                hp.x = h0; hp.y = h1; lp.x = l0; lp.y = l1;
                *(__nv_bfloat162*)(Oh + o) = hp;
                *(__nv_bfloat162*)(Ol + o) = lp;
            }
        }
    }
}

// ---------------------------------------------------------------------------
// Weight prep
// ---------------------------------------------------------------------------
__global__ void split_kernel(const float* __restrict__ X,
                             __nv_bfloat16* __restrict__ H,
                             __nv_bfloat16* __restrict__ L) {
    size_t i = (size_t)blockIdx.x * 256 + threadIdx.x;
    split2(X[i], H[i], L[i]);
}

__global__ void wtrans_split_kernel(const float* __restrict__ W,
                                    __nv_bfloat16* __restrict__ Th,
                                    __nv_bfloat16* __restrict__ Tl,
                                    int K, int N) {
    __shared__ float t[32][33];
    const float* Wl = W + (size_t)blockIdx.z * K * N;
    size_t ob = (size_t)blockIdx.z * K * N;
    int x = blockIdx.x * 32 + threadIdx.x;
    int y = blockIdx.y * 32 + threadIdx.y;
#pragma unroll
    for (int j = 0; j < 32; j += 8)
        t[threadIdx.y + j][threadIdx.x] = Wl[(size_t)(y + j) * N + x];
    __syncthreads();
    int n = blockIdx.x * 32 + threadIdx.y;
    int k = blockIdx.y * 32 + threadIdx.x;
#pragma unroll
    for (int j = 0; j < 32; j += 8) {
        size_t o = ob + (size_t)(n + j) * K + k;
        split2(t[threadIdx.x][threadIdx.y + j], Th[o], Tl[o]);
    }
}

__global__ void extract_patches_kernel(const float* __restrict__ img,
                                       __nv_bfloat16* __restrict__ H,
                                       __nv_bfloat16* __restrict__ L) {
    int idx = blockIdx.x * 256 + threadIdx.x;
    int col = idx % PATCHDIM;
    int row = idx / PATCHDIM;
    int b = row >> 7, t = row & 127;
    int h = t >> 4, w = t & 15;
    int c = col >> 10, r = col & 1023;
    int p = r >> 5, q = r & 31;
    float v = img[(((size_t)b * 3 + c) * 256 + h * 32 + p) * 512 + w * 32 + q];
    split2(v, H[idx], L[idx]);
}

// ---------------------------------------------------------------------------
// LayerNorm
// ---------------------------------------------------------------------------
__device__ __forceinline__ void ln_stats(const float* __restrict__ x, size_t base,
                                         int D, float& mu, float& rstd) {
    float s = 0.f, ss = 0.f;
    for (int i = threadIdx.x; i < D; i += 256) {
        float v = x[base + i];
        s += v; ss += v * v;
    }
#pragma unroll
    for (int o = 16; o; o >>= 1) {
        s  += __shfl_xor_sync(0xffffffffu, s, o);
        ss += __shfl_xor_sync(0xffffffffu, ss, o);
    }
    __shared__ float sh[2][8];
    int w = threadIdx.x >> 5;
    if ((threadIdx.x & 31) == 0) { sh[0][w] = s; sh[1][w] = ss; }
    __syncthreads();
    if (threadIdx.x < 32) {
        s  = (threadIdx.x < 8) ? sh[0][threadIdx.x] : 0.f;
        ss = (threadIdx.x < 8) ? sh[1][threadIdx.x] : 0.f;
#pragma unroll
        for (int o = 4; o; o >>= 1) {
            s  += __shfl_xor_sync(0xffffffffu, s, o);
            ss += __shfl_xor_sync(0xffffffffu, ss, o);
        }
        if (threadIdx.x == 0) { sh[0][0] = s; sh[1][0] = ss; }
    }
    __syncthreads();
    s = sh[0][0]; ss = sh[1][0];
    float invD = 1.0f / (float)D;
    mu = s * invD;
    float var = ss * invD - mu * mu;
    rstd = rsqrtf(var + LN_EPS);
}

__global__ void ln_kernel(const float* __restrict__ x, const float* __restrict__ g,
                          const float* __restrict__ beta, float* __restrict__ y, int D) {
    size_t base = (size_t)blockIdx.x * D;
    float mu, rstd;
    ln_stats(x, base, D, mu, rstd);
    for (int i = threadIdx.x; i < D; i += 256)
        y[base + i] = (x[base + i] - mu) * rstd * g[i] + beta[i];
}

__global__ void ln_split_kernel(const float* __restrict__ x, const float* __restrict__ g,
                                const float* __restrict__ beta,
                                __nv_bfloat16* __restrict__ H,
                                __nv_bfloat16* __restrict__ L, int D) {
    size_t base = (size_t)blockIdx.x * D;
    float mu, rstd;
    ln_stats(x, base, D, mu, rstd);
    for (int i = threadIdx.x; i < D; i += 256) {
        float v = (x[base + i] - mu) * rstd * g[i] + beta[i];
        split2(v, H[base + i], L[base + i]);
    }
}

__global__ void add_pos_kernel(float* __restrict__ x, const float* __restrict__ sph_pos,
                               const float* __restrict__ pos_w,
                               const float* __restrict__ pos_b) {
    int idx = blockIdx.x * 256 + threadIdx.x;
    int d = idx & 1023;
    int i = (idx >> 10) & 127;
    x[idx] += sph_pos[i * 2] * pos_w[d] + sph_pos[i * 2 + 1] * pos_w[1024 + d] + pos_b[d];
}

__global__ void reassemble_kernel(const float* __restrict__ Y, float* __restrict__ out) {
    int idx = blockIdx.x * 256 + threadIdx.x;
    int xq = idx & 511;
    int rest = idx >> 9;
    int yr = rest & 255;
    rest >>= 8;
    int c = rest % 3;
    int b = rest / 3;
    int h = yr >> 5, p1 = yr & 31, w = xq >> 5, p2 = xq & 31;
    out[idx] = Y[(size_t)(b * 128 + h * 16 + w) * PATCHDIM + (p1 * 32 + p2) * 3 + c];
}

// ---------------------------------------------------------------------------
// Host launcher
// ---------------------------------------------------------------------------
extern "C" void kernel_launch(void* const* d_in, const int* in_sizes, int n_in,
                              void* d_out, int out_size)
{
    const float* img      = (const float*)d_in[0];
    const float* sph_pos  = (const float*)d_in[1];
    const float* sph_dist = (const float*)d_in[2];
    const float* conv_w   = (const float*)d_in[3];
    const float* conv_b   = (const float*)d_in[4];
    const float* nl_ln1_g = (const float*)d_in[5];
    const float* nl_ln1_b = (const float*)d_in[6];
    const float* nl_w     = (const float*)d_in[7];
    const float* nl_b     = (const float*)d_in[8];
    const float* nl_ln2_g = (const float*)d_in[9];
    const float* nl_ln2_b = (const float*)d_in[10];
    const float* pos_w    = (const float*)d_in[11];
    const float* pos_b    = (const float*)d_in[12];
    const float* ln_g     = (const float*)d_in[13];
    const float* ln_b     = (const float*)d_in[14];
    const float* wqkv     = (const float*)d_in[15];
    const float* wo       = (const float*)d_in[16];
    const float* wo_b     = (const float*)d_in[17];
    const float* tr_ln_g  = (const float*)d_in[18];
    const float* tr_ln_b  = (const float*)d_in[19];
    const float* exp_w    = (const float*)d_in[20];
    const float* exp_b    = (const float*)d_in[21];
    const float* out_ln_g = (const float*)d_in[22];
    const float* out_ln_b = (const float*)d_in[23];

    float *big, *x, *w;
    cudaGetSymbolAddress((void**)&big, g_big);
    cudaGetSymbolAddress((void**)&x,   g_x);
    cudaGetSymbolAddress((void**)&w,   g_w);
    __nv_bfloat16 *Xph, *Xpl, *qkvh, *qkvl, *hh, *hl, *oh, *ol, *ph, *pl;
    __nv_bfloat16 *cwh, *cwl, *nlwh, *nlwl, *qwh, *qwl, *owh, *owl, *ewh, *ewl;
    cudaGetSymbolAddress((void**)&Xph, g_Xph);   cudaGetSymbolAddress((void**)&Xpl, g_Xpl);
    cudaGetSymbolAddress((void**)&qkvh, g_qkvh); cudaGetSymbolAddress((void**)&qkvl, g_qkvl);
    cudaGetSymbolAddress((void**)&hh,  g_hh);    cudaGetSymbolAddress((void**)&hl,  g_hl);
    cudaGetSymbolAddress((void**)&oh,  g_oh);    cudaGetSymbolAddress((void**)&ol,  g_ol);
    cudaGetSymbolAddress((void**)&ph,  g_ph);    cudaGetSymbolAddress((void**)&pl,  g_pl);
    cudaGetSymbolAddress((void**)&cwh, g_cwh);   cudaGetSymbolAddress((void**)&cwl, g_cwl);
    cudaGetSymbolAddress((void**)&nlwh,g_nlwh);  cudaGetSymbolAddress((void**)&nlwl,g_nlwl);
    cudaGetSymbolAddress((void**)&qwh, g_qwh);   cudaGetSymbolAddress((void**)&qwl, g_qwl);
    cudaGetSymbolAddress((void**)&owh, g_owh);   cudaGetSymbolAddress((void**)&owl, g_owl);
    cudaGetSymbolAddress((void**)&ewh, g_ewh);   cudaGetSymbolAddress((void**)&ewl, g_ewl);

    cudaFuncSetAttribute(hmma_gemm_kernel<false>,
                         cudaFuncAttributeMaxDynamicSharedMemorySize, HG_SMEM);
    cudaFuncSetAttribute(hmma_gemm_kernel<true>,
                         cudaFuncAttributeMaxDynamicSharedMemorySize, HG_SMEM);
    cudaFuncSetAttribute(qk_mma_kernel,
                         cudaFuncAttributeMaxDynamicSharedMemorySize, QK_SMEM);
    cudaFuncSetAttribute(av_mma_kernel,
                         cudaFuncAttributeMaxDynamicSharedMemorySize, AV_SMEM);

    // ---- prep; full conv GEMM is launch #6 (ncu -s 5 -c 1 lands here) ----
    split_kernel<<<DIMV * PATCHDIM / 256, 256>>>(conv_w, cwh, cwl);              // 1
    extract_patches_kernel<<<ROWS * PATCHDIM / 256, 256>>>(img, Xph, Xpl);       // 2
    wtrans_split_kernel<<<dim3(DIMV/32, DIMV/32, 1),     dim3(32,8)>>>(nl_w,  nlwh, nlwl, DIMV, DIMV);      // 3
    wtrans_split_kernel<<<dim3(PATCHDIM/32, DIMV/32, DEPTH), dim3(32,8)>>>(wqkv, qwh, qwl, DIMV, PATCHDIM); // 4
    wtrans_split_kernel<<<dim3(DIMV/32, DIMV/32, DEPTH), dim3(32,8)>>>(wo,    owh,  owl,  DIMV, DIMV);      // 5
    hmma_gemm_kernel<false><<<dim3(DIMV/128, ROWS/128), 256, HG_SMEM>>>(         // 6
        Xph, Xpl, cwh, cwl, conv_b, nullptr, x, nullptr, nullptr,
        ROWS, DIMV, PATCHDIM);
    wtrans_split_kernel<<<dim3(PATCHDIM/32, DIMV/32, 1), dim3(32,8)>>>(exp_w, ewh, ewl, DIMV, PATCHDIM);    // 7

    // ---- norm_linear + positional embedding ----
    ln_split_kernel<<<ROWS, 256>>>(x, nl_ln1_g, nl_ln1_b, hh, hl, DIMV);
    hmma_gemm_kernel<false><<<dim3(DIMV/128, ROWS/128), 256, HG_SMEM>>>(
        hh, hl, nlwh, nlwl, nl_b, nullptr, x, nullptr, nullptr, ROWS, DIMV, DIMV);
    ln_kernel<<<ROWS, 256>>>(x, nl_ln2_g, nl_ln2_b, x, DIMV);
    add_pos_kernel<<<ROWS * DIMV / 256, 256>>>(x, sph_pos, pos_w, pos_b);

    // ---- transformer layers ----
    for (int l = 0; l < DEPTH; l++) {
        ln_split_kernel<<<ROWS, 256>>>(x, ln_g + l * DIMV, ln_b + l * DIMV, hh, hl, DIMV);
        hmma_gemm_kernel<true><<<dim3(PATCHDIM/128, ROWS/128), 256, HG_SMEM>>>(
            hh, hl, qwh + (size_t)l * PATCHDIM * DIMV, qwl + (size_t)l * PATCHDIM * DIMV,
            nullptr, nullptr, nullptr, qkvh, qkvl, ROWS, PATCHDIM, DIMV);
        qk_mma_kernel<<<BATCH * NHEADS, 256, QK_SMEM>>>(qkvh, qkvl, sph_dist, w);
        std_softmax_kernel<<<BATCH * NTOK, 128>>>(w, ph, pl);
        av_mma_kernel<<<BATCH * NHEADS, 256, AV_SMEM>>>(ph, pl, qkvh, qkvl, oh, ol);
        hmma_gemm_kernel<false><<<dim3(DIMV/128, ROWS/128), 256, HG_SMEM>>>(
            oh, ol, owh + (size_t)l * DIMV * DIMV, owl + (size_t)l * DIMV * DIMV,
            wo_b + l * DIMV, x, x, nullptr, nullptr, ROWS, DIMV, DIMV);
    }

    // ---- final LN + expand + output LN + reassembly ----
    ln_split_kernel<<<ROWS, 256>>>(x, tr_ln_g, tr_ln_b, hh, hl, DIMV);
    hmma_gemm_kernel<false><<<dim3(PATCHDIM/128, ROWS/128), 256, HG_SMEM>>>(
        hh, hl, ewh, ewl, exp_b, nullptr, big, nullptr, nullptr, ROWS, PATCHDIM, DIMV);
    ln_kernel<<<ROWS, 256>>>(big, out_ln_g, out_ln_b, big, PATCHDIM);
    reassemble_kernel<<<ROWS * PATCHDIM / 256, 256>>>(big, (float*)d_out);
}

// round 9
// speedup vs baseline: 2.0727x; 1.3278x over previous
#include <cuda_runtime.h>
#include <cuda_fp16.h>
#include <cstdint>

// ---------------------------------------------------------------------------
// SphereViT forward — split-fp16 2-pass HMMA (x·wh exact; wl dropped ~2^-12).
// R9: bf16 3-pass -> fp16 2-pass everywhere; weight-lo arrays removed.
// ---------------------------------------------------------------------------

#define BATCH     32
#define NTOK      128
#define ROWS      4096
#define DIMV      1024
#define PATCHDIM  3072
#define NHEADS    16
#define DHEAD     64
#define DEPTH     12
#define LN_EPS    1e-5f

// -------------------- scratch (device globals; no allocs) ------------------
__device__ float g_big[ROWS * PATCHDIM];                 // expand output
__device__ float g_x  [ROWS * DIMV];                     // residual stream
__device__ float g_w  [BATCH * NHEADS * NTOK * NTOK];    // attention scores fp32

// split-fp16 activations
__device__ __half g_Xph[ROWS * PATCHDIM], g_Xpl[ROWS * PATCHDIM];
__device__ __half g_qkvh[ROWS * PATCHDIM], g_qkvl[ROWS * PATCHDIM];
__device__ __half g_hh [ROWS * DIMV],     g_hl [ROWS * DIMV];
__device__ __half g_oh [ROWS * DIMV],     g_ol [ROWS * DIMV];
__device__ __half g_ph [BATCH*NHEADS*NTOK*NTOK], g_pl [BATCH*NHEADS*NTOK*NTOK];

// fp16 transposed weights ([N,K] K-major), hi only
__device__ __half g_cwh[DIMV * PATCHDIM];
__device__ __half g_nlwh[DIMV * DIMV];
__device__ __half g_qwh[DEPTH * PATCHDIM * DIMV];
__device__ __half g_owh[DEPTH * DIMV * DIMV];
__device__ __half g_ewh[PATCHDIM * DIMV];

// ---------------------------------------------------------------------------
// PTX helpers
// ---------------------------------------------------------------------------
__device__ __forceinline__ uint32_t smem_u32(const void* p) {
    uint32_t a;
    asm("{ .reg .u64 t; cvta.to.shared.u64 t, %1; cvt.u32.u64 %0, t; }"
        : "=r"(a) : "l"(p));
    return a;
}
__device__ __forceinline__ void cpa16(uint32_t dst, const void* src) {
    asm volatile("cp.async.cg.shared.global [%0], [%1], 16;" :: "r"(dst), "l"(src));
}
__device__ __forceinline__ void cp_commit() { asm volatile("cp.async.commit_group;"); }
template <int NN>
__device__ __forceinline__ void cp_wait() {
    asm volatile("cp.async.wait_group %0;" :: "n"(NN));
}
__device__ __forceinline__ void ldsm4(uint32_t* r, uint32_t addr) {
    asm volatile("ldmatrix.sync.aligned.m8n8.x4.shared.b16 {%0,%1,%2,%3}, [%4];"
                 : "=r"(r[0]), "=r"(r[1]), "=r"(r[2]), "=r"(r[3]) : "r"(addr));
}
__device__ __forceinline__ void ldsm4t(uint32_t* r, uint32_t addr) {
    asm volatile("ldmatrix.sync.aligned.m8n8.x4.trans.shared.b16 {%0,%1,%2,%3}, [%4];"
                 : "=r"(r[0]), "=r"(r[1]), "=r"(r[2]), "=r"(r[3]) : "r"(addr));
}
__device__ __forceinline__ void mma16816(float* c, const uint32_t* a,
                                         const uint32_t* b) {
    asm volatile(
        "mma.sync.aligned.m16n8k16.row.col.f32.f16.f16.f32 "
        "{%0,%1,%2,%3}, {%4,%5,%6,%7}, {%8,%9}, {%0,%1,%2,%3};"
        : "+f"(c[0]), "+f"(c[1]), "+f"(c[2]), "+f"(c[3])
        : "r"(a[0]), "r"(a[1]), "r"(a[2]), "r"(a[3]), "r"(b[0]), "r"(b[1]));
}
__device__ __forceinline__ void split2(float v, __half& h, __half& l) {
    h = __float2half_rn(v);
    l = __float2half_rn(v - __half2float(h));
}

// ---------------------------------------------------------------------------
// Split-fp16 HMMA GEMM: C = (Ah+Al)[M,K] @ Bh[N,K]^T (+bias)(+res)
// 2 passes: Ah*Bh + Al*Bh.  OUTSPLIT: write split-fp16 (Ch,Cl).
// ---------------------------------------------------------------------------
#define GPAD 8
#define GLDS (32 + GPAD)
#define OPND_ELEMS (128 * GLDS)          // 5120
#define STAGE_ELEMS (3 * OPND_ELEMS)     // 15360
#define HG_SMEM (2 * STAGE_ELEMS * 2)    // 61440 bytes

template <bool OUTSPLIT>
__global__ __launch_bounds__(256, 2) void hmma_gemm_kernel(
    const __half* __restrict__ Ah, const __half* __restrict__ Al,
    const __half* __restrict__ Bh,
    const float* __restrict__ bias, const float* __restrict__ res,
    float* __restrict__ C, __half* __restrict__ Ch,
    __half* __restrict__ Cl, int M, int N, int K)
{
    extern __shared__ __half smem[];
    const uint32_t sbase = smem_u32(smem);
    const int tid  = threadIdx.x;
    const int lane = tid & 31, warp = tid >> 5;
    const int wm = warp & 1, wn = warp >> 1;
    const int m0 = blockIdx.y << 7, n0 = blockIdx.x << 7;

    const __half* g[3] = {
        Ah + (size_t)m0 * K, Al + (size_t)m0 * K, Bh + (size_t)n0 * K };

    const int r0c = tid >> 2;
    const int c0c = tid & 3;

    auto issue = [&](int stage, int k0) {
#pragma unroll
        for (int op = 0; op < 3; op++) {
            uint32_t sdst = sbase + (uint32_t)(stage * STAGE_ELEMS + op * OPND_ELEMS) * 2;
            const __half* gs = g[op];
#pragma unroll
            for (int half_ = 0; half_ < 2; half_++) {
                int r = r0c + half_ * 64;
                cpa16(sdst + (uint32_t)(r * GLDS + c0c * 8) * 2,
                      gs + (size_t)r * K + k0 + c0c * 8);
            }
        }
    };

    float acc[4][4][4];
#pragma unroll
    for (int i = 0; i < 4; i++)
#pragma unroll
        for (int j = 0; j < 4; j++)
#pragma unroll
            for (int q = 0; q < 4; q++) acc[i][j][q] = 0.f;

    const int nk = K >> 5;
    issue(0, 0);
    cp_commit();

    const int arow = wm * 64 + (lane & 15);
    const int acolb = (lane >> 4) * 8;
    const int brow = wn * 32 + ((lane >> 4) * 8) + (lane & 7);
    const int bcolb = ((lane >> 3) & 1) * 8;

    for (int it = 0; it < nk; ++it) {
        const int s = it & 1;
        if (it + 1 < nk) {
            issue(s ^ 1, (it + 1) << 5);
            cp_commit();
            cp_wait<1>();
        } else {
            cp_wait<0>();
        }
        __syncthreads();

        uint32_t sA  = sbase + (uint32_t)(s * STAGE_ELEMS) * 2;
        uint32_t sAl = sA + OPND_ELEMS * 2;
        uint32_t sB  = sA + 2 * OPND_ELEMS * 2;

#pragma unroll
        for (int ks = 0; ks < 2; ks++) {
            const int acol = ks * 16 + acolb;
            const int bcol = ks * 16 + bcolb;
            uint32_t ah[4][4], bh[4][2];
#pragma unroll
            for (int mi = 0; mi < 4; mi++)
                ldsm4(ah[mi], sA + (uint32_t)((arow + mi * 16) * GLDS + acol) * 2);
#pragma unroll
            for (int gp = 0; gp < 2; gp++) {
                uint32_t rh[4];
                ldsm4(rh, sB + (uint32_t)((brow + gp * 16) * GLDS + bcol) * 2);
                bh[gp*2][0] = rh[0]; bh[gp*2][1] = rh[1];
                bh[gp*2+1][0] = rh[2]; bh[gp*2+1][1] = rh[3];
            }
#pragma unroll
            for (int mi = 0; mi < 4; mi++)
#pragma unroll
                for (int nj = 0; nj < 4; nj++)
                    mma16816(acc[mi][nj], ah[mi], bh[nj]);

            uint32_t al[4][4];
#pragma unroll
            for (int mi = 0; mi < 4; mi++)
                ldsm4(al[mi], sAl + (uint32_t)((arow + mi * 16) * GLDS + acol) * 2);
#pragma unroll
            for (int mi = 0; mi < 4; mi++)
#pragma unroll
                for (int nj = 0; nj < 4; nj++)
                    mma16816(acc[mi][nj], al[mi], bh[nj]);
        }
        __syncthreads();
    }

    // epilogue
#pragma unroll
    for (int mi = 0; mi < 4; mi++) {
        int r0 = m0 + wm * 64 + mi * 16 + (lane >> 2);
#pragma unroll
        for (int nj = 0; nj < 4; nj++) {
            int c = n0 + wn * 32 + nj * 8 + (lane & 3) * 2;
            float v0x = acc[mi][nj][0], v0y = acc[mi][nj][1];
            float v1x = acc[mi][nj][2], v1y = acc[mi][nj][3];
            size_t o0 = (size_t)r0 * N + c;
            size_t o1 = o0 + (size_t)8 * N;
            if (OUTSPLIT) {
                __half h0, l0, h1, l1;
                split2(v0x, h0, l0); split2(v0y, h1, l1);
                *(__half2*)(Ch + o0) = __halves2half2(h0, h1);
                *(__half2*)(Cl + o0) = __halves2half2(l0, l1);
                split2(v1x, h0, l0); split2(v1y, h1, l1);
                *(__half2*)(Ch + o1) = __halves2half2(h0, h1);
                *(__half2*)(Cl + o1) = __halves2half2(l0, l1);
            } else {
                if (bias) {
                    float bx = bias[c], by = bias[c + 1];
                    v0x += bx; v0y += by; v1x += bx; v1y += by;
                }
                if (res) {
                    float2 ra = *(const float2*)(res + o0);
                    float2 rb = *(const float2*)(res + o1);
                    v0x += ra.x; v0y += ra.y; v1x += rb.x; v1y += rb.y;
                }
                *(float2*)(C + o0) = make_float2(v0x, v0y);
                *(float2*)(C + o1) = make_float2(v1x, v1y);
            }
        }
    }
}

// ---------------------------------------------------------------------------
// qk via HMMA: W[b,h,i,j] = ((qh+ql)_i . kh_j)*0.125*(1+dist). CTA per (b,h).
// ---------------------------------------------------------------------------
#define QKLD 72
#define QK_TILE (128 * QKLD)             // 9216 elems
#define QK_SMEM (3 * QK_TILE * 2)        // 55296 bytes

__global__ __launch_bounds__(256, 2) void qk_mma_kernel(
    const __half* __restrict__ qkvh, const __half* __restrict__ qkvl,
    const float* __restrict__ dist, float* __restrict__ W)
{
    extern __shared__ __half smem[];
    const uint32_t sbase = smem_u32(smem);
    const int tid = threadIdx.x, lane = tid & 31, warp = tid >> 5;
    const int wm = warp & 1, wn = warp >> 1;
    const int b = blockIdx.x >> 4, h = blockIdx.x & 15;
    const size_t rowbase = (size_t)b * NTOK * PATCHDIM + h * DHEAD;

    // tiles: 0=Qh 1=Ql 2=Kh.  Each tile: 128 rows x 64 fp16 = 1024 chunks.
    const __half* srcs[3] = { qkvh, qkvl, qkvh };
    const int offs[3] = { 0, 0, DIMV };
#pragma unroll
    for (int t = 0; t < 3; t++) {
        uint32_t dbase = sbase + (uint32_t)(t * QK_TILE) * 2;
#pragma unroll
        for (int p = 0; p < 4; p++) {
            int q = tid + p * 256;       // 0..1023
            int r = q >> 3, c = q & 7;
            cpa16(dbase + (uint32_t)(r * QKLD + c * 8) * 2,
                  srcs[t] + rowbase + (size_t)r * PATCHDIM + offs[t] + c * 8);
        }
    }
    cp_commit();
    cp_wait<0>();
    __syncthreads();

    float acc[4][4][4];
#pragma unroll
    for (int i = 0; i < 4; i++)
#pragma unroll
        for (int j = 0; j < 4; j++)
#pragma unroll
            for (int q = 0; q < 4; q++) acc[i][j][q] = 0.f;

    uint32_t sA  = sbase;
    uint32_t sAl = sbase + (uint32_t)QK_TILE * 2;
    uint32_t sB  = sbase + (uint32_t)(2 * QK_TILE) * 2;
    const int arow = wm * 64 + (lane & 15);
    const int acolb = (lane >> 4) * 8;
    const int brow = wn * 32 + ((lane >> 4) * 8) + (lane & 7);
    const int bcolb = ((lane >> 3) & 1) * 8;

#pragma unroll
    for (int ks = 0; ks < 4; ks++) {
        const int acol = ks * 16 + acolb;
        const int bcol = ks * 16 + bcolb;
        uint32_t ah[4][4], bh[4][2];
#pragma unroll
        for (int mi = 0; mi < 4; mi++)
            ldsm4(ah[mi], sA + (uint32_t)((arow + mi * 16) * QKLD + acol) * 2);
#pragma unroll
        for (int gp = 0; gp < 2; gp++) {
            uint32_t rh[4];
            ldsm4(rh, sB + (uint32_t)((brow + gp * 16) * QKLD + bcol) * 2);
            bh[gp*2][0] = rh[0]; bh[gp*2][1] = rh[1];
            bh[gp*2+1][0] = rh[2]; bh[gp*2+1][1] = rh[3];
        }
#pragma unroll
        for (int mi = 0; mi < 4; mi++)
#pragma unroll
            for (int nj = 0; nj < 4; nj++)
                mma16816(acc[mi][nj], ah[mi], bh[nj]);

        uint32_t al[4][4];
#pragma unroll
        for (int mi = 0; mi < 4; mi++)
            ldsm4(al[mi], sAl + (uint32_t)((arow + mi * 16) * QKLD + acol) * 2);
#pragma unroll
        for (int mi = 0; mi < 4; mi++)
#pragma unroll
            for (int nj = 0; nj < 4; nj++)
                mma16816(acc[mi][nj], al[mi], bh[nj]);
    }

    float* Wb = W + (size_t)blockIdx.x * (NTOK * NTOK);
#pragma unroll
    for (int mi = 0; mi < 4; mi++) {
        int i0 = wm * 64 + mi * 16 + (lane >> 2);
#pragma unroll
        for (int nj = 0; nj < 4; nj++) {
            int j0 = wn * 32 + nj * 8 + (lane & 3) * 2;
#pragma unroll
            for (int rr = 0; rr < 2; rr++) {
                int i = i0 + rr * 8;
                float vx = acc[mi][nj][rr*2], vy = acc[mi][nj][rr*2+1];
                Wb[i * 128 + j0]     = vx * 0.125f * (1.0f + dist[i * 128 + j0]);
                Wb[i * 128 + j0 + 1] = vy * 0.125f * (1.0f + dist[i * 128 + j0 + 1]);
            }
        }
    }
}

// ---------------------------------------------------------------------------
// Cross-head standardize (ddof=1) + softmax; emits split-fp16 P.
// ---------------------------------------------------------------------------
__global__ __launch_bounds__(128) void std_softmax_kernel(
    const float* __restrict__ W,
    __half* __restrict__ Ph, __half* __restrict__ Pl)
{
    int b = blockIdx.x >> 7, i = blockIdx.x & 127;
    int j = threadIdx.x;
    __shared__ float sm[NHEADS][128];

    size_t base = (size_t)b * (NHEADS * NTOK * NTOK) + (size_t)i * 128 + j;
    float vals[NHEADS];
    float s = 0.f;
#pragma unroll
    for (int h = 0; h < NHEADS; h++) {
        float v = W[base + (size_t)h * (NTOK * NTOK)];
        vals[h] = v; s += v;
    }
    float mu = s * (1.0f / 16.0f);
    float d2 = 0.f;
#pragma unroll
    for (int h = 0; h < NHEADS; h++) {
        float d = vals[h] - mu;
        d2 += d * d;
    }
    float inv = rsqrtf(d2 * (1.0f / 15.0f));
#pragma unroll
    for (int h = 0; h < NHEADS; h++) sm[h][j] = (vals[h] - mu) * inv;
    __syncthreads();

    int warp = j >> 5, lane = j & 31;
#pragma unroll
    for (int r = 0; r < 4; r++) {
        int h = warp * 4 + r;
        float v0 = sm[h][lane], v1 = sm[h][lane + 32];
        float v2 = sm[h][lane + 64], v3 = sm[h][lane + 96];
        float m = fmaxf(fmaxf(v0, v1), fmaxf(v2, v3));
#pragma unroll
        for (int o = 16; o; o >>= 1) m = fmaxf(m, __shfl_xor_sync(0xffffffffu, m, o));
        float e0 = expf(v0 - m), e1 = expf(v1 - m);
        float e2 = expf(v2 - m), e3 = expf(v3 - m);
        float sum = e0 + e1 + e2 + e3;
#pragma unroll
        for (int o = 16; o; o >>= 1) sum += __shfl_xor_sync(0xffffffffu, sum, o);
        float rs = 1.0f / sum;
        size_t wb = (size_t)b * (NHEADS * NTOK * NTOK) + (size_t)h * (NTOK * NTOK)
                  + (size_t)i * 128;
        float p0 = e0 * rs, p1 = e1 * rs, p2 = e2 * rs, p3 = e3 * rs;
        __half hh, ll;
        split2(p0, hh, ll); Ph[wb + lane]      = hh; Pl[wb + lane]      = ll;
        split2(p1, hh, ll); Ph[wb + lane + 32] = hh; Pl[wb + lane + 32] = ll;
        split2(p2, hh, ll); Ph[wb + lane + 64] = hh; Pl[wb + lane + 64] = ll;
        split2(p3, hh, ll); Ph[wb + lane + 96] = hh; Pl[wb + lane + 96] = ll;
    }
}

// ---------------------------------------------------------------------------
// av via HMMA: O[i, h*64+d] = sum_j (Ph+Pl)[i,j] * Vh[j,d].  CTA per (b,h).
// B = V [128 j][64 d] read via ldmatrix.trans.
// ---------------------------------------------------------------------------
#define AVPLD 136
#define AVVLD 72
#define AVP_TILE (128 * AVPLD)           // 17408 elems
#define AVV_TILE (128 * AVVLD)           // 9216 elems
#define AV_SMEM ((2 * AVP_TILE + AVV_TILE) * 2)   // 88064 bytes

__global__ __launch_bounds__(256, 2) void av_mma_kernel(
    const __half* __restrict__ Ph, const __half* __restrict__ Pl,
    const __half* __restrict__ qkvh,
    __half* __restrict__ Oh, __half* __restrict__ Ol)
{
    extern __shared__ __half smem[];
    const uint32_t sbase = smem_u32(smem);
    const int tid = threadIdx.x, lane = tid & 31, warp = tid >> 5;
    const int wm = warp & 3, wn = warp >> 2;
    const int b = blockIdx.x >> 4, h = blockIdx.x & 15;
    const size_t pbase = (size_t)blockIdx.x * (NTOK * NTOK);
    const size_t vbase = (size_t)b * NTOK * PATCHDIM + 2 * DIMV + h * DHEAD;

    // load P hi/lo via cp.async, [i][128] -> [i][AVPLD]
    const __half* psrc[2] = { Ph, Pl };
#pragma unroll
    for (int t = 0; t < 2; t++) {
        uint32_t dbase = sbase + (uint32_t)(t * AVP_TILE) * 2;
#pragma unroll
        for (int p = 0; p < 8; p++) {
            int q = tid + p * 256;       // 0..2047
            int r = q >> 4, c = q & 15;
            cpa16(dbase + (uint32_t)(r * AVPLD + c * 8) * 2,
                  psrc[t] + pbase + (size_t)r * 128 + c * 8);
        }
    }
    // load V hi via cp.async, [j][64] -> [j][AVVLD]
    {
        uint32_t dbase = sbase + (uint32_t)(2 * AVP_TILE) * 2;
#pragma unroll
        for (int p = 0; p < 4; p++) {
            int q = tid + p * 256;       // 0..1023
            int j = q >> 3, c = q & 7;
            cpa16(dbase + (uint32_t)(j * AVVLD + c * 8) * 2,
                  qkvh + vbase + (size_t)j * PATCHDIM + c * 8);
        }
    }
    cp_commit();
    cp_wait<0>();
    __syncthreads();

    float acc[2][4][4];
#pragma unroll
    for (int i = 0; i < 2; i++)
#pragma unroll
        for (int j = 0; j < 4; j++)
#pragma unroll
            for (int q = 0; q < 4; q++) acc[i][j][q] = 0.f;

    uint32_t sA  = sbase;
    uint32_t sAl = sbase + (uint32_t)AVP_TILE * 2;
    uint32_t sB  = sbase + (uint32_t)(2 * AVP_TILE) * 2;
    const int arow = wm * 32 + (lane & 15);
    const int acolb = (lane >> 4) * 8;
    const int bjrow = lane & 15;
    const int bdcol = (lane >> 4) * 8;

#pragma unroll
    for (int kc = 0; kc < 8; kc++) {
        const int acol = kc * 16 + acolb;
        uint32_t ah[2][4], bh[4][2];
#pragma unroll
        for (int mi = 0; mi < 2; mi++)
            ldsm4(ah[mi], sA + (uint32_t)((arow + mi * 16) * AVPLD + acol) * 2);
#pragma unroll
        for (int gp = 0; gp < 2; gp++) {
            uint32_t rh[4];
            uint32_t off = (uint32_t)((kc * 16 + bjrow) * AVVLD
                                      + wn * 32 + gp * 16 + bdcol) * 2;
            ldsm4t(rh, sB + off);
            bh[gp*2][0] = rh[0]; bh[gp*2][1] = rh[1];
            bh[gp*2+1][0] = rh[2]; bh[gp*2+1][1] = rh[3];
        }
#pragma unroll
        for (int mi = 0; mi < 2; mi++)
#pragma unroll
            for (int nj = 0; nj < 4; nj++)
                mma16816(acc[mi][nj], ah[mi], bh[nj]);

        uint32_t al[2][4];
#pragma unroll
        for (int mi = 0; mi < 2; mi++)
            ldsm4(al[mi], sAl + (uint32_t)((arow + mi * 16) * AVPLD + acol) * 2);
#pragma unroll
        for (int mi = 0; mi < 2; mi++)
#pragma unroll
            for (int nj = 0; nj < 4; nj++)
                mma16816(acc[mi][nj], al[mi], bh[nj]);
    }

#pragma unroll
    for (int mi = 0; mi < 2; mi++) {
        int i0 = wm * 32 + mi * 16 + (lane >> 2);
#pragma unroll
        for (int nj = 0; nj < 4; nj++) {
            int d0 = wn * 32 + nj * 8 + (lane & 3) * 2;
#pragma unroll
            for (int rr = 0; rr < 2; rr++) {
                int i = i0 + rr * 8;
                size_t o = (size_t)(b * 128 + i) * DIMV + h * DHEAD + d0;
                __half h0, l0, h1, l1;
                split2(acc[mi][nj][rr*2],     h0, l0);
                split2(acc[mi][nj][rr*2 + 1], h1, l1);
                *(__half2*)(Oh + o) = __halves2half2(h0, h1);
                *(__half2*)(Ol + o) = __halves2half2(l0, l1);
            }
        }
    }
}

// ---------------------------------------------------------------------------
// Weight prep (fp16 hi only)
// ---------------------------------------------------------------------------
__global__ void split_kernel(const float* __restrict__ X, __half* __restrict__ H) {
    size_t i = (size_t)blockIdx.x * 256 + threadIdx.x;
    H[i] = __float2half_rn(X[i]);
}

__global__ void wtrans_kernel(const float* __restrict__ W,
                              __half* __restrict__ Th, int K, int N) {
    __shared__ float t[32][33];
    const float* Wl = W + (size_t)blockIdx.z * K * N;
    size_t ob = (size_t)blockIdx.z * K * N;
    int x = blockIdx.x * 32 + threadIdx.x;
    int y = blockIdx.y * 32 + threadIdx.y;
#pragma unroll
    for (int j = 0; j < 32; j += 8)
        t[threadIdx.y + j][threadIdx.x] = Wl[(size_t)(y + j) * N + x];
    __syncthreads();
    int n = blockIdx.x * 32 + threadIdx.y;
    int k = blockIdx.y * 32 + threadIdx.x;
#pragma unroll
    for (int j = 0; j < 32; j += 8) {
        size_t o = ob + (size_t)(n + j) * K + k;
        Th[o] = __float2half_rn(t[threadIdx.x][threadIdx.y + j]);
    }
}

__global__ void extract_patches_kernel(const float* __restrict__ img,
                                       __half* __restrict__ H,
                                       __half* __restrict__ L) {
    int idx = blockIdx.x * 256 + threadIdx.x;
    int col = idx % PATCHDIM;
    int row = idx / PATCHDIM;
    int b = row >> 7, t = row & 127;
    int h = t >> 4, w = t & 15;
    int c = col >> 10, r = col & 1023;
    int p = r >> 5, q = r & 31;
    float v = img[(((size_t)b * 3 + c) * 256 + h * 32 + p) * 512 + w * 32 + q];
    split2(v, H[idx], L[idx]);
}

// ---------------------------------------------------------------------------
// LayerNorm
// ---------------------------------------------------------------------------
__device__ __forceinline__ void ln_stats(const float* __restrict__ x, size_t base,
                                         int D, float& mu, float& rstd) {
    float s = 0.f, ss = 0.f;
    for (int i = threadIdx.x; i < D; i += 256) {
        float v = x[base + i];
        s += v; ss += v * v;
    }
#pragma unroll
    for (int o = 16; o; o >>= 1) {
        s  += __shfl_xor_sync(0xffffffffu, s, o);
        ss += __shfl_xor_sync(0xffffffffu, ss, o);
    }
    __shared__ float sh[2][8];
    int w = threadIdx.x >> 5;
    if ((threadIdx.x & 31) == 0) { sh[0][w] = s; sh[1][w] = ss; }
    __syncthreads();
    if (threadIdx.x < 32) {
        s  = (threadIdx.x < 8) ? sh[0][threadIdx.x] : 0.f;
        ss = (threadIdx.x < 8) ? sh[1][threadIdx.x] : 0.f;
#pragma unroll
        for (int o = 4; o; o >>= 1) {
            s  += __shfl_xor_sync(0xffffffffu, s, o);
            ss += __shfl_xor_sync(0xffffffffu, ss, o);
        }
        if (threadIdx.x == 0) { sh[0][0] = s; sh[1][0] = ss; }
    }
    __syncthreads();
    s = sh[0][0]; ss = sh[1][0];
    float invD = 1.0f / (float)D;
    mu = s * invD;
    float var = ss * invD - mu * mu;
    rstd = rsqrtf(var + LN_EPS);
}

__global__ void ln_kernel(const float* __restrict__ x, const float* __restrict__ g,
                          const float* __restrict__ beta, float* __restrict__ y, int D) {
    size_t base = (size_t)blockIdx.x * D;
    float mu, rstd;
    ln_stats(x, base, D, mu, rstd);
    for (int i = threadIdx.x; i < D; i += 256)
        y[base + i] = (x[base + i] - mu) * rstd * g[i] + beta[i];
}

__global__ void ln_split_kernel(const float* __restrict__ x, const float* __restrict__ g,
                                const float* __restrict__ beta,
                                __half* __restrict__ H,
                                __half* __restrict__ L, int D) {
    size_t base = (size_t)blockIdx.x * D;
    float mu, rstd;
    ln_stats(x, base, D, mu, rstd);
    for (int i = threadIdx.x; i < D; i += 256) {
        float v = (x[base + i] - mu) * rstd * g[i] + beta[i];
        split2(v, H[base + i], L[base + i]);
    }
}

__global__ void add_pos_kernel(float* __restrict__ x, const float* __restrict__ sph_pos,
                               const float* __restrict__ pos_w,
                               const float* __restrict__ pos_b) {
    int idx = blockIdx.x * 256 + threadIdx.x;
    int d = idx & 1023;
    int i = (idx >> 10) & 127;
    x[idx] += sph_pos[i * 2] * pos_w[d] + sph_pos[i * 2 + 1] * pos_w[1024 + d] + pos_b[d];
}

__global__ void reassemble_kernel(const float* __restrict__ Y, float* __restrict__ out) {
    int idx = blockIdx.x * 256 + threadIdx.x;
    int xq = idx & 511;
    int rest = idx >> 9;
    int yr = rest & 255;
    rest >>= 8;
    int c = rest % 3;
    int b = rest / 3;
    int h = yr >> 5, p1 = yr & 31, w = xq >> 5, p2 = xq & 31;
    out[idx] = Y[(size_t)(b * 128 + h * 16 + w) * PATCHDIM + (p1 * 32 + p2) * 3 + c];
}

// ---------------------------------------------------------------------------
// Host launcher
// ---------------------------------------------------------------------------
extern "C" void kernel_launch(void* const* d_in, const int* in_sizes, int n_in,
                              void* d_out, int out_size)
{
    const float* img      = (const float*)d_in[0];
    const float* sph_pos  = (const float*)d_in[1];
    const float* sph_dist = (const float*)d_in[2];
    const float* conv_w   = (const float*)d_in[3];
    const float* conv_b   = (const float*)d_in[4];
    const float* nl_ln1_g = (const float*)d_in[5];
    const float* nl_ln1_b = (const float*)d_in[6];
    const float* nl_w     = (const float*)d_in[7];
    const float* nl_b     = (const float*)d_in[8];
    const float* nl_ln2_g = (const float*)d_in[9];
    const float* nl_ln2_b = (const float*)d_in[10];
    const float* pos_w    = (const float*)d_in[11];
    const float* pos_b    = (const float*)d_in[12];
    const float* ln_g     = (const float*)d_in[13];
    const float* ln_b     = (const float*)d_in[14];
    const float* wqkv     = (const float*)d_in[15];
    const float* wo       = (const float*)d_in[16];
    const float* wo_b     = (const float*)d_in[17];
    const float* tr_ln_g  = (const float*)d_in[18];
    const float* tr_ln_b  = (const float*)d_in[19];
    const float* exp_w    = (const float*)d_in[20];
    const float* exp_b    = (const float*)d_in[21];
    const float* out_ln_g = (const float*)d_in[22];
    const float* out_ln_b = (const float*)d_in[23];

    float *big, *x, *w;
    cudaGetSymbolAddress((void**)&big, g_big);
    cudaGetSymbolAddress((void**)&x,   g_x);
    cudaGetSymbolAddress((void**)&w,   g_w);
    __half *Xph, *Xpl, *qkvh, *qkvl, *hh, *hl, *oh, *ol, *ph, *pl;
    __half *cwh, *nlwh, *qwh, *owh, *ewh;
    cudaGetSymbolAddress((void**)&Xph, g_Xph);   cudaGetSymbolAddress((void**)&Xpl, g_Xpl);
    cudaGetSymbolAddress((void**)&qkvh, g_qkvh); cudaGetSymbolAddress((void**)&qkvl, g_qkvl);
    cudaGetSymbolAddress((void**)&hh,  g_hh);    cudaGetSymbolAddress((void**)&hl,  g_hl);
    cudaGetSymbolAddress((void**)&oh,  g_oh);    cudaGetSymbolAddress((void**)&ol,  g_ol);
    cudaGetSymbolAddress((void**)&ph,  g_ph);    cudaGetSymbolAddress((void**)&pl,  g_pl);
    cudaGetSymbolAddress((void**)&cwh, g_cwh);
    cudaGetSymbolAddress((void**)&nlwh, g_nlwh);
    cudaGetSymbolAddress((void**)&qwh, g_qwh);
    cudaGetSymbolAddress((void**)&owh, g_owh);
    cudaGetSymbolAddress((void**)&ewh, g_ewh);

    cudaFuncSetAttribute(hmma_gemm_kernel<false>,
                         cudaFuncAttributeMaxDynamicSharedMemorySize, HG_SMEM);
    cudaFuncSetAttribute(hmma_gemm_kernel<true>,
                         cudaFuncAttributeMaxDynamicSharedMemorySize, HG_SMEM);
    cudaFuncSetAttribute(qk_mma_kernel,
                         cudaFuncAttributeMaxDynamicSharedMemorySize, QK_SMEM);
    cudaFuncSetAttribute(av_mma_kernel,
                         cudaFuncAttributeMaxDynamicSharedMemorySize, AV_SMEM);

    // ---- prep ----
    split_kernel<<<DIMV * PATCHDIM / 256, 256>>>(conv_w, cwh);
    extract_patches_kernel<<<ROWS * PATCHDIM / 256, 256>>>(img, Xph, Xpl);
    wtrans_kernel<<<dim3(DIMV/32, DIMV/32, 1),     dim3(32,8)>>>(nl_w,  nlwh, DIMV, DIMV);
    wtrans_kernel<<<dim3(PATCHDIM/32, DIMV/32, DEPTH), dim3(32,8)>>>(wqkv, qwh, DIMV, PATCHDIM);
    wtrans_kernel<<<dim3(DIMV/32, DIMV/32, DEPTH), dim3(32,8)>>>(wo,    owh,  DIMV, DIMV);
    hmma_gemm_kernel<false><<<dim3(DIMV/128, ROWS/128), 256, HG_SMEM>>>(
        Xph, Xpl, cwh, conv_b, nullptr, x, nullptr, nullptr, ROWS, DIMV, PATCHDIM);
    wtrans_kernel<<<dim3(PATCHDIM/32, DIMV/32, 1), dim3(32,8)>>>(exp_w, ewh, DIMV, PATCHDIM);

    // ---- norm_linear + positional embedding ----
    ln_split_kernel<<<ROWS, 256>>>(x, nl_ln1_g, nl_ln1_b, hh, hl, DIMV);
    hmma_gemm_kernel<false><<<dim3(DIMV/128, ROWS/128), 256, HG_SMEM>>>(
        hh, hl, nlwh, nl_b, nullptr, x, nullptr, nullptr, ROWS, DIMV, DIMV);
    ln_kernel<<<ROWS, 256>>>(x, nl_ln2_g, nl_ln2_b, x, DIMV);
    add_pos_kernel<<<ROWS * DIMV / 256, 256>>>(x, sph_pos, pos_w, pos_b);

    // ---- transformer layers ----
    for (int l = 0; l < DEPTH; l++) {
        ln_split_kernel<<<ROWS, 256>>>(x, ln_g + l * DIMV, ln_b + l * DIMV, hh, hl, DIMV);
        hmma_gemm_kernel<true><<<dim3(PATCHDIM/128, ROWS/128), 256, HG_SMEM>>>(
            hh, hl, qwh + (size_t)l * PATCHDIM * DIMV,
            nullptr, nullptr, nullptr, qkvh, qkvl, ROWS, PATCHDIM, DIMV);
        qk_mma_kernel<<<BATCH * NHEADS, 256, QK_SMEM>>>(qkvh, qkvl, sph_dist, w);
        std_softmax_kernel<<<BATCH * NTOK, 128>>>(w, ph, pl);
        av_mma_kernel<<<BATCH * NHEADS, 256, AV_SMEM>>>(ph, pl, qkvh, oh, ol);
        hmma_gemm_kernel<false><<<dim3(DIMV/128, ROWS/128), 256, HG_SMEM>>>(
            oh, ol, owh + (size_t)l * DIMV * DIMV,
            wo_b + l * DIMV, x, x, nullptr, nullptr, ROWS, DIMV, DIMV);
    }

    // ---- final LN + expand + output LN + reassembly ----
    ln_split_kernel<<<ROWS, 256>>>(x, tr_ln_g, tr_ln_b, hh, hl, DIMV);
    hmma_gemm_kernel<false><<<dim3(PATCHDIM/128, ROWS/128), 256, HG_SMEM>>>(
        hh, hl, ewh, exp_b, nullptr, big, nullptr, nullptr, ROWS, PATCHDIM, DIMV);
    ln_kernel<<<ROWS, 256>>>(big, out_ln_g, out_ln_b, big, PATCHDIM);
    reassemble_kernel<<<ROWS * PATCHDIM / 256, 256>>>(big, (float*)d_out);
}

// round 10
// speedup vs baseline: 2.1731x; 1.0485x over previous
#include <cuda_runtime.h>
#include <cuda_fp16.h>
#include <cstdint>

// ---------------------------------------------------------------------------
// SphereViT forward — split-fp16 2-pass weight GEMMs, single-pass fp16
// attention matmuls. R10: drop q/k/p lo-planes; fuse add_pos into LN.
// ---------------------------------------------------------------------------

#define BATCH     32
#define NTOK      128
#define ROWS      4096
#define DIMV      1024
#define PATCHDIM  3072
#define NHEADS    16
#define DHEAD     64
#define DEPTH     12
#define LN_EPS    1e-5f

// -------------------- scratch (device globals; no allocs) ------------------
__device__ float g_big[ROWS * PATCHDIM];                 // expand output
__device__ float g_x  [ROWS * DIMV];                     // residual stream
__device__ float g_w  [BATCH * NHEADS * NTOK * NTOK];    // attention scores fp32

// fp16 activations
__device__ __half g_Xph[ROWS * PATCHDIM], g_Xpl[ROWS * PATCHDIM];
__device__ __half g_qkvh[ROWS * PATCHDIM];               // q/k/v hi only
__device__ __half g_hh [ROWS * DIMV],     g_hl [ROWS * DIMV];
__device__ __half g_oh [ROWS * DIMV],     g_ol [ROWS * DIMV];
__device__ __half g_ph [BATCH*NHEADS*NTOK*NTOK];         // probs hi only

// fp16 transposed weights ([N,K] K-major), hi only
__device__ __half g_cwh[DIMV * PATCHDIM];
__device__ __half g_nlwh[DIMV * DIMV];
__device__ __half g_qwh[DEPTH * PATCHDIM * DIMV];
__device__ __half g_owh[DEPTH * DIMV * DIMV];
__device__ __half g_ewh[PATCHDIM * DIMV];

// ---------------------------------------------------------------------------
// PTX helpers
// ---------------------------------------------------------------------------
__device__ __forceinline__ uint32_t smem_u32(const void* p) {
    uint32_t a;
    asm("{ .reg .u64 t; cvta.to.shared.u64 t, %1; cvt.u32.u64 %0, t; }"
        : "=r"(a) : "l"(p));
    return a;
}
__device__ __forceinline__ void cpa16(uint32_t dst, const void* src) {
    asm volatile("cp.async.cg.shared.global [%0], [%1], 16;" :: "r"(dst), "l"(src));
}
__device__ __forceinline__ void cp_commit() { asm volatile("cp.async.commit_group;"); }
template <int NN>
__device__ __forceinline__ void cp_wait() {
    asm volatile("cp.async.wait_group %0;" :: "n"(NN));
}
__device__ __forceinline__ void ldsm4(uint32_t* r, uint32_t addr) {
    asm volatile("ldmatrix.sync.aligned.m8n8.x4.shared.b16 {%0,%1,%2,%3}, [%4];"
                 : "=r"(r[0]), "=r"(r[1]), "=r"(r[2]), "=r"(r[3]) : "r"(addr));
}
__device__ __forceinline__ void ldsm4t(uint32_t* r, uint32_t addr) {
    asm volatile("ldmatrix.sync.aligned.m8n8.x4.trans.shared.b16 {%0,%1,%2,%3}, [%4];"
                 : "=r"(r[0]), "=r"(r[1]), "=r"(r[2]), "=r"(r[3]) : "r"(addr));
}
__device__ __forceinline__ void mma16816(float* c, const uint32_t* a,
                                         const uint32_t* b) {
    asm volatile(
        "mma.sync.aligned.m16n8k16.row.col.f32.f16.f16.f32 "
        "{%0,%1,%2,%3}, {%4,%5,%6,%7}, {%8,%9}, {%0,%1,%2,%3};"
        : "+f"(c[0]), "+f"(c[1]), "+f"(c[2]), "+f"(c[3])
        : "r"(a[0]), "r"(a[1]), "r"(a[2]), "r"(a[3]), "r"(b[0]), "r"(b[1]));
}
__device__ __forceinline__ void split2(float v, __half& h, __half& l) {
    h = __float2half_rn(v);
    l = __float2half_rn(v - __half2float(h));
}

// ---------------------------------------------------------------------------
// Split-fp16 HMMA GEMM: C = (Ah+Al)[M,K] @ Bh[N,K]^T (+bias)(+res)
// OM: 0 = fp32 C (+bias +res), 1 = split-fp16 (Ch,Cl), 2 = fp16 hi-only Ch.
// ---------------------------------------------------------------------------
#define GPAD 8
#define GLDS (32 + GPAD)
#define OPND_ELEMS (128 * GLDS)          // 5120
#define STAGE_ELEMS (3 * OPND_ELEMS)     // 15360
#define HG_SMEM (2 * STAGE_ELEMS * 2)    // 61440 bytes

template <int OM>
__global__ __launch_bounds__(256, 2) void hmma_gemm_kernel(
    const __half* __restrict__ Ah, const __half* __restrict__ Al,
    const __half* __restrict__ Bh,
    const float* __restrict__ bias, const float* __restrict__ res,
    float* __restrict__ C, __half* __restrict__ Ch,
    __half* __restrict__ Cl, int M, int N, int K)
{
    extern __shared__ __half smem[];
    const uint32_t sbase = smem_u32(smem);
    const int tid  = threadIdx.x;
    const int lane = tid & 31, warp = tid >> 5;
    const int wm = warp & 1, wn = warp >> 1;
    const int m0 = blockIdx.y << 7, n0 = blockIdx.x << 7;

    const __half* g[3] = {
        Ah + (size_t)m0 * K, Al + (size_t)m0 * K, Bh + (size_t)n0 * K };

    const int r0c = tid >> 2;
    const int c0c = tid & 3;

    auto issue = [&](int stage, int k0) {
#pragma unroll
        for (int op = 0; op < 3; op++) {
            uint32_t sdst = sbase + (uint32_t)(stage * STAGE_ELEMS + op * OPND_ELEMS) * 2;
            const __half* gs = g[op];
#pragma unroll
            for (int half_ = 0; half_ < 2; half_++) {
                int r = r0c + half_ * 64;
                cpa16(sdst + (uint32_t)(r * GLDS + c0c * 8) * 2,
                      gs + (size_t)r * K + k0 + c0c * 8);
            }
        }
    };

    float acc[4][4][4];
#pragma unroll
    for (int i = 0; i < 4; i++)
#pragma unroll
        for (int j = 0; j < 4; j++)
#pragma unroll
            for (int q = 0; q < 4; q++) acc[i][j][q] = 0.f;

    const int nk = K >> 5;
    issue(0, 0);
    cp_commit();

    const int arow = wm * 64 + (lane & 15);
    const int acolb = (lane >> 4) * 8;
    const int brow = wn * 32 + ((lane >> 4) * 8) + (lane & 7);
    const int bcolb = ((lane >> 3) & 1) * 8;

    for (int it = 0; it < nk; ++it) {
        const int s = it & 1;
        if (it + 1 < nk) {
            issue(s ^ 1, (it + 1) << 5);
            cp_commit();
            cp_wait<1>();
        } else {
            cp_wait<0>();
        }
        __syncthreads();

        uint32_t sA  = sbase + (uint32_t)(s * STAGE_ELEMS) * 2;
        uint32_t sAl = sA + OPND_ELEMS * 2;
        uint32_t sB  = sA + 2 * OPND_ELEMS * 2;

#pragma unroll
        for (int ks = 0; ks < 2; ks++) {
            const int acol = ks * 16 + acolb;
            const int bcol = ks * 16 + bcolb;
            uint32_t ah[4][4], bh[4][2];
#pragma unroll
            for (int mi = 0; mi < 4; mi++)
                ldsm4(ah[mi], sA + (uint32_t)((arow + mi * 16) * GLDS + acol) * 2);
#pragma unroll
            for (int gp = 0; gp < 2; gp++) {
                uint32_t rh[4];
                ldsm4(rh, sB + (uint32_t)((brow + gp * 16) * GLDS + bcol) * 2);
                bh[gp*2][0] = rh[0]; bh[gp*2][1] = rh[1];
                bh[gp*2+1][0] = rh[2]; bh[gp*2+1][1] = rh[3];
            }
#pragma unroll
            for (int mi = 0; mi < 4; mi++)
#pragma unroll
                for (int nj = 0; nj < 4; nj++)
                    mma16816(acc[mi][nj], ah[mi], bh[nj]);

            uint32_t al[4][4];
#pragma unroll
            for (int mi = 0; mi < 4; mi++)
                ldsm4(al[mi], sAl + (uint32_t)((arow + mi * 16) * GLDS + acol) * 2);
#pragma unroll
            for (int mi = 0; mi < 4; mi++)
#pragma unroll
                for (int nj = 0; nj < 4; nj++)
                    mma16816(acc[mi][nj], al[mi], bh[nj]);
        }
        __syncthreads();
    }

    // epilogue
#pragma unroll
    for (int mi = 0; mi < 4; mi++) {
        int r0 = m0 + wm * 64 + mi * 16 + (lane >> 2);
#pragma unroll
        for (int nj = 0; nj < 4; nj++) {
            int c = n0 + wn * 32 + nj * 8 + (lane & 3) * 2;
            float v0x = acc[mi][nj][0], v0y = acc[mi][nj][1];
            float v1x = acc[mi][nj][2], v1y = acc[mi][nj][3];
            size_t o0 = (size_t)r0 * N + c;
            size_t o1 = o0 + (size_t)8 * N;
            if (OM == 1) {
                __half h0, l0, h1, l1;
                split2(v0x, h0, l0); split2(v0y, h1, l1);
                *(__half2*)(Ch + o0) = __halves2half2(h0, h1);
                *(__half2*)(Cl + o0) = __halves2half2(l0, l1);
                split2(v1x, h0, l0); split2(v1y, h1, l1);
                *(__half2*)(Ch + o1) = __halves2half2(h0, h1);
                *(__half2*)(Cl + o1) = __halves2half2(l0, l1);
            } else if (OM == 2) {
                *(__half2*)(Ch + o0) =
                    __halves2half2(__float2half_rn(v0x), __float2half_rn(v0y));
                *(__half2*)(Ch + o1) =
                    __halves2half2(__float2half_rn(v1x), __float2half_rn(v1y));
            } else {
                if (bias) {
                    float bx = bias[c], by = bias[c + 1];
                    v0x += bx; v0y += by; v1x += bx; v1y += by;
                }
                if (res) {
                    float2 ra = *(const float2*)(res + o0);
                    float2 rb = *(const float2*)(res + o1);
                    v0x += ra.x; v0y += ra.y; v1x += rb.x; v1y += rb.y;
                }
                *(float2*)(C + o0) = make_float2(v0x, v0y);
                *(float2*)(C + o1) = make_float2(v1x, v1y);
            }
        }
    }
}

// ---------------------------------------------------------------------------
// qk via HMMA (single pass): W = (qh_i . kh_j)*0.125*(1+dist). CTA per (b,h).
// ---------------------------------------------------------------------------
#define QKLD 72
#define QK_TILE (128 * QKLD)             // 9216 elems
#define QK_SMEM (2 * QK_TILE * 2)        // 36864 bytes

__global__ __launch_bounds__(256, 2) void qk_mma_kernel(
    const __half* __restrict__ qkvh,
    const float* __restrict__ dist, float* __restrict__ W)
{
    extern __shared__ __half smem[];
    const uint32_t sbase = smem_u32(smem);
    const int tid = threadIdx.x, lane = tid & 31, warp = tid >> 5;
    const int wm = warp & 1, wn = warp >> 1;
    const int b = blockIdx.x >> 4, h = blockIdx.x & 15;
    const size_t rowbase = (size_t)b * NTOK * PATCHDIM + h * DHEAD;

    const int offs[2] = { 0, DIMV };     // 0=Qh 1=Kh
#pragma unroll
    for (int t = 0; t < 2; t++) {
        uint32_t dbase = sbase + (uint32_t)(t * QK_TILE) * 2;
#pragma unroll
        for (int p = 0; p < 4; p++) {
            int q = tid + p * 256;       // 0..1023
            int r = q >> 3, c = q & 7;
            cpa16(dbase + (uint32_t)(r * QKLD + c * 8) * 2,
                  qkvh + rowbase + (size_t)r * PATCHDIM + offs[t] + c * 8);
        }
    }
    cp_commit();
    cp_wait<0>();
    __syncthreads();

    float acc[4][4][4];
#pragma unroll
    for (int i = 0; i < 4; i++)
#pragma unroll
        for (int j = 0; j < 4; j++)
#pragma unroll
            for (int q = 0; q < 4; q++) acc[i][j][q] = 0.f;

    uint32_t sA  = sbase;
    uint32_t sB  = sbase + (uint32_t)QK_TILE * 2;
    const int arow = wm * 64 + (lane & 15);
    const int acolb = (lane >> 4) * 8;
    const int brow = wn * 32 + ((lane >> 4) * 8) + (lane & 7);
    const int bcolb = ((lane >> 3) & 1) * 8;

#pragma unroll
    for (int ks = 0; ks < 4; ks++) {
        const int acol = ks * 16 + acolb;
        const int bcol = ks * 16 + bcolb;
        uint32_t ah[4][4], bh[4][2];
#pragma unroll
        for (int mi = 0; mi < 4; mi++)
            ldsm4(ah[mi], sA + (uint32_t)((arow + mi * 16) * QKLD + acol) * 2);
#pragma unroll
        for (int gp = 0; gp < 2; gp++) {
            uint32_t rh[4];
            ldsm4(rh, sB + (uint32_t)((brow + gp * 16) * QKLD + bcol) * 2);
            bh[gp*2][0] = rh[0]; bh[gp*2][1] = rh[1];
            bh[gp*2+1][0] = rh[2]; bh[gp*2+1][1] = rh[3];
        }
#pragma unroll
        for (int mi = 0; mi < 4; mi++)
#pragma unroll
            for (int nj = 0; nj < 4; nj++)
                mma16816(acc[mi][nj], ah[mi], bh[nj]);
    }

    float* Wb = W + (size_t)blockIdx.x * (NTOK * NTOK);
#pragma unroll
    for (int mi = 0; mi < 4; mi++) {
        int i0 = wm * 64 + mi * 16 + (lane >> 2);
#pragma unroll
        for (int nj = 0; nj < 4; nj++) {
            int j0 = wn * 32 + nj * 8 + (lane & 3) * 2;
#pragma unroll
            for (int rr = 0; rr < 2; rr++) {
                int i = i0 + rr * 8;
                float vx = acc[mi][nj][rr*2], vy = acc[mi][nj][rr*2+1];
                Wb[i * 128 + j0]     = vx * 0.125f * (1.0f + dist[i * 128 + j0]);
                Wb[i * 128 + j0 + 1] = vy * 0.125f * (1.0f + dist[i * 128 + j0 + 1]);
            }
        }
    }
}

// ---------------------------------------------------------------------------
// Cross-head standardize (ddof=1) + softmax; emits fp16 P (hi only).
// ---------------------------------------------------------------------------
__global__ __launch_bounds__(128) void std_softmax_kernel(
    const float* __restrict__ W, __half* __restrict__ Ph)
{
    int b = blockIdx.x >> 7, i = blockIdx.x & 127;
    int j = threadIdx.x;
    __shared__ float sm[NHEADS][128];

    size_t base = (size_t)b * (NHEADS * NTOK * NTOK) + (size_t)i * 128 + j;
    float vals[NHEADS];
    float s = 0.f;
#pragma unroll
    for (int h = 0; h < NHEADS; h++) {
        float v = W[base + (size_t)h * (NTOK * NTOK)];
        vals[h] = v; s += v;
    }
    float mu = s * (1.0f / 16.0f);
    float d2 = 0.f;
#pragma unroll
    for (int h = 0; h < NHEADS; h++) {
        float d = vals[h] - mu;
        d2 += d * d;
    }
    float inv = rsqrtf(d2 * (1.0f / 15.0f));
#pragma unroll
    for (int h = 0; h < NHEADS; h++) sm[h][j] = (vals[h] - mu) * inv;
    __syncthreads();

    int warp = j >> 5, lane = j & 31;
#pragma unroll
    for (int r = 0; r < 4; r++) {
        int h = warp * 4 + r;
        float v0 = sm[h][lane], v1 = sm[h][lane + 32];
        float v2 = sm[h][lane + 64], v3 = sm[h][lane + 96];
        float m = fmaxf(fmaxf(v0, v1), fmaxf(v2, v3));
#pragma unroll
        for (int o = 16; o; o >>= 1) m = fmaxf(m, __shfl_xor_sync(0xffffffffu, m, o));
        float e0 = expf(v0 - m), e1 = expf(v1 - m);
        float e2 = expf(v2 - m), e3 = expf(v3 - m);
        float sum = e0 + e1 + e2 + e3;
#pragma unroll
        for (int o = 16; o; o >>= 1) sum += __shfl_xor_sync(0xffffffffu, sum, o);
        float rs = 1.0f / sum;
        size_t wb = (size_t)b * (NHEADS * NTOK * NTOK) + (size_t)h * (NTOK * NTOK)
                  + (size_t)i * 128;
        Ph[wb + lane]      = __float2half_rn(e0 * rs);
        Ph[wb + lane + 32] = __float2half_rn(e1 * rs);
        Ph[wb + lane + 64] = __float2half_rn(e2 * rs);
        Ph[wb + lane + 96] = __float2half_rn(e3 * rs);
    }
}

// ---------------------------------------------------------------------------
// av via HMMA (single pass): O[i,h*64+d] = sum_j Ph[i,j]*Vh[j,d]. CTA per (b,h).
// ---------------------------------------------------------------------------
#define AVPLD 136
#define AVVLD 72
#define AVP_TILE (128 * AVPLD)           // 17408 elems
#define AVV_TILE (128 * AVVLD)           // 9216 elems
#define AV_SMEM ((AVP_TILE + AVV_TILE) * 2)   // 53248 bytes

__global__ __launch_bounds__(256, 2) void av_mma_kernel(
    const __half* __restrict__ Ph, const __half* __restrict__ qkvh,
    __half* __restrict__ Oh, __half* __restrict__ Ol)
{
    extern __shared__ __half smem[];
    const uint32_t sbase = smem_u32(smem);
    const int tid = threadIdx.x, lane = tid & 31, warp = tid >> 5;
    const int wm = warp & 3, wn = warp >> 2;
    const int b = blockIdx.x >> 4, h = blockIdx.x & 15;
    const size_t pbase = (size_t)blockIdx.x * (NTOK * NTOK);
    const size_t vbase = (size_t)b * NTOK * PATCHDIM + 2 * DIMV + h * DHEAD;

    // load P via cp.async, [i][128] -> [i][AVPLD]
#pragma unroll
    for (int p = 0; p < 8; p++) {
        int q = tid + p * 256;           // 0..2047
        int r = q >> 4, c = q & 15;
        cpa16(sbase + (uint32_t)(r * AVPLD + c * 8) * 2,
              Ph + pbase + (size_t)r * 128 + c * 8);
    }
    // load V via cp.async, [j][64] -> [j][AVVLD]
    {
        uint32_t dbase = sbase + (uint32_t)AVP_TILE * 2;
#pragma unroll
        for (int p = 0; p < 4; p++) {
            int q = tid + p * 256;       // 0..1023
            int j = q >> 3, c = q & 7;
            cpa16(dbase + (uint32_t)(j * AVVLD + c * 8) * 2,
                  qkvh + vbase + (size_t)j * PATCHDIM + c * 8);
        }
    }
    cp_commit();
    cp_wait<0>();
    __syncthreads();

    float acc[2][4][4];
#pragma unroll
    for (int i = 0; i < 2; i++)
#pragma unroll
        for (int j = 0; j < 4; j++)
#pragma unroll
            for (int q = 0; q < 4; q++) acc[i][j][q] = 0.f;

    uint32_t sA  = sbase;
    uint32_t sB  = sbase + (uint32_t)AVP_TILE * 2;
    const int arow = wm * 32 + (lane & 15);
    const int acolb = (lane >> 4) * 8;
    const int bjrow = lane & 15;
    const int bdcol = (lane >> 4) * 8;

#pragma unroll
    for (int kc = 0; kc < 8; kc++) {
        const int acol = kc * 16 + acolb;
        uint32_t ah[2][4], bh[4][2];
#pragma unroll
        for (int mi = 0; mi < 2; mi++)
            ldsm4(ah[mi], sA + (uint32_t)((arow + mi * 16) * AVPLD + acol) * 2);
#pragma unroll
        for (int gp = 0; gp < 2; gp++) {
            uint32_t rh[4];
            uint32_t off = (uint32_t)((kc * 16 + bjrow) * AVVLD
                                      + wn * 32 + gp * 16 + bdcol) * 2;
            ldsm4t(rh, sB + off);
            bh[gp*2][0] = rh[0]; bh[gp*2][1] = rh[1];
            bh[gp*2+1][0] = rh[2]; bh[gp*2+1][1] = rh[3];
        }
#pragma unroll
        for (int mi = 0; mi < 2; mi++)
#pragma unroll
            for (int nj = 0; nj < 4; nj++)
                mma16816(acc[mi][nj], ah[mi], bh[nj]);
    }

#pragma unroll
    for (int mi = 0; mi < 2; mi++) {
        int i0 = wm * 32 + mi * 16 + (lane >> 2);
#pragma unroll
        for (int nj = 0; nj < 4; nj++) {
            int d0 = wn * 32 + nj * 8 + (lane & 3) * 2;
#pragma unroll
            for (int rr = 0; rr < 2; rr++) {
                int i = i0 + rr * 8;
                size_t o = (size_t)(b * 128 + i) * DIMV + h * DHEAD + d0;
                __half h0, l0, h1, l1;
                split2(acc[mi][nj][rr*2],     h0, l0);
                split2(acc[mi][nj][rr*2 + 1], h1, l1);
                *(__half2*)(Oh + o) = __halves2half2(h0, h1);
                *(__half2*)(Ol + o) = __halves2half2(l0, l1);
            }
        }
    }
}

// ---------------------------------------------------------------------------
// Weight prep (fp16 hi only)
// ---------------------------------------------------------------------------
__global__ void split_kernel(const float* __restrict__ X, __half* __restrict__ H) {
    size_t i = (size_t)blockIdx.x * 256 + threadIdx.x;
    H[i] = __float2half_rn(X[i]);
}

__global__ void wtrans_kernel(const float* __restrict__ W,
                              __half* __restrict__ Th, int K, int N) {
    __shared__ float t[32][33];
    const float* Wl = W + (size_t)blockIdx.z * K * N;
    size_t ob = (size_t)blockIdx.z * K * N;
    int x = blockIdx.x * 32 + threadIdx.x;
    int y = blockIdx.y * 32 + threadIdx.y;
#pragma unroll
    for (int j = 0; j < 32; j += 8)
        t[threadIdx.y + j][threadIdx.x] = Wl[(size_t)(y + j) * N + x];
    __syncthreads();
    int n = blockIdx.x * 32 + threadIdx.y;
    int k = blockIdx.y * 32 + threadIdx.x;
#pragma unroll
    for (int j = 0; j < 32; j += 8) {
        size_t o = ob + (size_t)(n + j) * K + k;
        Th[o] = __float2half_rn(t[threadIdx.x][threadIdx.y + j]);
    }
}

__global__ void extract_patches_kernel(const float* __restrict__ img,
                                       __half* __restrict__ H,
                                       __half* __restrict__ L) {
    int idx = blockIdx.x * 256 + threadIdx.x;
    int col = idx % PATCHDIM;
    int row = idx / PATCHDIM;
    int b = row >> 7, t = row & 127;
    int h = t >> 4, w = t & 15;
    int c = col >> 10, r = col & 1023;
    int p = r >> 5, q = r & 31;
    float v = img[(((size_t)b * 3 + c) * 256 + h * 32 + p) * 512 + w * 32 + q];
    split2(v, H[idx], L[idx]);
}

// ---------------------------------------------------------------------------
// LayerNorm
// ---------------------------------------------------------------------------
__device__ __forceinline__ void ln_stats(const float* __restrict__ x, size_t base,
                                         int D, float& mu, float& rstd) {
    float s = 0.f, ss = 0.f;
    for (int i = threadIdx.x; i < D; i += 256) {
        float v = x[base + i];
        s += v; ss += v * v;
    }
#pragma unroll
    for (int o = 16; o; o >>= 1) {
        s  += __shfl_xor_sync(0xffffffffu, s, o);
        ss += __shfl_xor_sync(0xffffffffu, ss, o);
    }
    __shared__ float sh[2][8];
    int w = threadIdx.x >> 5;
    if ((threadIdx.x & 31) == 0) { sh[0][w] = s; sh[1][w] = ss; }
    __syncthreads();
    if (threadIdx.x < 32) {
        s  = (threadIdx.x < 8) ? sh[0][threadIdx.x] : 0.f;
        ss = (threadIdx.x < 8) ? sh[1][threadIdx.x] : 0.f;
#pragma unroll
        for (int o = 4; o; o >>= 1) {
            s  += __shfl_xor_sync(0xffffffffu, s, o);
            ss += __shfl_xor_sync(0xffffffffu, ss, o);
        }
        if (threadIdx.x == 0) { sh[0][0] = s; sh[1][0] = ss; }
    }
    __syncthreads();
    s = sh[0][0]; ss = sh[1][0];
    float invD = 1.0f / (float)D;
    mu = s * invD;
    float var = ss * invD - mu * mu;
    rstd = rsqrtf(var + LN_EPS);
}

__global__ void ln_kernel(const float* __restrict__ x, const float* __restrict__ g,
                          const float* __restrict__ beta, float* __restrict__ y, int D) {
    size_t base = (size_t)blockIdx.x * D;
    float mu, rstd;
    ln_stats(x, base, D, mu, rstd);
    for (int i = threadIdx.x; i < D; i += 256)
        y[base + i] = (x[base + i] - mu) * rstd * g[i] + beta[i];
}

// LN then add positional embedding: y = LN(x)*g+b + (sph_pos[row%128] @ pos_w + pos_b)
__global__ void ln_addpos_kernel(const float* __restrict__ x, const float* __restrict__ g,
                                 const float* __restrict__ beta,
                                 const float* __restrict__ sph_pos,
                                 const float* __restrict__ pos_w,
                                 const float* __restrict__ pos_b,
                                 float* __restrict__ y, int D) {
    size_t base = (size_t)blockIdx.x * D;
    float mu, rstd;
    ln_stats(x, base, D, mu, rstd);
    int tok = blockIdx.x & 127;
    float p0 = sph_pos[tok * 2], p1 = sph_pos[tok * 2 + 1];
    for (int i = threadIdx.x; i < D; i += 256) {
        float v = (x[base + i] - mu) * rstd * g[i] + beta[i];
        y[base + i] = v + p0 * pos_w[i] + p1 * pos_w[1024 + i] + pos_b[i];
    }
}

__global__ void ln_split_kernel(const float* __restrict__ x, const float* __restrict__ g,
                                const float* __restrict__ beta,
                                __half* __restrict__ H,
                                __half* __restrict__ L, int D) {
    size_t base = (size_t)blockIdx.x * D;
    float mu, rstd;
    ln_stats(x, base, D, mu, rstd);
    for (int i = threadIdx.x; i < D; i += 256) {
        float v = (x[base + i] - mu) * rstd * g[i] + beta[i];
        split2(v, H[base + i], L[base + i]);
    }
}

__global__ void reassemble_kernel(const float* __restrict__ Y, float* __restrict__ out) {
    int idx = blockIdx.x * 256 + threadIdx.x;
    int xq = idx & 511;
    int rest = idx >> 9;
    int yr = rest & 255;
    rest >>= 8;
    int c = rest % 3;
    int b = rest / 3;
    int h = yr >> 5, p1 = yr & 31, w = xq >> 5, p2 = xq & 31;
    out[idx] = Y[(size_t)(b * 128 + h * 16 + w) * PATCHDIM + (p1 * 32 + p2) * 3 + c];
}

// ---------------------------------------------------------------------------
// Host launcher
// ---------------------------------------------------------------------------
extern "C" void kernel_launch(void* const* d_in, const int* in_sizes, int n_in,
                              void* d_out, int out_size)
{
    const float* img      = (const float*)d_in[0];
    const float* sph_pos  = (const float*)d_in[1];
    const float* sph_dist = (const float*)d_in[2];
    const float* conv_w   = (const float*)d_in[3];
    const float* conv_b   = (const float*)d_in[4];
    const float* nl_ln1_g = (const float*)d_in[5];
    const float* nl_ln1_b = (const float*)d_in[6];
    const float* nl_w     = (const float*)d_in[7];
    const float* nl_b     = (const float*)d_in[8];
    const float* nl_ln2_g = (const float*)d_in[9];
    const float* nl_ln2_b = (const float*)d_in[10];
    const float* pos_w    = (const float*)d_in[11];
    const float* pos_b    = (const float*)d_in[12];
    const float* ln_g     = (const float*)d_in[13];
    const float* ln_b     = (const float*)d_in[14];
    const float* wqkv     = (const float*)d_in[15];
    const float* wo       = (const float*)d_in[16];
    const float* wo_b     = (const float*)d_in[17];
    const float* tr_ln_g  = (const float*)d_in[18];
    const float* tr_ln_b  = (const float*)d_in[19];
    const float* exp_w    = (const float*)d_in[20];
    const float* exp_b    = (const float*)d_in[21];
    const float* out_ln_g = (const float*)d_in[22];
    const float* out_ln_b = (const float*)d_in[23];

    float *big, *x, *w;
    cudaGetSymbolAddress((void**)&big, g_big);
    cudaGetSymbolAddress((void**)&x,   g_x);
    cudaGetSymbolAddress((void**)&w,   g_w);
    __half *Xph, *Xpl, *qkvh, *hh, *hl, *oh, *ol, *ph;
    __half *cwh, *nlwh, *qwh, *owh, *ewh;
    cudaGetSymbolAddress((void**)&Xph, g_Xph);   cudaGetSymbolAddress((void**)&Xpl, g_Xpl);
    cudaGetSymbolAddress((void**)&qkvh, g_qkvh);
    cudaGetSymbolAddress((void**)&hh,  g_hh);    cudaGetSymbolAddress((void**)&hl,  g_hl);
    cudaGetSymbolAddress((void**)&oh,  g_oh);    cudaGetSymbolAddress((void**)&ol,  g_ol);
    cudaGetSymbolAddress((void**)&ph,  g_ph);
    cudaGetSymbolAddress((void**)&cwh, g_cwh);
    cudaGetSymbolAddress((void**)&nlwh, g_nlwh);
    cudaGetSymbolAddress((void**)&qwh, g_qwh);
    cudaGetSymbolAddress((void**)&owh, g_owh);
    cudaGetSymbolAddress((void**)&ewh, g_ewh);

    cudaFuncSetAttribute(hmma_gemm_kernel<0>,
                         cudaFuncAttributeMaxDynamicSharedMemorySize, HG_SMEM);
    cudaFuncSetAttribute(hmma_gemm_kernel<2>,
                         cudaFuncAttributeMaxDynamicSharedMemorySize, HG_SMEM);
    cudaFuncSetAttribute(qk_mma_kernel,
                         cudaFuncAttributeMaxDynamicSharedMemorySize, QK_SMEM);
    cudaFuncSetAttribute(av_mma_kernel,
                         cudaFuncAttributeMaxDynamicSharedMemorySize, AV_SMEM);

    // ---- prep; conv GEMM is launch #6 (ncu -s 5 -c 1 lands here) ----
    split_kernel<<<DIMV * PATCHDIM / 256, 256>>>(conv_w, cwh);
    extract_patches_kernel<<<ROWS * PATCHDIM / 256, 256>>>(img, Xph, Xpl);
    wtrans_kernel<<<dim3(DIMV/32, DIMV/32, 1),     dim3(32,8)>>>(nl_w,  nlwh, DIMV, DIMV);
    wtrans_kernel<<<dim3(PATCHDIM/32, DIMV/32, DEPTH), dim3(32,8)>>>(wqkv, qwh, DIMV, PATCHDIM);
    wtrans_kernel<<<dim3(DIMV/32, DIMV/32, DEPTH), dim3(32,8)>>>(wo,    owh,  DIMV, DIMV);
    hmma_gemm_kernel<0><<<dim3(DIMV/128, ROWS/128), 256, HG_SMEM>>>(
        Xph, Xpl, cwh, conv_b, nullptr, x, nullptr, nullptr, ROWS, DIMV, PATCHDIM);
    wtrans_kernel<<<dim3(PATCHDIM/32, DIMV/32, 1), dim3(32,8)>>>(exp_w, ewh, DIMV, PATCHDIM);

    // ---- norm_linear + positional embedding (fused into second LN) ----
    ln_split_kernel<<<ROWS, 256>>>(x, nl_ln1_g, nl_ln1_b, hh, hl, DIMV);
    hmma_gemm_kernel<0><<<dim3(DIMV/128, ROWS/128), 256, HG_SMEM>>>(
        hh, hl, nlwh, nl_b, nullptr, x, nullptr, nullptr, ROWS, DIMV, DIMV);
    ln_addpos_kernel<<<ROWS, 256>>>(x, nl_ln2_g, nl_ln2_b, sph_pos, pos_w, pos_b,
                                    x, DIMV);

    // ---- transformer layers ----
    for (int l = 0; l < DEPTH; l++) {
        ln_split_kernel<<<ROWS, 256>>>(x, ln_g + l * DIMV, ln_b + l * DIMV, hh, hl, DIMV);
        hmma_gemm_kernel<2><<<dim3(PATCHDIM/128, ROWS/128), 256, HG_SMEM>>>(
            hh, hl, qwh + (size_t)l * PATCHDIM * DIMV,
            nullptr, nullptr, nullptr, qkvh, nullptr, ROWS, PATCHDIM, DIMV);
        qk_mma_kernel<<<BATCH * NHEADS, 256, QK_SMEM>>>(qkvh, sph_dist, w);
        std_softmax_kernel<<<BATCH * NTOK, 128>>>(w, ph);
        av_mma_kernel<<<BATCH * NHEADS, 256, AV_SMEM>>>(ph, qkvh, oh, ol);
        hmma_gemm_kernel<0><<<dim3(DIMV/128, ROWS/128), 256, HG_SMEM>>>(
            oh, ol, owh + (size_t)l * DIMV * DIMV,
            wo_b + l * DIMV, x, x, nullptr, nullptr, ROWS, DIMV, DIMV);
    }

    // ---- final LN + expand + output LN + reassembly ----
    ln_split_kernel<<<ROWS, 256>>>(x, tr_ln_g, tr_ln_b, hh, hl, DIMV);
    hmma_gemm_kernel<0><<<dim3(PATCHDIM/128, ROWS/128), 256, HG_SMEM>>>(
        hh, hl, ewh, exp_b, nullptr, big, nullptr, nullptr, ROWS, PATCHDIM, DIMV);
    ln_kernel<<<ROWS, 256>>>(big, out_ln_g, out_ln_b, big, PATCHDIM);
    reassemble_kernel<<<ROWS * PATCHDIM / 256, 256>>>(big, (float*)d_out);
}

// round 11
// speedup vs baseline: 3.2231x; 1.4832x over previous
#include <cuda_runtime.h>
#include <cuda_fp16.h>
#include <cstdint>

// ---------------------------------------------------------------------------
// SphereViT forward — pure-fp16 single-pass HMMA everywhere.
// R11: drop activation lo-planes; weight GEMMs 2-pass -> 1-pass.
// Error model: weight-round + act-round add in quadrature ~= 5.5e-4 (<1e-3).
// ---------------------------------------------------------------------------

#define BATCH     32
#define NTOK      128
#define ROWS      4096
#define DIMV      1024
#define PATCHDIM  3072
#define NHEADS    16
#define DHEAD     64
#define DEPTH     12
#define LN_EPS    1e-5f

// -------------------- scratch (device globals; no allocs) ------------------
__device__ float g_big[ROWS * PATCHDIM];                 // expand output
__device__ float g_x  [ROWS * DIMV];                     // residual stream fp32
__device__ float g_w  [BATCH * NHEADS * NTOK * NTOK];    // attention scores fp32

// fp16 activations (hi only)
__device__ __half g_Xph[ROWS * PATCHDIM];
__device__ __half g_qkvh[ROWS * PATCHDIM];
__device__ __half g_hh [ROWS * DIMV];
__device__ __half g_oh [ROWS * DIMV];
__device__ __half g_ph [BATCH*NHEADS*NTOK*NTOK];

// fp16 transposed weights ([N,K] K-major)
__device__ __half g_cwh[DIMV * PATCHDIM];
__device__ __half g_nlwh[DIMV * DIMV];
__device__ __half g_qwh[DEPTH * PATCHDIM * DIMV];
__device__ __half g_owh[DEPTH * DIMV * DIMV];
__device__ __half g_ewh[PATCHDIM * DIMV];

// ---------------------------------------------------------------------------
// PTX helpers
// ---------------------------------------------------------------------------
__device__ __forceinline__ uint32_t smem_u32(const void* p) {
    uint32_t a;
    asm("{ .reg .u64 t; cvta.to.shared.u64 t, %1; cvt.u32.u64 %0, t; }"
        : "=r"(a) : "l"(p));
    return a;
}
__device__ __forceinline__ void cpa16(uint32_t dst, const void* src) {
    asm volatile("cp.async.cg.shared.global [%0], [%1], 16;" :: "r"(dst), "l"(src));
}
__device__ __forceinline__ void cp_commit() { asm volatile("cp.async.commit_group;"); }
template <int NN>
__device__ __forceinline__ void cp_wait() {
    asm volatile("cp.async.wait_group %0;" :: "n"(NN));
}
__device__ __forceinline__ void ldsm4(uint32_t* r, uint32_t addr) {
    asm volatile("ldmatrix.sync.aligned.m8n8.x4.shared.b16 {%0,%1,%2,%3}, [%4];"
                 : "=r"(r[0]), "=r"(r[1]), "=r"(r[2]), "=r"(r[3]) : "r"(addr));
}
__device__ __forceinline__ void ldsm4t(uint32_t* r, uint32_t addr) {
    asm volatile("ldmatrix.sync.aligned.m8n8.x4.trans.shared.b16 {%0,%1,%2,%3}, [%4];"
                 : "=r"(r[0]), "=r"(r[1]), "=r"(r[2]), "=r"(r[3]) : "r"(addr));
}
__device__ __forceinline__ void mma16816(float* c, const uint32_t* a,
                                         const uint32_t* b) {
    asm volatile(
        "mma.sync.aligned.m16n8k16.row.col.f32.f16.f16.f32 "
        "{%0,%1,%2,%3}, {%4,%5,%6,%7}, {%8,%9}, {%0,%1,%2,%3};"
        : "+f"(c[0]), "+f"(c[1]), "+f"(c[2]), "+f"(c[3])
        : "r"(a[0]), "r"(a[1]), "r"(a[2]), "r"(a[3]), "r"(b[0]), "r"(b[1]));
}

// ---------------------------------------------------------------------------
// fp16 single-pass HMMA GEMM: C = Ah[M,K] @ Bh[N,K]^T (+bias)(+res)
// OM: 0 = fp32 C (+bias +res), 2 = fp16 Ch.
// ---------------------------------------------------------------------------
#define GPAD 8
#define GLDS (32 + GPAD)
#define OPND_ELEMS (128 * GLDS)          // 5120
#define STAGE_ELEMS (2 * OPND_ELEMS)     // 10240
#define HG_SMEM (2 * STAGE_ELEMS * 2)    // 40960 bytes

template <int OM>
__global__ __launch_bounds__(256, 2) void hmma_gemm_kernel(
    const __half* __restrict__ Ah, const __half* __restrict__ Bh,
    const float* __restrict__ bias, const float* __restrict__ res,
    float* __restrict__ C, __half* __restrict__ Ch, int M, int N, int K)
{
    extern __shared__ __half smem[];
    const uint32_t sbase = smem_u32(smem);
    const int tid  = threadIdx.x;
    const int lane = tid & 31, warp = tid >> 5;
    const int wm = warp & 1, wn = warp >> 1;
    const int m0 = blockIdx.y << 7, n0 = blockIdx.x << 7;

    const __half* g[2] = { Ah + (size_t)m0 * K, Bh + (size_t)n0 * K };

    const int r0c = tid >> 2;
    const int c0c = tid & 3;

    auto issue = [&](int stage, int k0) {
#pragma unroll
        for (int op = 0; op < 2; op++) {
            uint32_t sdst = sbase + (uint32_t)(stage * STAGE_ELEMS + op * OPND_ELEMS) * 2;
            const __half* gs = g[op];
#pragma unroll
            for (int half_ = 0; half_ < 2; half_++) {
                int r = r0c + half_ * 64;
                cpa16(sdst + (uint32_t)(r * GLDS + c0c * 8) * 2,
                      gs + (size_t)r * K + k0 + c0c * 8);
            }
        }
    };

    float acc[4][4][4];
#pragma unroll
    for (int i = 0; i < 4; i++)
#pragma unroll
        for (int j = 0; j < 4; j++)
#pragma unroll
            for (int q = 0; q < 4; q++) acc[i][j][q] = 0.f;

    const int nk = K >> 5;
    issue(0, 0);
    cp_commit();

    const int arow = wm * 64 + (lane & 15);
    const int acolb = (lane >> 4) * 8;
    const int brow = wn * 32 + ((lane >> 4) * 8) + (lane & 7);
    const int bcolb = ((lane >> 3) & 1) * 8;

    for (int it = 0; it < nk; ++it) {
        const int s = it & 1;
        if (it + 1 < nk) {
            issue(s ^ 1, (it + 1) << 5);
            cp_commit();
            cp_wait<1>();
        } else {
            cp_wait<0>();
        }
        __syncthreads();

        uint32_t sA = sbase + (uint32_t)(s * STAGE_ELEMS) * 2;
        uint32_t sB = sA + OPND_ELEMS * 2;

#pragma unroll
        for (int ks = 0; ks < 2; ks++) {
            const int acol = ks * 16 + acolb;
            const int bcol = ks * 16 + bcolb;
            uint32_t ah[4][4], bh[4][2];
#pragma unroll
            for (int mi = 0; mi < 4; mi++)
                ldsm4(ah[mi], sA + (uint32_t)((arow + mi * 16) * GLDS + acol) * 2);
#pragma unroll
            for (int gp = 0; gp < 2; gp++) {
                uint32_t rh[4];
                ldsm4(rh, sB + (uint32_t)((brow + gp * 16) * GLDS + bcol) * 2);
                bh[gp*2][0] = rh[0]; bh[gp*2][1] = rh[1];
                bh[gp*2+1][0] = rh[2]; bh[gp*2+1][1] = rh[3];
            }
#pragma unroll
            for (int mi = 0; mi < 4; mi++)
#pragma unroll
                for (int nj = 0; nj < 4; nj++)
                    mma16816(acc[mi][nj], ah[mi], bh[nj]);
        }
        __syncthreads();
    }

    // epilogue
#pragma unroll
    for (int mi = 0; mi < 4; mi++) {
        int r0 = m0 + wm * 64 + mi * 16 + (lane >> 2);
#pragma unroll
        for (int nj = 0; nj < 4; nj++) {
            int c = n0 + wn * 32 + nj * 8 + (lane & 3) * 2;
            float v0x = acc[mi][nj][0], v0y = acc[mi][nj][1];
            float v1x = acc[mi][nj][2], v1y = acc[mi][nj][3];
            size_t o0 = (size_t)r0 * N + c;
            size_t o1 = o0 + (size_t)8 * N;
            if (OM == 2) {
                *(__half2*)(Ch + o0) =
                    __halves2half2(__float2half_rn(v0x), __float2half_rn(v0y));
                *(__half2*)(Ch + o1) =
                    __halves2half2(__float2half_rn(v1x), __float2half_rn(v1y));
            } else {
                if (bias) {
                    float bx = bias[c], by = bias[c + 1];
                    v0x += bx; v0y += by; v1x += bx; v1y += by;
                }
                if (res) {
                    float2 ra = *(const float2*)(res + o0);
                    float2 rb = *(const float2*)(res + o1);
                    v0x += ra.x; v0y += ra.y; v1x += rb.x; v1y += rb.y;
                }
                *(float2*)(C + o0) = make_float2(v0x, v0y);
                *(float2*)(C + o1) = make_float2(v1x, v1y);
            }
        }
    }
}

// ---------------------------------------------------------------------------
// qk via HMMA (single pass): W = (qh_i . kh_j)*0.125*(1+dist). CTA per (b,h).
// ---------------------------------------------------------------------------
#define QKLD 72
#define QK_TILE (128 * QKLD)             // 9216 elems
#define QK_SMEM (2 * QK_TILE * 2)        // 36864 bytes

__global__ __launch_bounds__(256, 2) void qk_mma_kernel(
    const __half* __restrict__ qkvh,
    const float* __restrict__ dist, float* __restrict__ W)
{
    extern __shared__ __half smem[];
    const uint32_t sbase = smem_u32(smem);
    const int tid = threadIdx.x, lane = tid & 31, warp = tid >> 5;
    const int wm = warp & 1, wn = warp >> 1;
    const int b = blockIdx.x >> 4, h = blockIdx.x & 15;
    const size_t rowbase = (size_t)b * NTOK * PATCHDIM + h * DHEAD;

    const int offs[2] = { 0, DIMV };     // 0=Qh 1=Kh
#pragma unroll
    for (int t = 0; t < 2; t++) {
        uint32_t dbase = sbase + (uint32_t)(t * QK_TILE) * 2;
#pragma unroll
        for (int p = 0; p < 4; p++) {
            int q = tid + p * 256;       // 0..1023
            int r = q >> 3, c = q & 7;
            cpa16(dbase + (uint32_t)(r * QKLD + c * 8) * 2,
                  qkvh + rowbase + (size_t)r * PATCHDIM + offs[t] + c * 8);
        }
    }
    cp_commit();
    cp_wait<0>();
    __syncthreads();

    float acc[4][4][4];
#pragma unroll
    for (int i = 0; i < 4; i++)
#pragma unroll
        for (int j = 0; j < 4; j++)
#pragma unroll
            for (int q = 0; q < 4; q++) acc[i][j][q] = 0.f;

    uint32_t sA  = sbase;
    uint32_t sB  = sbase + (uint32_t)QK_TILE * 2;
    const int arow = wm * 64 + (lane & 15);
    const int acolb = (lane >> 4) * 8;
    const int brow = wn * 32 + ((lane >> 4) * 8) + (lane & 7);
    const int bcolb = ((lane >> 3) & 1) * 8;

#pragma unroll
    for (int ks = 0; ks < 4; ks++) {
        const int acol = ks * 16 + acolb;
        const int bcol = ks * 16 + bcolb;
        uint32_t ah[4][4], bh[4][2];
#pragma unroll
        for (int mi = 0; mi < 4; mi++)
            ldsm4(ah[mi], sA + (uint32_t)((arow + mi * 16) * QKLD + acol) * 2);
#pragma unroll
        for (int gp = 0; gp < 2; gp++) {
            uint32_t rh[4];
            ldsm4(rh, sB + (uint32_t)((brow + gp * 16) * QKLD + bcol) * 2);
            bh[gp*2][0] = rh[0]; bh[gp*2][1] = rh[1];
            bh[gp*2+1][0] = rh[2]; bh[gp*2+1][1] = rh[3];
        }
#pragma unroll
        for (int mi = 0; mi < 4; mi++)
#pragma unroll
            for (int nj = 0; nj < 4; nj++)
                mma16816(acc[mi][nj], ah[mi], bh[nj]);
    }

    float* Wb = W + (size_t)blockIdx.x * (NTOK * NTOK);
#pragma unroll
    for (int mi = 0; mi < 4; mi++) {
        int i0 = wm * 64 + mi * 16 + (lane >> 2);
#pragma unroll
        for (int nj = 0; nj < 4; nj++) {
            int j0 = wn * 32 + nj * 8 + (lane & 3) * 2;
#pragma unroll
            for (int rr = 0; rr < 2; rr++) {
                int i = i0 + rr * 8;
                float vx = acc[mi][nj][rr*2], vy = acc[mi][nj][rr*2+1];
                Wb[i * 128 + j0]     = vx * 0.125f * (1.0f + dist[i * 128 + j0]);
                Wb[i * 128 + j0 + 1] = vy * 0.125f * (1.0f + dist[i * 128 + j0 + 1]);
            }
        }
    }
}

// ---------------------------------------------------------------------------
// Cross-head standardize (ddof=1) + softmax; emits fp16 P.
// ---------------------------------------------------------------------------
__global__ __launch_bounds__(128) void std_softmax_kernel(
    const float* __restrict__ W, __half* __restrict__ Ph)
{
    int b = blockIdx.x >> 7, i = blockIdx.x & 127;
    int j = threadIdx.x;
    __shared__ float sm[NHEADS][128];

    size_t base = (size_t)b * (NHEADS * NTOK * NTOK) + (size_t)i * 128 + j;
    float vals[NHEADS];
    float s = 0.f;
#pragma unroll
    for (int h = 0; h < NHEADS; h++) {
        float v = W[base + (size_t)h * (NTOK * NTOK)];
        vals[h] = v; s += v;
    }
    float mu = s * (1.0f / 16.0f);
    float d2 = 0.f;
#pragma unroll
    for (int h = 0; h < NHEADS; h++) {
        float d = vals[h] - mu;
        d2 += d * d;
    }
    float inv = rsqrtf(d2 * (1.0f / 15.0f));
#pragma unroll
    for (int h = 0; h < NHEADS; h++) sm[h][j] = (vals[h] - mu) * inv;
    __syncthreads();

    int warp = j >> 5, lane = j & 31;
#pragma unroll
    for (int r = 0; r < 4; r++) {
        int h = warp * 4 + r;
        float v0 = sm[h][lane], v1 = sm[h][lane + 32];
        float v2 = sm[h][lane + 64], v3 = sm[h][lane + 96];
        float m = fmaxf(fmaxf(v0, v1), fmaxf(v2, v3));
#pragma unroll
        for (int o = 16; o; o >>= 1) m = fmaxf(m, __shfl_xor_sync(0xffffffffu, m, o));
        float e0 = expf(v0 - m), e1 = expf(v1 - m);
        float e2 = expf(v2 - m), e3 = expf(v3 - m);
        float sum = e0 + e1 + e2 + e3;
#pragma unroll
        for (int o = 16; o; o >>= 1) sum += __shfl_xor_sync(0xffffffffu, sum, o);
        float rs = 1.0f / sum;
        size_t wb = (size_t)b * (NHEADS * NTOK * NTOK) + (size_t)h * (NTOK * NTOK)
                  + (size_t)i * 128;
        Ph[wb + lane]      = __float2half_rn(e0 * rs);
        Ph[wb + lane + 32] = __float2half_rn(e1 * rs);
        Ph[wb + lane + 64] = __float2half_rn(e2 * rs);
        Ph[wb + lane + 96] = __float2half_rn(e3 * rs);
    }
}

// ---------------------------------------------------------------------------
// av via HMMA (single pass): O[i,h*64+d] = sum_j Ph[i,j]*Vh[j,d]. CTA per (b,h).
// ---------------------------------------------------------------------------
#define AVPLD 136
#define AVVLD 72
#define AVP_TILE (128 * AVPLD)           // 17408 elems
#define AVV_TILE (128 * AVVLD)           // 9216 elems
#define AV_SMEM ((AVP_TILE + AVV_TILE) * 2)   // 53248 bytes

__global__ __launch_bounds__(256, 2) void av_mma_kernel(
    const __half* __restrict__ Ph, const __half* __restrict__ qkvh,
    __half* __restrict__ Oh)
{
    extern __shared__ __half smem[];
    const uint32_t sbase = smem_u32(smem);
    const int tid = threadIdx.x, lane = tid & 31, warp = tid >> 5;
    const int wm = warp & 3, wn = warp >> 2;
    const int b = blockIdx.x >> 4, h = blockIdx.x & 15;
    const size_t pbase = (size_t)blockIdx.x * (NTOK * NTOK);
    const size_t vbase = (size_t)b * NTOK * PATCHDIM + 2 * DIMV + h * DHEAD;

    // load P via cp.async, [i][128] -> [i][AVPLD]
#pragma unroll
    for (int p = 0; p < 8; p++) {
        int q = tid + p * 256;           // 0..2047
        int r = q >> 4, c = q & 15;
        cpa16(sbase + (uint32_t)(r * AVPLD + c * 8) * 2,
              Ph + pbase + (size_t)r * 128 + c * 8);
    }
    // load V via cp.async, [j][64] -> [j][AVVLD]
    {
        uint32_t dbase = sbase + (uint32_t)AVP_TILE * 2;
#pragma unroll
        for (int p = 0; p < 4; p++) {
            int q = tid + p * 256;       // 0..1023
            int j = q >> 3, c = q & 7;
            cpa16(dbase + (uint32_t)(j * AVVLD + c * 8) * 2,
                  qkvh + vbase + (size_t)j * PATCHDIM + c * 8);
        }
    }
    cp_commit();
    cp_wait<0>();
    __syncthreads();

    float acc[2][4][4];
#pragma unroll
    for (int i = 0; i < 2; i++)
#pragma unroll
        for (int j = 0; j < 4; j++)
#pragma unroll
            for (int q = 0; q < 4; q++) acc[i][j][q] = 0.f;

    uint32_t sA  = sbase;
    uint32_t sB  = sbase + (uint32_t)AVP_TILE * 2;
    const int arow = wm * 32 + (lane & 15);
    const int acolb = (lane >> 4) * 8;
    const int bjrow = lane & 15;
    const int bdcol = (lane >> 4) * 8;

#pragma unroll
    for (int kc = 0; kc < 8; kc++) {
        const int acol = kc * 16 + acolb;
        uint32_t ah[2][4], bh[4][2];
#pragma unroll
        for (int mi = 0; mi < 2; mi++)
            ldsm4(ah[mi], sA + (uint32_t)((arow + mi * 16) * AVPLD + acol) * 2);
#pragma unroll
        for (int gp = 0; gp < 2; gp++) {
            uint32_t rh[4];
            uint32_t off = (uint32_t)((kc * 16 + bjrow) * AVVLD
                                      + wn * 32 + gp * 16 + bdcol) * 2;
            ldsm4t(rh, sB + off);
            bh[gp*2][0] = rh[0]; bh[gp*2][1] = rh[1];
            bh[gp*2+1][0] = rh[2]; bh[gp*2+1][1] = rh[3];
        }
#pragma unroll
        for (int mi = 0; mi < 2; mi++)
#pragma unroll
            for (int nj = 0; nj < 4; nj++)
                mma16816(acc[mi][nj], ah[mi], bh[nj]);
    }

#pragma unroll
    for (int mi = 0; mi < 2; mi++) {
        int i0 = wm * 32 + mi * 16 + (lane >> 2);
#pragma unroll
        for (int nj = 0; nj < 4; nj++) {
            int d0 = wn * 32 + nj * 8 + (lane & 3) * 2;
#pragma unroll
            for (int rr = 0; rr < 2; rr++) {
                int i = i0 + rr * 8;
                size_t o = (size_t)(b * 128 + i) * DIMV + h * DHEAD + d0;
                *(__half2*)(Oh + o) =
                    __halves2half2(__float2half_rn(acc[mi][nj][rr*2]),
                                   __float2half_rn(acc[mi][nj][rr*2 + 1]));
            }
        }
    }
}

// ---------------------------------------------------------------------------
// Weight prep (fp16)
// ---------------------------------------------------------------------------
__global__ void split_kernel(const float* __restrict__ X, __half* __restrict__ H) {
    size_t i = (size_t)blockIdx.x * 256 + threadIdx.x;
    H[i] = __float2half_rn(X[i]);
}

__global__ void wtrans_kernel(const float* __restrict__ W,
                              __half* __restrict__ Th, int K, int N) {
    __shared__ float t[32][33];
    const float* Wl = W + (size_t)blockIdx.z * K * N;
    size_t ob = (size_t)blockIdx.z * K * N;
    int x = blockIdx.x * 32 + threadIdx.x;
    int y = blockIdx.y * 32 + threadIdx.y;
#pragma unroll
    for (int j = 0; j < 32; j += 8)
        t[threadIdx.y + j][threadIdx.x] = Wl[(size_t)(y + j) * N + x];
    __syncthreads();
    int n = blockIdx.x * 32 + threadIdx.y;
    int k = blockIdx.y * 32 + threadIdx.x;
#pragma unroll
    for (int j = 0; j < 32; j += 8) {
        size_t o = ob + (size_t)(n + j) * K + k;
        Th[o] = __float2half_rn(t[threadIdx.x][threadIdx.y + j]);
    }
}

__global__ void extract_patches_kernel(const float* __restrict__ img,
                                       __half* __restrict__ H) {
    int idx = blockIdx.x * 256 + threadIdx.x;
    int col = idx % PATCHDIM;
    int row = idx / PATCHDIM;
    int b = row >> 7, t = row & 127;
    int h = t >> 4, w = t & 15;
    int c = col >> 10, r = col & 1023;
    int p = r >> 5, q = r & 31;
    float v = img[(((size_t)b * 3 + c) * 256 + h * 32 + p) * 512 + w * 32 + q];
    H[idx] = __float2half_rn(v);
}

// ---------------------------------------------------------------------------
// LayerNorm
// ---------------------------------------------------------------------------
__device__ __forceinline__ void ln_stats(const float* __restrict__ x, size_t base,
                                         int D, float& mu, float& rstd) {
    float s = 0.f, ss = 0.f;
    for (int i = threadIdx.x; i < D; i += 256) {
        float v = x[base + i];
        s += v; ss += v * v;
    }
#pragma unroll
    for (int o = 16; o; o >>= 1) {
        s  += __shfl_xor_sync(0xffffffffu, s, o);
        ss += __shfl_xor_sync(0xffffffffu, ss, o);
    }
    __shared__ float sh[2][8];
    int w = threadIdx.x >> 5;
    if ((threadIdx.x & 31) == 0) { sh[0][w] = s; sh[1][w] = ss; }
    __syncthreads();
    if (threadIdx.x < 32) {
        s  = (threadIdx.x < 8) ? sh[0][threadIdx.x] : 0.f;
        ss = (threadIdx.x < 8) ? sh[1][threadIdx.x] : 0.f;
#pragma unroll
        for (int o = 4; o; o >>= 1) {
            s  += __shfl_xor_sync(0xffffffffu, s, o);
            ss += __shfl_xor_sync(0xffffffffu, ss, o);
        }
        if (threadIdx.x == 0) { sh[0][0] = s; sh[1][0] = ss; }
    }
    __syncthreads();
    s = sh[0][0]; ss = sh[1][0];
    float invD = 1.0f / (float)D;
    mu = s * invD;
    float var = ss * invD - mu * mu;
    rstd = rsqrtf(var + LN_EPS);
}

__global__ void ln_kernel(const float* __restrict__ x, const float* __restrict__ g,
                          const float* __restrict__ beta, float* __restrict__ y, int D) {
    size_t base = (size_t)blockIdx.x * D;
    float mu, rstd;
    ln_stats(x, base, D, mu, rstd);
    for (int i = threadIdx.x; i < D; i += 256)
        y[base + i] = (x[base + i] - mu) * rstd * g[i] + beta[i];
}

// LN then add positional embedding.
__global__ void ln_addpos_kernel(const float* __restrict__ x, const float* __restrict__ g,
                                 const float* __restrict__ beta,
                                 const float* __restrict__ sph_pos,
                                 const float* __restrict__ pos_w,
                                 const float* __restrict__ pos_b,
                                 float* __restrict__ y, int D) {
    size_t base = (size_t)blockIdx.x * D;
    float mu, rstd;
    ln_stats(x, base, D, mu, rstd);
    int tok = blockIdx.x & 127;
    float p0 = sph_pos[tok * 2], p1 = sph_pos[tok * 2 + 1];
    for (int i = threadIdx.x; i < D; i += 256) {
        float v = (x[base + i] - mu) * rstd * g[i] + beta[i];
        y[base + i] = v + p0 * pos_w[i] + p1 * pos_w[1024 + i] + pos_b[i];
    }
}

// LN emitting fp16.
__global__ void ln_half_kernel(const float* __restrict__ x, const float* __restrict__ g,
                               const float* __restrict__ beta,
                               __half* __restrict__ H, int D) {
    size_t base = (size_t)blockIdx.x * D;
    float mu, rstd;
    ln_stats(x, base, D, mu, rstd);
    for (int i = threadIdx.x; i < D; i += 256) {
        float v = (x[base + i] - mu) * rstd * g[i] + beta[i];
        H[base + i] = __float2half_rn(v);
    }
}

__global__ void reassemble_kernel(const float* __restrict__ Y, float* __restrict__ out) {
    int idx = blockIdx.x * 256 + threadIdx.x;
    int xq = idx & 511;
    int rest = idx >> 9;
    int yr = rest & 255;
    rest >>= 8;
    int c = rest % 3;
    int b = rest / 3;
    int h = yr >> 5, p1 = yr & 31, w = xq >> 5, p2 = xq & 31;
    out[idx] = Y[(size_t)(b * 128 + h * 16 + w) * PATCHDIM + (p1 * 32 + p2) * 3 + c];
}

// ---------------------------------------------------------------------------
// Host launcher
// ---------------------------------------------------------------------------
extern "C" void kernel_launch(void* const* d_in, const int* in_sizes, int n_in,
                              void* d_out, int out_size)
{
    const float* img      = (const float*)d_in[0];
    const float* sph_pos  = (const float*)d_in[1];
    const float* sph_dist = (const float*)d_in[2];
    const float* conv_w   = (const float*)d_in[3];
    const float* conv_b   = (const float*)d_in[4];
    const float* nl_ln1_g = (const float*)d_in[5];
    const float* nl_ln1_b = (const float*)d_in[6];
    const float* nl_w     = (const float*)d_in[7];
    const float* nl_b     = (const float*)d_in[8];
    const float* nl_ln2_g = (const float*)d_in[9];
    const float* nl_ln2_b = (const float*)d_in[10];
    const float* pos_w    = (const float*)d_in[11];
    const float* pos_b    = (const float*)d_in[12];
    const float* ln_g     = (const float*)d_in[13];
    const float* ln_b     = (const float*)d_in[14];
    const float* wqkv     = (const float*)d_in[15];
    const float* wo       = (const float*)d_in[16];
    const float* wo_b     = (const float*)d_in[17];
    const float* tr_ln_g  = (const float*)d_in[18];
    const float* tr_ln_b  = (const float*)d_in[19];
    const float* exp_w    = (const float*)d_in[20];
    const float* exp_b    = (const float*)d_in[21];
    const float* out_ln_g = (const float*)d_in[22];
    const float* out_ln_b = (const float*)d_in[23];

    float *big, *x, *w;
    cudaGetSymbolAddress((void**)&big, g_big);
    cudaGetSymbolAddress((void**)&x,   g_x);
    cudaGetSymbolAddress((void**)&w,   g_w);
    __half *Xph, *qkvh, *hh, *oh, *ph;
    __half *cwh, *nlwh, *qwh, *owh, *ewh;
    cudaGetSymbolAddress((void**)&Xph, g_Xph);
    cudaGetSymbolAddress((void**)&qkvh, g_qkvh);
    cudaGetSymbolAddress((void**)&hh,  g_hh);
    cudaGetSymbolAddress((void**)&oh,  g_oh);
    cudaGetSymbolAddress((void**)&ph,  g_ph);
    cudaGetSymbolAddress((void**)&cwh, g_cwh);
    cudaGetSymbolAddress((void**)&nlwh, g_nlwh);
    cudaGetSymbolAddress((void**)&qwh, g_qwh);
    cudaGetSymbolAddress((void**)&owh, g_owh);
    cudaGetSymbolAddress((void**)&ewh, g_ewh);

    cudaFuncSetAttribute(hmma_gemm_kernel<0>,
                         cudaFuncAttributeMaxDynamicSharedMemorySize, HG_SMEM);
    cudaFuncSetAttribute(hmma_gemm_kernel<2>,
                         cudaFuncAttributeMaxDynamicSharedMemorySize, HG_SMEM);
    cudaFuncSetAttribute(qk_mma_kernel,
                         cudaFuncAttributeMaxDynamicSharedMemorySize, QK_SMEM);
    cudaFuncSetAttribute(av_mma_kernel,
                         cudaFuncAttributeMaxDynamicSharedMemorySize, AV_SMEM);

    // ---- prep; conv GEMM is launch #6 (ncu -s 5 -c 1 lands here) ----
    split_kernel<<<DIMV * PATCHDIM / 256, 256>>>(conv_w, cwh);
    extract_patches_kernel<<<ROWS * PATCHDIM / 256, 256>>>(img, Xph);
    wtrans_kernel<<<dim3(DIMV/32, DIMV/32, 1),     dim3(32,8)>>>(nl_w,  nlwh, DIMV, DIMV);
    wtrans_kernel<<<dim3(PATCHDIM/32, DIMV/32, DEPTH), dim3(32,8)>>>(wqkv, qwh, DIMV, PATCHDIM);
    wtrans_kernel<<<dim3(DIMV/32, DIMV/32, DEPTH), dim3(32,8)>>>(wo,    owh,  DIMV, DIMV);
    hmma_gemm_kernel<0><<<dim3(DIMV/128, ROWS/128), 256, HG_SMEM>>>(
        Xph, cwh, conv_b, nullptr, x, nullptr, ROWS, DIMV, PATCHDIM);
    wtrans_kernel<<<dim3(PATCHDIM/32, DIMV/32, 1), dim3(32,8)>>>(exp_w, ewh, DIMV, PATCHDIM);

    // ---- norm_linear + positional embedding ----
    ln_half_kernel<<<ROWS, 256>>>(x, nl_ln1_g, nl_ln1_b, hh, DIMV);
    hmma_gemm_kernel<0><<<dim3(DIMV/128, ROWS/128), 256, HG_SMEM>>>(
        hh, nlwh, nl_b, nullptr, x, nullptr, ROWS, DIMV, DIMV);
    ln_addpos_kernel<<<ROWS, 256>>>(x, nl_ln2_g, nl_ln2_b, sph_pos, pos_w, pos_b,
                                    x, DIMV);

    // ---- transformer layers ----
    for (int l = 0; l < DEPTH; l++) {
        ln_half_kernel<<<ROWS, 256>>>(x, ln_g + l * DIMV, ln_b + l * DIMV, hh, DIMV);
        hmma_gemm_kernel<2><<<dim3(PATCHDIM/128, ROWS/128), 256, HG_SMEM>>>(
            hh, qwh + (size_t)l * PATCHDIM * DIMV,
            nullptr, nullptr, nullptr, qkvh, ROWS, PATCHDIM, DIMV);
        qk_mma_kernel<<<BATCH * NHEADS, 256, QK_SMEM>>>(qkvh, sph_dist, w);
        std_softmax_kernel<<<BATCH * NTOK, 128>>>(w, ph);
        av_mma_kernel<<<BATCH * NHEADS, 256, AV_SMEM>>>(ph, qkvh, oh);
        hmma_gemm_kernel<0><<<dim3(DIMV/128, ROWS/128), 256, HG_SMEM>>>(
            oh, owh + (size_t)l * DIMV * DIMV,
            wo_b + l * DIMV, x, x, nullptr, ROWS, DIMV, DIMV);
    }

    // ---- final LN + expand + output LN + reassembly ----
    ln_half_kernel<<<ROWS, 256>>>(x, tr_ln_g, tr_ln_b, hh, DIMV);
    hmma_gemm_kernel<0><<<dim3(PATCHDIM/128, ROWS/128), 256, HG_SMEM>>>(
        hh, ewh, exp_b, nullptr, big, nullptr, ROWS, PATCHDIM, DIMV);
    ln_kernel<<<ROWS, 256>>>(big, out_ln_g, out_ln_b, big, PATCHDIM);
    reassemble_kernel<<<ROWS * PATCHDIM / 256, 256>>>(big, (float*)d_out);
}

// round 12
// speedup vs baseline: 3.3433x; 1.0373x over previous
#include <cuda_runtime.h>
#include <cuda_fp16.h>
#include <cstdint>

// ---------------------------------------------------------------------------
// SphereViT forward — pure-fp16 single-pass HMMA.
// R12: 128x256-tile 3-stage GEMM for N=3072 (qkv, expand); 128x128 otherwise.
// ---------------------------------------------------------------------------

#define BATCH     32
#define NTOK      128
#define ROWS      4096
#define DIMV      1024
#define PATCHDIM  3072
#define NHEADS    16
#define DHEAD     64
#define DEPTH     12
#define LN_EPS    1e-5f

// -------------------- scratch (device globals; no allocs) ------------------
__device__ float g_big[ROWS * PATCHDIM];
__device__ float g_x  [ROWS * DIMV];
__device__ float g_w  [BATCH * NHEADS * NTOK * NTOK];

__device__ __half g_Xph[ROWS * PATCHDIM];
__device__ __half g_qkvh[ROWS * PATCHDIM];
__device__ __half g_hh [ROWS * DIMV];
__device__ __half g_oh [ROWS * DIMV];
__device__ __half g_ph [BATCH*NHEADS*NTOK*NTOK];

__device__ __half g_cwh[DIMV * PATCHDIM];
__device__ __half g_nlwh[DIMV * DIMV];
__device__ __half g_qwh[DEPTH * PATCHDIM * DIMV];
__device__ __half g_owh[DEPTH * DIMV * DIMV];
__device__ __half g_ewh[PATCHDIM * DIMV];

// ---------------------------------------------------------------------------
// PTX helpers
// ---------------------------------------------------------------------------
__device__ __forceinline__ uint32_t smem_u32(const void* p) {
    uint32_t a;
    asm("{ .reg .u64 t; cvta.to.shared.u64 t, %1; cvt.u32.u64 %0, t; }"
        : "=r"(a) : "l"(p));
    return a;
}
__device__ __forceinline__ void cpa16(uint32_t dst, const void* src) {
    asm volatile("cp.async.cg.shared.global [%0], [%1], 16;" :: "r"(dst), "l"(src));
}
__device__ __forceinline__ void cp_commit() { asm volatile("cp.async.commit_group;"); }
template <int NN>
__device__ __forceinline__ void cp_wait() {
    asm volatile("cp.async.wait_group %0;" :: "n"(NN));
}
__device__ __forceinline__ void ldsm4(uint32_t* r, uint32_t addr) {
    asm volatile("ldmatrix.sync.aligned.m8n8.x4.shared.b16 {%0,%1,%2,%3}, [%4];"
                 : "=r"(r[0]), "=r"(r[1]), "=r"(r[2]), "=r"(r[3]) : "r"(addr));
}
__device__ __forceinline__ void ldsm4t(uint32_t* r, uint32_t addr) {
    asm volatile("ldmatrix.sync.aligned.m8n8.x4.trans.shared.b16 {%0,%1,%2,%3}, [%4];"
                 : "=r"(r[0]), "=r"(r[1]), "=r"(r[2]), "=r"(r[3]) : "r"(addr));
}
__device__ __forceinline__ void mma16816(float* c, const uint32_t* a,
                                         const uint32_t* b) {
    asm volatile(
        "mma.sync.aligned.m16n8k16.row.col.f32.f16.f16.f32 "
        "{%0,%1,%2,%3}, {%4,%5,%6,%7}, {%8,%9}, {%0,%1,%2,%3};"
        : "+f"(c[0]), "+f"(c[1]), "+f"(c[2]), "+f"(c[3])
        : "r"(a[0]), "r"(a[1]), "r"(a[2]), "r"(a[3]), "r"(b[0]), "r"(b[1]));
}

#define GPAD 8
#define GLDS (32 + GPAD)

// ---------------------------------------------------------------------------
// 128x128 GEMM (2 CTAs/SM, 2-stage) — used for N=1024 GEMMs.
// ---------------------------------------------------------------------------
#define OPND_ELEMS (128 * GLDS)          // 5120
#define STAGE_ELEMS (2 * OPND_ELEMS)     // 10240
#define HG_SMEM (2 * STAGE_ELEMS * 2)    // 40960 bytes

template <int OM>     // 0 = fp32 +bias +res, 2 = fp16 out
__global__ __launch_bounds__(256, 2) void hmma_gemm_kernel(
    const __half* __restrict__ Ah, const __half* __restrict__ Bh,
    const float* __restrict__ bias, const float* __restrict__ res,
    float* __restrict__ C, __half* __restrict__ Ch, int M, int N, int K)
{
    extern __shared__ __half smem[];
    const uint32_t sbase = smem_u32(smem);
    const int tid  = threadIdx.x;
    const int lane = tid & 31, warp = tid >> 5;
    const int wm = warp & 1, wn = warp >> 1;
    const int m0 = blockIdx.y << 7, n0 = blockIdx.x << 7;

    const __half* g[2] = { Ah + (size_t)m0 * K, Bh + (size_t)n0 * K };

    const int r0c = tid >> 2;
    const int c0c = tid & 3;

    auto issue = [&](int stage, int k0) {
#pragma unroll
        for (int op = 0; op < 2; op++) {
            uint32_t sdst = sbase + (uint32_t)(stage * STAGE_ELEMS + op * OPND_ELEMS) * 2;
            const __half* gs = g[op];
#pragma unroll
            for (int half_ = 0; half_ < 2; half_++) {
                int r = r0c + half_ * 64;
                cpa16(sdst + (uint32_t)(r * GLDS + c0c * 8) * 2,
                      gs + (size_t)r * K + k0 + c0c * 8);
            }
        }
    };

    float acc[4][4][4];
#pragma unroll
    for (int i = 0; i < 4; i++)
#pragma unroll
        for (int j = 0; j < 4; j++)
#pragma unroll
            for (int q = 0; q < 4; q++) acc[i][j][q] = 0.f;

    const int nk = K >> 5;
    issue(0, 0);
    cp_commit();

    const int arow = wm * 64 + (lane & 15);
    const int acolb = (lane >> 4) * 8;
    const int brow = wn * 32 + ((lane >> 4) * 8) + (lane & 7);
    const int bcolb = ((lane >> 3) & 1) * 8;

    for (int it = 0; it < nk; ++it) {
        const int s = it & 1;
        if (it + 1 < nk) {
            issue(s ^ 1, (it + 1) << 5);
            cp_commit();
            cp_wait<1>();
        } else {
            cp_wait<0>();
        }
        __syncthreads();

        uint32_t sA = sbase + (uint32_t)(s * STAGE_ELEMS) * 2;
        uint32_t sB = sA + OPND_ELEMS * 2;

#pragma unroll
        for (int ks = 0; ks < 2; ks++) {
            const int acol = ks * 16 + acolb;
            const int bcol = ks * 16 + bcolb;
            uint32_t ah[4][4], bh[4][2];
#pragma unroll
            for (int mi = 0; mi < 4; mi++)
                ldsm4(ah[mi], sA + (uint32_t)((arow + mi * 16) * GLDS + acol) * 2);
#pragma unroll
            for (int gp = 0; gp < 2; gp++) {
                uint32_t rh[4];
                ldsm4(rh, sB + (uint32_t)((brow + gp * 16) * GLDS + bcol) * 2);
                bh[gp*2][0] = rh[0]; bh[gp*2][1] = rh[1];
                bh[gp*2+1][0] = rh[2]; bh[gp*2+1][1] = rh[3];
            }
#pragma unroll
            for (int mi = 0; mi < 4; mi++)
#pragma unroll
                for (int nj = 0; nj < 4; nj++)
                    mma16816(acc[mi][nj], ah[mi], bh[nj]);
        }
        __syncthreads();
    }

#pragma unroll
    for (int mi = 0; mi < 4; mi++) {
        int r0 = m0 + wm * 64 + mi * 16 + (lane >> 2);
#pragma unroll
        for (int nj = 0; nj < 4; nj++) {
            int c = n0 + wn * 32 + nj * 8 + (lane & 3) * 2;
            float v0x = acc[mi][nj][0], v0y = acc[mi][nj][1];
            float v1x = acc[mi][nj][2], v1y = acc[mi][nj][3];
            size_t o0 = (size_t)r0 * N + c;
            size_t o1 = o0 + (size_t)8 * N;
            if (OM == 2) {
                *(__half2*)(Ch + o0) =
                    __halves2half2(__float2half_rn(v0x), __float2half_rn(v0y));
                *(__half2*)(Ch + o1) =
                    __halves2half2(__float2half_rn(v1x), __float2half_rn(v1y));
            } else {
                if (bias) {
                    float bx = bias[c], by = bias[c + 1];
                    v0x += bx; v0y += by; v1x += bx; v1y += by;
                }
                if (res) {
                    float2 ra = *(const float2*)(res + o0);
                    float2 rb = *(const float2*)(res + o1);
                    v0x += ra.x; v0y += ra.y; v1x += rb.x; v1y += rb.y;
                }
                *(float2*)(C + o0) = make_float2(v0x, v0y);
                *(float2*)(C + o1) = make_float2(v1x, v1y);
            }
        }
    }
}

// ---------------------------------------------------------------------------
// 128x256 GEMM (1 CTA/SM, 3-stage) — used for N=3072 GEMMs (qkv, expand).
// Warp tile 64x64 (2x4 warp grid). Higher intensity: 68 flops/smem-byte.
// ---------------------------------------------------------------------------
#define OPB_ELEMS (256 * GLDS)            // 10240
#define STG2_ELEMS (OPND_ELEMS + OPB_ELEMS)  // 15360
#define HG2_SMEM (3 * STG2_ELEMS * 2)     // 92160 bytes

template <int OM>
__global__ __launch_bounds__(256, 1) void hmma_gemm256_kernel(
    const __half* __restrict__ Ah, const __half* __restrict__ Bh,
    const float* __restrict__ bias, const float* __restrict__ res,
    float* __restrict__ C, __half* __restrict__ Ch, int M, int N, int K)
{
    extern __shared__ __half smem[];
    const uint32_t sbase = smem_u32(smem);
    const int tid  = threadIdx.x;
    const int lane = tid & 31, warp = tid >> 5;
    const int wm = warp & 1, wn = warp >> 1;           // wn 0..3
    const int m0 = blockIdx.y << 7, n0 = blockIdx.x << 8;

    const __half* gA = Ah + (size_t)m0 * K;
    const __half* gB = Bh + (size_t)n0 * K;

    const int ra = tid >> 2, ca = tid & 3;             // A: 2 chunks/thread
    const int rb = tid >> 2, cb = tid & 3;             // B: 4 chunks/thread (4 passes of row-groups)

    auto issue = [&](int stage, int k0) {
        uint32_t sA = sbase + (uint32_t)(stage * STG2_ELEMS) * 2;
        uint32_t sB = sA + OPND_ELEMS * 2;
#pragma unroll
        for (int half_ = 0; half_ < 2; half_++) {
            int r = ra + half_ * 64;
            cpa16(sA + (uint32_t)(r * GLDS + ca * 8) * 2,
                  gA + (size_t)r * K + k0 + ca * 8);
        }
#pragma unroll
        for (int p = 0; p < 4; p++) {
            int r = rb + p * 64;
            cpa16(sB + (uint32_t)(r * GLDS + cb * 8) * 2,
                  gB + (size_t)r * K + k0 + cb * 8);
        }
    };

    float acc[4][8][4];
#pragma unroll
    for (int i = 0; i < 4; i++)
#pragma unroll
        for (int j = 0; j < 8; j++)
#pragma unroll
            for (int q = 0; q < 4; q++) acc[i][j][q] = 0.f;

    const int nk = K >> 5;
    issue(0, 0);  cp_commit();
    if (nk > 1) { issue(1, 32); cp_commit(); }

    const int arow = wm * 64 + (lane & 15);
    const int acolb = (lane >> 4) * 8;
    const int brow = wn * 64 + ((lane >> 4) * 8) + (lane & 7);
    const int bcolb = ((lane >> 3) & 1) * 8;

    for (int it = 0; it < nk; ++it) {
        if (it == nk - 1) cp_wait<0>(); else cp_wait<1>();
        __syncthreads();

        const int s = it % 3;
        uint32_t sA = sbase + (uint32_t)(s * STG2_ELEMS) * 2;
        uint32_t sB = sA + OPND_ELEMS * 2;

#pragma unroll
        for (int ks = 0; ks < 2; ks++) {
            const int acol = ks * 16 + acolb;
            const int bcol = ks * 16 + bcolb;
            uint32_t ah[4][4], bh[8][2];
#pragma unroll
            for (int mi = 0; mi < 4; mi++)
                ldsm4(ah[mi], sA + (uint32_t)((arow + mi * 16) * GLDS + acol) * 2);
#pragma unroll
            for (int gp = 0; gp < 4; gp++) {
                uint32_t rh[4];
                ldsm4(rh, sB + (uint32_t)((brow + gp * 16) * GLDS + bcol) * 2);
                bh[gp*2][0] = rh[0]; bh[gp*2][1] = rh[1];
                bh[gp*2+1][0] = rh[2]; bh[gp*2+1][1] = rh[3];
            }
#pragma unroll
            for (int mi = 0; mi < 4; mi++)
#pragma unroll
                for (int nj = 0; nj < 8; nj++)
                    mma16816(acc[mi][nj], ah[mi], bh[nj]);
        }

        if (it + 2 < nk) { issue((it + 2) % 3, (it + 2) << 5); cp_commit(); }
    }

#pragma unroll
    for (int mi = 0; mi < 4; mi++) {
        int r0 = m0 + wm * 64 + mi * 16 + (lane >> 2);
#pragma unroll
        for (int nj = 0; nj < 8; nj++) {
            int c = n0 + wn * 64 + nj * 8 + (lane & 3) * 2;
            float v0x = acc[mi][nj][0], v0y = acc[mi][nj][1];
            float v1x = acc[mi][nj][2], v1y = acc[mi][nj][3];
            size_t o0 = (size_t)r0 * N + c;
            size_t o1 = o0 + (size_t)8 * N;
            if (OM == 2) {
                *(__half2*)(Ch + o0) =
                    __halves2half2(__float2half_rn(v0x), __float2half_rn(v0y));
                *(__half2*)(Ch + o1) =
                    __halves2half2(__float2half_rn(v1x), __float2half_rn(v1y));
            } else {
                if (bias) {
                    float bx = bias[c], by = bias[c + 1];
                    v0x += bx; v0y += by; v1x += bx; v1y += by;
                }
                if (res) {
                    float2 ra = *(const float2*)(res + o0);
                    float2 rb = *(const float2*)(res + o1);
                    v0x += ra.x; v0y += ra.y; v1x += rb.x; v1y += rb.y;
                }
                *(float2*)(C + o0) = make_float2(v0x, v0y);
                *(float2*)(C + o1) = make_float2(v1x, v1y);
            }
        }
    }
}

// ---------------------------------------------------------------------------
// qk via HMMA: W = (qh_i . kh_j)*0.125*(1+dist). CTA per (b,h).
// ---------------------------------------------------------------------------
#define QKLD 72
#define QK_TILE (128 * QKLD)
#define QK_SMEM (2 * QK_TILE * 2)

__global__ __launch_bounds__(256, 2) void qk_mma_kernel(
    const __half* __restrict__ qkvh,
    const float* __restrict__ dist, float* __restrict__ W)
{
    extern __shared__ __half smem[];
    const uint32_t sbase = smem_u32(smem);
    const int tid = threadIdx.x, lane = tid & 31, warp = tid >> 5;
    const int wm = warp & 1, wn = warp >> 1;
    const int b = blockIdx.x >> 4, h = blockIdx.x & 15;
    const size_t rowbase = (size_t)b * NTOK * PATCHDIM + h * DHEAD;

    const int offs[2] = { 0, DIMV };
#pragma unroll
    for (int t = 0; t < 2; t++) {
        uint32_t dbase = sbase + (uint32_t)(t * QK_TILE) * 2;
#pragma unroll
        for (int p = 0; p < 4; p++) {
            int q = tid + p * 256;
            int r = q >> 3, c = q & 7;
            cpa16(dbase + (uint32_t)(r * QKLD + c * 8) * 2,
                  qkvh + rowbase + (size_t)r * PATCHDIM + offs[t] + c * 8);
        }
    }
    cp_commit();
    cp_wait<0>();
    __syncthreads();

    float acc[4][4][4];
#pragma unroll
    for (int i = 0; i < 4; i++)
#pragma unroll
        for (int j = 0; j < 4; j++)
#pragma unroll
            for (int q = 0; q < 4; q++) acc[i][j][q] = 0.f;

    uint32_t sA  = sbase;
    uint32_t sB  = sbase + (uint32_t)QK_TILE * 2;
    const int arow = wm * 64 + (lane & 15);
    const int acolb = (lane >> 4) * 8;
    const int brow = wn * 32 + ((lane >> 4) * 8) + (lane & 7);
    const int bcolb = ((lane >> 3) & 1) * 8;

#pragma unroll
    for (int ks = 0; ks < 4; ks++) {
        const int acol = ks * 16 + acolb;
        const int bcol = ks * 16 + bcolb;
        uint32_t ah[4][4], bh[4][2];
#pragma unroll
        for (int mi = 0; mi < 4; mi++)
            ldsm4(ah[mi], sA + (uint32_t)((arow + mi * 16) * QKLD + acol) * 2);
#pragma unroll
        for (int gp = 0; gp < 2; gp++) {
            uint32_t rh[4];
            ldsm4(rh, sB + (uint32_t)((brow + gp * 16) * QKLD + bcol) * 2);
            bh[gp*2][0] = rh[0]; bh[gp*2][1] = rh[1];
            bh[gp*2+1][0] = rh[2]; bh[gp*2+1][1] = rh[3];
        }
#pragma unroll
        for (int mi = 0; mi < 4; mi++)
#pragma unroll
            for (int nj = 0; nj < 4; nj++)
                mma16816(acc[mi][nj], ah[mi], bh[nj]);
    }

    float* Wb = W + (size_t)blockIdx.x * (NTOK * NTOK);
#pragma unroll
    for (int mi = 0; mi < 4; mi++) {
        int i0 = wm * 64 + mi * 16 + (lane >> 2);
#pragma unroll
        for (int nj = 0; nj < 4; nj++) {
            int j0 = wn * 32 + nj * 8 + (lane & 3) * 2;
#pragma unroll
            for (int rr = 0; rr < 2; rr++) {
                int i = i0 + rr * 8;
                float vx = acc[mi][nj][rr*2], vy = acc[mi][nj][rr*2+1];
                Wb[i * 128 + j0]     = vx * 0.125f * (1.0f + dist[i * 128 + j0]);
                Wb[i * 128 + j0 + 1] = vy * 0.125f * (1.0f + dist[i * 128 + j0 + 1]);
            }
        }
    }
}

// ---------------------------------------------------------------------------
// Cross-head standardize (ddof=1) + softmax; emits fp16 P.
// ---------------------------------------------------------------------------
__global__ __launch_bounds__(128) void std_softmax_kernel(
    const float* __restrict__ W, __half* __restrict__ Ph)
{
    int b = blockIdx.x >> 7, i = blockIdx.x & 127;
    int j = threadIdx.x;
    __shared__ float sm[NHEADS][128];

    size_t base = (size_t)b * (NHEADS * NTOK * NTOK) + (size_t)i * 128 + j;
    float vals[NHEADS];
    float s = 0.f;
#pragma unroll
    for (int h = 0; h < NHEADS; h++) {
        float v = W[base + (size_t)h * (NTOK * NTOK)];
        vals[h] = v; s += v;
    }
    float mu = s * (1.0f / 16.0f);
    float d2 = 0.f;
#pragma unroll
    for (int h = 0; h < NHEADS; h++) {
        float d = vals[h] - mu;
        d2 += d * d;
    }
    float inv = rsqrtf(d2 * (1.0f / 15.0f));
#pragma unroll
    for (int h = 0; h < NHEADS; h++) sm[h][j] = (vals[h] - mu) * inv;
    __syncthreads();

    int warp = j >> 5, lane = j & 31;
#pragma unroll
    for (int r = 0; r < 4; r++) {
        int h = warp * 4 + r;
        float v0 = sm[h][lane], v1 = sm[h][lane + 32];
        float v2 = sm[h][lane + 64], v3 = sm[h][lane + 96];
        float m = fmaxf(fmaxf(v0, v1), fmaxf(v2, v3));
#pragma unroll
        for (int o = 16; o; o >>= 1) m = fmaxf(m, __shfl_xor_sync(0xffffffffu, m, o));
        float e0 = expf(v0 - m), e1 = expf(v1 - m);
        float e2 = expf(v2 - m), e3 = expf(v3 - m);
        float sum = e0 + e1 + e2 + e3;
#pragma unroll
        for (int o = 16; o; o >>= 1) sum += __shfl_xor_sync(0xffffffffu, sum, o);
        float rs = 1.0f / sum;
        size_t wb = (size_t)b * (NHEADS * NTOK * NTOK) + (size_t)h * (NTOK * NTOK)
                  + (size_t)i * 128;
        Ph[wb + lane]      = __float2half_rn(e0 * rs);
        Ph[wb + lane + 32] = __float2half_rn(e1 * rs);
        Ph[wb + lane + 64] = __float2half_rn(e2 * rs);
        Ph[wb + lane + 96] = __float2half_rn(e3 * rs);
    }
}

// ---------------------------------------------------------------------------
// av via HMMA: O[i,h*64+d] = sum_j Ph[i,j]*Vh[j,d]. CTA per (b,h).
// ---------------------------------------------------------------------------
#define AVPLD 136
#define AVVLD 72
#define AVP_TILE (128 * AVPLD)
#define AVV_TILE (128 * AVVLD)
#define AV_SMEM ((AVP_TILE + AVV_TILE) * 2)

__global__ __launch_bounds__(256, 2) void av_mma_kernel(
    const __half* __restrict__ Ph, const __half* __restrict__ qkvh,
    __half* __restrict__ Oh)
{
    extern __shared__ __half smem[];
    const uint32_t sbase = smem_u32(smem);
    const int tid = threadIdx.x, lane = tid & 31, warp = tid >> 5;
    const int wm = warp & 3, wn = warp >> 2;
    const int b = blockIdx.x >> 4, h = blockIdx.x & 15;
    const size_t pbase = (size_t)blockIdx.x * (NTOK * NTOK);
    const size_t vbase = (size_t)b * NTOK * PATCHDIM + 2 * DIMV + h * DHEAD;

#pragma unroll
    for (int p = 0; p < 8; p++) {
        int q = tid + p * 256;
        int r = q >> 4, c = q & 15;
        cpa16(sbase + (uint32_t)(r * AVPLD + c * 8) * 2,
              Ph + pbase + (size_t)r * 128 + c * 8);
    }
    {
        uint32_t dbase = sbase + (uint32_t)AVP_TILE * 2;
#pragma unroll
        for (int p = 0; p < 4; p++) {
            int q = tid + p * 256;
            int j = q >> 3, c = q & 7;
            cpa16(dbase + (uint32_t)(j * AVVLD + c * 8) * 2,
                  qkvh + vbase + (size_t)j * PATCHDIM + c * 8);
        }
    }
    cp_commit();
    cp_wait<0>();
    __syncthreads();

    float acc[2][4][4];
#pragma unroll
    for (int i = 0; i < 2; i++)
#pragma unroll
        for (int j = 0; j < 4; j++)
#pragma unroll
            for (int q = 0; q < 4; q++) acc[i][j][q] = 0.f;

    uint32_t sA  = sbase;
    uint32_t sB  = sbase + (uint32_t)AVP_TILE * 2;
    const int arow = wm * 32 + (lane & 15);
    const int acolb = (lane >> 4) * 8;
    const int bjrow = lane & 15;
    const int bdcol = (lane >> 4) * 8;

#pragma unroll
    for (int kc = 0; kc < 8; kc++) {
        const int acol = kc * 16 + acolb;
        uint32_t ah[2][4], bh[4][2];
#pragma unroll
        for (int mi = 0; mi < 2; mi++)
            ldsm4(ah[mi], sA + (uint32_t)((arow + mi * 16) * AVPLD + acol) * 2);
#pragma unroll
        for (int gp = 0; gp < 2; gp++) {
            uint32_t rh[4];
            uint32_t off = (uint32_t)((kc * 16 + bjrow) * AVVLD
                                      + wn * 32 + gp * 16 + bdcol) * 2;
            ldsm4t(rh, sB + off);
            bh[gp*2][0] = rh[0]; bh[gp*2][1] = rh[1];
            bh[gp*2+1][0] = rh[2]; bh[gp*2+1][1] = rh[3];
        }
#pragma unroll
        for (int mi = 0; mi < 2; mi++)
#pragma unroll
            for (int nj = 0; nj < 4; nj++)
                mma16816(acc[mi][nj], ah[mi], bh[nj]);
    }

#pragma unroll
    for (int mi = 0; mi < 2; mi++) {
        int i0 = wm * 32 + mi * 16 + (lane >> 2);
#pragma unroll
        for (int nj = 0; nj < 4; nj++) {
            int d0 = wn * 32 + nj * 8 + (lane & 3) * 2;
#pragma unroll
            for (int rr = 0; rr < 2; rr++) {
                int i = i0 + rr * 8;
                size_t o = (size_t)(b * 128 + i) * DIMV + h * DHEAD + d0;
                *(__half2*)(Oh + o) =
                    __halves2half2(__float2half_rn(acc[mi][nj][rr*2]),
                                   __float2half_rn(acc[mi][nj][rr*2 + 1]));
            }
        }
    }
}

// ---------------------------------------------------------------------------
// Weight prep (fp16)
// ---------------------------------------------------------------------------
__global__ void split_kernel(const float* __restrict__ X, __half* __restrict__ H) {
    size_t i = (size_t)blockIdx.x * 256 + threadIdx.x;
    H[i] = __float2half_rn(X[i]);
}

__global__ void wtrans_kernel(const float* __restrict__ W,
                              __half* __restrict__ Th, int K, int N) {
    __shared__ float t[32][33];
    const float* Wl = W + (size_t)blockIdx.z * K * N;
    size_t ob = (size_t)blockIdx.z * K * N;
    int x = blockIdx.x * 32 + threadIdx.x;
    int y = blockIdx.y * 32 + threadIdx.y;
#pragma unroll
    for (int j = 0; j < 32; j += 8)
        t[threadIdx.y + j][threadIdx.x] = Wl[(size_t)(y + j) * N + x];
    __syncthreads();
    int n = blockIdx.x * 32 + threadIdx.y;
    int k = blockIdx.y * 32 + threadIdx.x;
#pragma unroll
    for (int j = 0; j < 32; j += 8) {
        size_t o = ob + (size_t)(n + j) * K + k;
        Th[o] = __float2half_rn(t[threadIdx.x][threadIdx.y + j]);
    }
}

__global__ void extract_patches_kernel(const float* __restrict__ img,
                                       __half* __restrict__ H) {
    int idx = blockIdx.x * 256 + threadIdx.x;
    int col = idx % PATCHDIM;
    int row = idx / PATCHDIM;
    int b = row >> 7, t = row & 127;
    int h = t >> 4, w = t & 15;
    int c = col >> 10, r = col & 1023;
    int p = r >> 5, q = r & 31;
    float v = img[(((size_t)b * 3 + c) * 256 + h * 32 + p) * 512 + w * 32 + q];
    H[idx] = __float2half_rn(v);
}

// ---------------------------------------------------------------------------
// LayerNorm
// ---------------------------------------------------------------------------
__device__ __forceinline__ void ln_stats(const float* __restrict__ x, size_t base,
                                         int D, float& mu, float& rstd) {
    float s = 0.f, ss = 0.f;
    for (int i = threadIdx.x; i < D; i += 256) {
        float v = x[base + i];
        s += v; ss += v * v;
    }
#pragma unroll
    for (int o = 16; o; o >>= 1) {
        s  += __shfl_xor_sync(0xffffffffu, s, o);
        ss += __shfl_xor_sync(0xffffffffu, ss, o);
    }
    __shared__ float sh[2][8];
    int w = threadIdx.x >> 5;
    if ((threadIdx.x & 31) == 0) { sh[0][w] = s; sh[1][w] = ss; }
    __syncthreads();
    if (threadIdx.x < 32) {
        s  = (threadIdx.x < 8) ? sh[0][threadIdx.x] : 0.f;
        ss = (threadIdx.x < 8) ? sh[1][threadIdx.x] : 0.f;
#pragma unroll
        for (int o = 4; o; o >>= 1) {
            s  += __shfl_xor_sync(0xffffffffu, s, o);
            ss += __shfl_xor_sync(0xffffffffu, ss, o);
        }
        if (threadIdx.x == 0) { sh[0][0] = s; sh[1][0] = ss; }
    }
    __syncthreads();
    s = sh[0][0]; ss = sh[1][0];
    float invD = 1.0f / (float)D;
    mu = s * invD;
    float var = ss * invD - mu * mu;
    rstd = rsqrtf(var + LN_EPS);
}

__global__ void ln_kernel(const float* __restrict__ x, const float* __restrict__ g,
                          const float* __restrict__ beta, float* __restrict__ y, int D) {
    size_t base = (size_t)blockIdx.x * D;
    float mu, rstd;
    ln_stats(x, base, D, mu, rstd);
    for (int i = threadIdx.x; i < D; i += 256)
        y[base + i] = (x[base + i] - mu) * rstd * g[i] + beta[i];
}

__global__ void ln_addpos_kernel(const float* __restrict__ x, const float* __restrict__ g,
                                 const float* __restrict__ beta,
                                 const float* __restrict__ sph_pos,
                                 const float* __restrict__ pos_w,
                                 const float* __restrict__ pos_b,
                                 float* __restrict__ y, int D) {
    size_t base = (size_t)blockIdx.x * D;
    float mu, rstd;
    ln_stats(x, base, D, mu, rstd);
    int tok = blockIdx.x & 127;
    float p0 = sph_pos[tok * 2], p1 = sph_pos[tok * 2 + 1];
    for (int i = threadIdx.x; i < D; i += 256) {
        float v = (x[base + i] - mu) * rstd * g[i] + beta[i];
        y[base + i] = v + p0 * pos_w[i] + p1 * pos_w[1024 + i] + pos_b[i];
    }
}

__global__ void ln_half_kernel(const float* __restrict__ x, const float* __restrict__ g,
                               const float* __restrict__ beta,
                               __half* __restrict__ H, int D) {
    size_t base = (size_t)blockIdx.x * D;
    float mu, rstd;
    ln_stats(x, base, D, mu, rstd);
    for (int i = threadIdx.x; i < D; i += 256) {
        float v = (x[base + i] - mu) * rstd * g[i] + beta[i];
        H[base + i] = __float2half_rn(v);
    }
}

__global__ void reassemble_kernel(const float* __restrict__ Y, float* __restrict__ out) {
    int idx = blockIdx.x * 256 + threadIdx.x;
    int xq = idx & 511;
    int rest = idx >> 9;
    int yr = rest & 255;
    rest >>= 8;
    int c = rest % 3;
    int b = rest / 3;
    int h = yr >> 5, p1 = yr & 31, w = xq >> 5, p2 = xq & 31;
    out[idx] = Y[(size_t)(b * 128 + h * 16 + w) * PATCHDIM + (p1 * 32 + p2) * 3 + c];
}

// ---------------------------------------------------------------------------
// Host launcher
// ---------------------------------------------------------------------------
extern "C" void kernel_launch(void* const* d_in, const int* in_sizes, int n_in,
                              void* d_out, int out_size)
{
    const float* img      = (const float*)d_in[0];
    const float* sph_pos  = (const float*)d_in[1];
    const float* sph_dist = (const float*)d_in[2];
    const float* conv_w   = (const float*)d_in[3];
    const float* conv_b   = (const float*)d_in[4];
    const float* nl_ln1_g = (const float*)d_in[5];
    const float* nl_ln1_b = (const float*)d_in[6];
    const float* nl_w     = (const float*)d_in[7];
    const float* nl_b     = (const float*)d_in[8];
    const float* nl_ln2_g = (const float*)d_in[9];
    const float* nl_ln2_b = (const float*)d_in[10];
    const float* pos_w    = (const float*)d_in[11];
    const float* pos_b    = (const float*)d_in[12];
    const float* ln_g     = (const float*)d_in[13];
    const float* ln_b     = (const float*)d_in[14];
    const float* wqkv     = (const float*)d_in[15];
    const float* wo       = (const float*)d_in[16];
    const float* wo_b     = (const float*)d_in[17];
    const float* tr_ln_g  = (const float*)d_in[18];
    const float* tr_ln_b  = (const float*)d_in[19];
    const float* exp_w    = (const float*)d_in[20];
    const float* exp_b    = (const float*)d_in[21];
    const float* out_ln_g = (const float*)d_in[22];
    const float* out_ln_b = (const float*)d_in[23];

    float *big, *x, *w;
    cudaGetSymbolAddress((void**)&big, g_big);
    cudaGetSymbolAddress((void**)&x,   g_x);
    cudaGetSymbolAddress((void**)&w,   g_w);
    __half *Xph, *qkvh, *hh, *oh, *ph;
    __half *cwh, *nlwh, *qwh, *owh, *ewh;
    cudaGetSymbolAddress((void**)&Xph, g_Xph);
    cudaGetSymbolAddress((void**)&qkvh, g_qkvh);
    cudaGetSymbolAddress((void**)&hh,  g_hh);
    cudaGetSymbolAddress((void**)&oh,  g_oh);
    cudaGetSymbolAddress((void**)&ph,  g_ph);
    cudaGetSymbolAddress((void**)&cwh, g_cwh);
    cudaGetSymbolAddress((void**)&nlwh, g_nlwh);
    cudaGetSymbolAddress((void**)&qwh, g_qwh);
    cudaGetSymbolAddress((void**)&owh, g_owh);
    cudaGetSymbolAddress((void**)&ewh, g_ewh);

    cudaFuncSetAttribute(hmma_gemm_kernel<0>,
                         cudaFuncAttributeMaxDynamicSharedMemorySize, HG_SMEM);
    cudaFuncSetAttribute(hmma_gemm256_kernel<0>,
                         cudaFuncAttributeMaxDynamicSharedMemorySize, HG2_SMEM);
    cudaFuncSetAttribute(hmma_gemm256_kernel<2>,
                         cudaFuncAttributeMaxDynamicSharedMemorySize, HG2_SMEM);
    cudaFuncSetAttribute(qk_mma_kernel,
                         cudaFuncAttributeMaxDynamicSharedMemorySize, QK_SMEM);
    cudaFuncSetAttribute(av_mma_kernel,
                         cudaFuncAttributeMaxDynamicSharedMemorySize, AV_SMEM);

    // ---- prep ----
    split_kernel<<<DIMV * PATCHDIM / 256, 256>>>(conv_w, cwh);
    extract_patches_kernel<<<ROWS * PATCHDIM / 256, 256>>>(img, Xph);
    wtrans_kernel<<<dim3(DIMV/32, DIMV/32, 1),     dim3(32,8)>>>(nl_w,  nlwh, DIMV, DIMV);
    wtrans_kernel<<<dim3(PATCHDIM/32, DIMV/32, DEPTH), dim3(32,8)>>>(wqkv, qwh, DIMV, PATCHDIM);
    wtrans_kernel<<<dim3(DIMV/32, DIMV/32, DEPTH), dim3(32,8)>>>(wo,    owh,  DIMV, DIMV);
    hmma_gemm_kernel<0><<<dim3(DIMV/128, ROWS/128), 256, HG_SMEM>>>(
        Xph, cwh, conv_b, nullptr, x, nullptr, ROWS, DIMV, PATCHDIM);
    wtrans_kernel<<<dim3(PATCHDIM/32, DIMV/32, 1), dim3(32,8)>>>(exp_w, ewh, DIMV, PATCHDIM);

    // ---- norm_linear + positional embedding ----
    ln_half_kernel<<<ROWS, 256>>>(x, nl_ln1_g, nl_ln1_b, hh, DIMV);
    hmma_gemm_kernel<0><<<dim3(DIMV/128, ROWS/128), 256, HG_SMEM>>>(
        hh, nlwh, nl_b, nullptr, x, nullptr, ROWS, DIMV, DIMV);
    ln_addpos_kernel<<<ROWS, 256>>>(x, nl_ln2_g, nl_ln2_b, sph_pos, pos_w, pos_b,
                                    x, DIMV);

    // ---- transformer layers ----
    for (int l = 0; l < DEPTH; l++) {
        ln_half_kernel<<<ROWS, 256>>>(x, ln_g + l * DIMV, ln_b + l * DIMV, hh, DIMV);
        hmma_gemm256_kernel<2><<<dim3(PATCHDIM/256, ROWS/128), 256, HG2_SMEM>>>(
            hh, qwh + (size_t)l * PATCHDIM * DIMV,
            nullptr, nullptr, nullptr, qkvh, ROWS, PATCHDIM, DIMV);
        qk_mma_kernel<<<BATCH * NHEADS, 256, QK_SMEM>>>(qkvh, sph_dist, w);
        std_softmax_kernel<<<BATCH * NTOK, 128>>>(w, ph);
        av_mma_kernel<<<BATCH * NHEADS, 256, AV_SMEM>>>(ph, qkvh, oh);
        hmma_gemm_kernel<0><<<dim3(DIMV/128, ROWS/128), 256, HG_SMEM>>>(
            oh, owh + (size_t)l * DIMV * DIMV,
            wo_b + l * DIMV, x, x, nullptr, ROWS, DIMV, DIMV);
    }

    // ---- final LN + expand + output LN + reassembly ----
    ln_half_kernel<<<ROWS, 256>>>(x, tr_ln_g, tr_ln_b, hh, DIMV);
    hmma_gemm256_kernel<0><<<dim3(PATCHDIM/256, ROWS/128), 256, HG2_SMEM>>>(
        hh, ewh, exp_b, nullptr, big, nullptr, ROWS, PATCHDIM, DIMV);
    ln_kernel<<<ROWS, 256>>>(big, out_ln_g, out_ln_b, big, PATCHDIM);
    reassemble_kernel<<<ROWS * PATCHDIM / 256, 256>>>(big, (float*)d_out);
}

// round 13
// speedup vs baseline: 3.4487x; 1.0315x over previous
#include <cuda_runtime.h>
#include <cuda_fp16.h>
#include <cstdint>

// ---------------------------------------------------------------------------
// SphereViT forward — pure-fp16 single-pass HMMA.
// R13: 3-stage 128x128 / 4-stage 128x256 pipelines; B read untransposed
//      ([K,N] + ldmatrix.trans) so weight prep is a pure fp32->fp16 stream.
// ---------------------------------------------------------------------------

#define BATCH     32
#define NTOK      128
#define ROWS      4096
#define DIMV      1024
#define PATCHDIM  3072
#define NHEADS    16
#define DHEAD     64
#define DEPTH     12
#define LN_EPS    1e-5f

// -------------------- scratch (device globals; no allocs) ------------------
__device__ float g_big[ROWS * PATCHDIM];
__device__ float g_x  [ROWS * DIMV];
__device__ float g_w  [BATCH * NHEADS * NTOK * NTOK];

__device__ __half g_Xph[ROWS * PATCHDIM];
__device__ __half g_qkvh[ROWS * PATCHDIM];
__device__ __half g_hh [ROWS * DIMV];
__device__ __half g_oh [ROWS * DIMV];
__device__ __half g_ph [BATCH*NHEADS*NTOK*NTOK];

// fp16 weights: conv in [N,K]; all others kept in native [K,N]
__device__ __half g_cwh[DIMV * PATCHDIM];
__device__ __half g_nlwh[DIMV * DIMV];
__device__ __half g_qwh[DEPTH * DIMV * PATCHDIM];
__device__ __half g_owh[DEPTH * DIMV * DIMV];
__device__ __half g_ewh[DIMV * PATCHDIM];

// ---------------------------------------------------------------------------
// PTX helpers
// ---------------------------------------------------------------------------
__device__ __forceinline__ uint32_t smem_u32(const void* p) {
    uint32_t a;
    asm("{ .reg .u64 t; cvta.to.shared.u64 t, %1; cvt.u32.u64 %0, t; }"
        : "=r"(a) : "l"(p));
    return a;
}
__device__ __forceinline__ void cpa16(uint32_t dst, const void* src) {
    asm volatile("cp.async.cg.shared.global [%0], [%1], 16;" :: "r"(dst), "l"(src));
}
__device__ __forceinline__ void cp_commit() { asm volatile("cp.async.commit_group;"); }
template <int NN>
__device__ __forceinline__ void cp_wait() {
    asm volatile("cp.async.wait_group %0;" :: "n"(NN));
}
__device__ __forceinline__ void ldsm4(uint32_t* r, uint32_t addr) {
    asm volatile("ldmatrix.sync.aligned.m8n8.x4.shared.b16 {%0,%1,%2,%3}, [%4];"
                 : "=r"(r[0]), "=r"(r[1]), "=r"(r[2]), "=r"(r[3]) : "r"(addr));
}
__device__ __forceinline__ void ldsm4t(uint32_t* r, uint32_t addr) {
    asm volatile("ldmatrix.sync.aligned.m8n8.x4.trans.shared.b16 {%0,%1,%2,%3}, [%4];"
                 : "=r"(r[0]), "=r"(r[1]), "=r"(r[2]), "=r"(r[3]) : "r"(addr));
}
__device__ __forceinline__ void mma16816(float* c, const uint32_t* a,
                                         const uint32_t* b) {
    asm volatile(
        "mma.sync.aligned.m16n8k16.row.col.f32.f16.f16.f32 "
        "{%0,%1,%2,%3}, {%4,%5,%6,%7}, {%8,%9}, {%0,%1,%2,%3};"
        : "+f"(c[0]), "+f"(c[1]), "+f"(c[2]), "+f"(c[3])
        : "r"(a[0]), "r"(a[1]), "r"(a[2]), "r"(a[3]), "r"(b[0]), "r"(b[1]));
}

#define GLDS 40
#define A_ELEMS (128 * GLDS)             // 5120
#define BKN_LD 136                        // [32 k][128+8 n]
#define STG_ELEMS (A_ELEMS + 5120)       // 10240 (B region sized for max layout)
#define HG_SMEM (3 * STG_ELEMS * 2)      // 61440 bytes, 3-stage

// ---------------------------------------------------------------------------
// 128x128 GEMM, 3-stage, 2 CTAs/SM.
// BT=true : B is [N,K] K-major (conv).  BT=false: B is [K,N] via ldsm.trans.
// OM: 0 = fp32 +bias +res, 2 = fp16 out.
// ---------------------------------------------------------------------------
template <int OM, bool BT>
__global__ __launch_bounds__(256, 2) void hmma_gemm_kernel(
    const __half* __restrict__ Ah, const __half* __restrict__ Bh,
    const float* __restrict__ bias, const float* __restrict__ res,
    float* __restrict__ C, __half* __restrict__ Ch, int M, int N, int K)
{
    extern __shared__ __half smem[];
    const uint32_t sbase = smem_u32(smem);
    const int tid  = threadIdx.x;
    const int lane = tid & 31, warp = tid >> 5;
    const int wm = warp & 1, wn = warp >> 1;
    const int m0 = blockIdx.y << 7, n0 = blockIdx.x << 7;

    const __half* gA = Ah + (size_t)m0 * K;
    const __half* gB = BT ? (Bh + (size_t)n0 * K) : (Bh + n0);

    const int r0c = tid >> 2, c0c = tid & 3;

    auto issue = [&](int stage, int k0) {
        uint32_t sA = sbase + (uint32_t)(stage * STG_ELEMS) * 2;
        uint32_t sB = sA + A_ELEMS * 2;
#pragma unroll
        for (int half_ = 0; half_ < 2; half_++) {
            int r = r0c + half_ * 64;
            cpa16(sA + (uint32_t)(r * GLDS + c0c * 8) * 2,
                  gA + (size_t)r * K + k0 + c0c * 8);
        }
        if (BT) {
#pragma unroll
            for (int half_ = 0; half_ < 2; half_++) {
                int r = r0c + half_ * 64;
                cpa16(sB + (uint32_t)(r * GLDS + c0c * 8) * 2,
                      gB + (size_t)r * K + k0 + c0c * 8);
            }
        } else {
#pragma unroll
            for (int p = 0; p < 2; p++) {
                int q = tid + p * 256;       // 0..511
                int r = q >> 4, c = q & 15;  // k row, 8-half chunk
                cpa16(sB + (uint32_t)(r * BKN_LD + c * 8) * 2,
                      gB + (size_t)(k0 + r) * N + c * 8);
            }
        }
    };

    float acc[4][4][4];
#pragma unroll
    for (int i = 0; i < 4; i++)
#pragma unroll
        for (int j = 0; j < 4; j++)
#pragma unroll
            for (int q = 0; q < 4; q++) acc[i][j][q] = 0.f;

    const int nk = K >> 5;
    issue(0, 0);  cp_commit();
    if (nk > 1) issue(1, 32);
    cp_commit();

    const int arow = wm * 64 + (lane & 15);
    const int acolb = (lane >> 4) * 8;
    // BT=true fragment addressing
    const int brow = wn * 32 + ((lane >> 4) * 8) + (lane & 7);
    const int bcolb = ((lane >> 3) & 1) * 8;
    // BT=false fragment addressing
    const int bjrow = lane & 15;
    const int bdcol = (lane >> 4) * 8;

    for (int it = 0; it < nk; ++it) {
        cp_wait<1>();
        __syncthreads();

        const int s = it % 3;
        uint32_t sA = sbase + (uint32_t)(s * STG_ELEMS) * 2;
        uint32_t sB = sA + A_ELEMS * 2;

#pragma unroll
        for (int ks = 0; ks < 2; ks++) {
            const int acol = ks * 16 + acolb;
            uint32_t ah[4][4], bh[4][2];
#pragma unroll
            for (int mi = 0; mi < 4; mi++)
                ldsm4(ah[mi], sA + (uint32_t)((arow + mi * 16) * GLDS + acol) * 2);
            if (BT) {
                const int bcol = ks * 16 + bcolb;
#pragma unroll
                for (int gp = 0; gp < 2; gp++) {
                    uint32_t rh[4];
                    ldsm4(rh, sB + (uint32_t)((brow + gp * 16) * GLDS + bcol) * 2);
                    bh[gp*2][0] = rh[0]; bh[gp*2][1] = rh[1];
                    bh[gp*2+1][0] = rh[2]; bh[gp*2+1][1] = rh[3];
                }
            } else {
#pragma unroll
                for (int gp = 0; gp < 2; gp++) {
                    uint32_t rh[4];
                    uint32_t off = (uint32_t)((ks * 16 + bjrow) * BKN_LD
                                              + wn * 32 + gp * 16 + bdcol) * 2;
                    ldsm4t(rh, sB + off);
                    bh[gp*2][0] = rh[0]; bh[gp*2][1] = rh[1];
                    bh[gp*2+1][0] = rh[2]; bh[gp*2+1][1] = rh[3];
                }
            }
#pragma unroll
            for (int mi = 0; mi < 4; mi++)
#pragma unroll
                for (int nj = 0; nj < 4; nj++)
                    mma16816(acc[mi][nj], ah[mi], bh[nj]);
        }

        if (it + 2 < nk) issue((it + 2) % 3, (it + 2) << 5);
        cp_commit();
    }

#pragma unroll
    for (int mi = 0; mi < 4; mi++) {
        int r0 = m0 + wm * 64 + mi * 16 + (lane >> 2);
#pragma unroll
        for (int nj = 0; nj < 4; nj++) {
            int c = n0 + wn * 32 + nj * 8 + (lane & 3) * 2;
            float v0x = acc[mi][nj][0], v0y = acc[mi][nj][1];
            float v1x = acc[mi][nj][2], v1y = acc[mi][nj][3];
            size_t o0 = (size_t)r0 * N + c;
            size_t o1 = o0 + (size_t)8 * N;
            if (OM == 2) {
                *(__half2*)(Ch + o0) =
                    __halves2half2(__float2half_rn(v0x), __float2half_rn(v0y));
                *(__half2*)(Ch + o1) =
                    __halves2half2(__float2half_rn(v1x), __float2half_rn(v1y));
            } else {
                if (bias) {
                    float bx = bias[c], by = bias[c + 1];
                    v0x += bx; v0y += by; v1x += bx; v1y += by;
                }
                if (res) {
                    float2 ra = *(const float2*)(res + o0);
                    float2 rb = *(const float2*)(res + o1);
                    v0x += ra.x; v0y += ra.y; v1x += rb.x; v1y += rb.y;
                }
                *(float2*)(C + o0) = make_float2(v0x, v0y);
                *(float2*)(C + o1) = make_float2(v1x, v1y);
            }
        }
    }
}

// ---------------------------------------------------------------------------
// 128x256 GEMM, 4-stage, 1 CTA/SM, B in [K,N] via ldsm.trans.
// ---------------------------------------------------------------------------
#define BKN2_LD 264                      // [32 k][256+8 n]
#define BF2_ELEMS (32 * BKN2_LD)         // 8448
#define STG2_ELEMS (A_ELEMS + BF2_ELEMS) // 13568
#define HG2_SMEM (4 * STG2_ELEMS * 2)    // 108544 bytes

template <int OM>
__global__ __launch_bounds__(256, 1) void hmma_gemm256_kernel(
    const __half* __restrict__ Ah, const __half* __restrict__ Bh,
    const float* __restrict__ bias, const float* __restrict__ res,
    float* __restrict__ C, __half* __restrict__ Ch, int M, int N, int K)
{
    extern __shared__ __half smem[];
    const uint32_t sbase = smem_u32(smem);
    const int tid  = threadIdx.x;
    const int lane = tid & 31, warp = tid >> 5;
    const int wm = warp & 1, wn = warp >> 1;          // wn 0..3
    const int m0 = blockIdx.y << 7, n0 = blockIdx.x << 8;

    const __half* gA = Ah + (size_t)m0 * K;
    const __half* gB = Bh + n0;

    const int r0c = tid >> 2, c0c = tid & 3;

    auto issue = [&](int stage, int k0) {
        uint32_t sA = sbase + (uint32_t)(stage * STG2_ELEMS) * 2;
        uint32_t sB = sA + A_ELEMS * 2;
#pragma unroll
        for (int half_ = 0; half_ < 2; half_++) {
            int r = r0c + half_ * 64;
            cpa16(sA + (uint32_t)(r * GLDS + c0c * 8) * 2,
                  gA + (size_t)r * K + k0 + c0c * 8);
        }
#pragma unroll
        for (int p = 0; p < 4; p++) {
            int q = tid + p * 256;       // 0..1023
            int r = q >> 5, c = q & 31;  // k row, 8-half chunk
            cpa16(sB + (uint32_t)(r * BKN2_LD + c * 8) * 2,
                  gB + (size_t)(k0 + r) * N + c * 8);
        }
    };

    float acc[4][8][4];
#pragma unroll
    for (int i = 0; i < 4; i++)
#pragma unroll
        for (int j = 0; j < 8; j++)
#pragma unroll
            for (int q = 0; q < 4; q++) acc[i][j][q] = 0.f;

    const int nk = K >> 5;
    issue(0, 0);              cp_commit();
    if (nk > 1) issue(1, 32); cp_commit();
    if (nk > 2) issue(2, 64); cp_commit();

    const int arow = wm * 64 + (lane & 15);
    const int acolb = (lane >> 4) * 8;
    const int bjrow = lane & 15;
    const int bdcol = (lane >> 4) * 8;

    for (int it = 0; it < nk; ++it) {
        cp_wait<2>();
        __syncthreads();

        const int s = it & 3;
        uint32_t sA = sbase + (uint32_t)(s * STG2_ELEMS) * 2;
        uint32_t sB = sA + A_ELEMS * 2;

#pragma unroll
        for (int ks = 0; ks < 2; ks++) {
            const int acol = ks * 16 + acolb;
            uint32_t ah[4][4], bh[8][2];
#pragma unroll
            for (int mi = 0; mi < 4; mi++)
                ldsm4(ah[mi], sA + (uint32_t)((arow + mi * 16) * GLDS + acol) * 2);
#pragma unroll
            for (int gp = 0; gp < 4; gp++) {
                uint32_t rh[4];
                uint32_t off = (uint32_t)((ks * 16 + bjrow) * BKN2_LD
                                          + wn * 64 + gp * 16 + bdcol) * 2;
                ldsm4t(rh, sB + off);
                bh[gp*2][0] = rh[0]; bh[gp*2][1] = rh[1];
                bh[gp*2+1][0] = rh[2]; bh[gp*2+1][1] = rh[3];
            }
#pragma unroll
            for (int mi = 0; mi < 4; mi++)
#pragma unroll
                for (int nj = 0; nj < 8; nj++)
                    mma16816(acc[mi][nj], ah[mi], bh[nj]);
        }

        if (it + 3 < nk) issue((it + 3) & 3, (it + 3) << 5);
        cp_commit();
    }

#pragma unroll
    for (int mi = 0; mi < 4; mi++) {
        int r0 = m0 + wm * 64 + mi * 16 + (lane >> 2);
#pragma unroll
        for (int nj = 0; nj < 8; nj++) {
            int c = n0 + wn * 64 + nj * 8 + (lane & 3) * 2;
            float v0x = acc[mi][nj][0], v0y = acc[mi][nj][1];
            float v1x = acc[mi][nj][2], v1y = acc[mi][nj][3];
            size_t o0 = (size_t)r0 * N + c;
            size_t o1 = o0 + (size_t)8 * N;
            if (OM == 2) {
                *(__half2*)(Ch + o0) =
                    __halves2half2(__float2half_rn(v0x), __float2half_rn(v0y));
                *(__half2*)(Ch + o1) =
                    __halves2half2(__float2half_rn(v1x), __float2half_rn(v1y));
            } else {
                if (bias) {
                    float bx = bias[c], by = bias[c + 1];
                    v0x += bx; v0y += by; v1x += bx; v1y += by;
                }
                if (res) {
                    float2 ra = *(const float2*)(res + o0);
                    float2 rb = *(const float2*)(res + o1);
                    v0x += ra.x; v0y += ra.y; v1x += rb.x; v1y += rb.y;
                }
                *(float2*)(C + o0) = make_float2(v0x, v0y);
                *(float2*)(C + o1) = make_float2(v1x, v1y);
            }
        }
    }
}

// ---------------------------------------------------------------------------
// qk via HMMA: W = (qh_i . kh_j)*0.125*(1+dist). CTA per (b,h).
// ---------------------------------------------------------------------------
#define QKLD 72
#define QK_TILE (128 * QKLD)
#define QK_SMEM (2 * QK_TILE * 2)

__global__ __launch_bounds__(256, 2) void qk_mma_kernel(
    const __half* __restrict__ qkvh,
    const float* __restrict__ dist, float* __restrict__ W)
{
    extern __shared__ __half smem[];
    const uint32_t sbase = smem_u32(smem);
    const int tid = threadIdx.x, lane = tid & 31, warp = tid >> 5;
    const int wm = warp & 1, wn = warp >> 1;
    const int b = blockIdx.x >> 4, h = blockIdx.x & 15;
    const size_t rowbase = (size_t)b * NTOK * PATCHDIM + h * DHEAD;

    const int offs[2] = { 0, DIMV };
#pragma unroll
    for (int t = 0; t < 2; t++) {
        uint32_t dbase = sbase + (uint32_t)(t * QK_TILE) * 2;
#pragma unroll
        for (int p = 0; p < 4; p++) {
            int q = tid + p * 256;
            int r = q >> 3, c = q & 7;
            cpa16(dbase + (uint32_t)(r * QKLD + c * 8) * 2,
                  qkvh + rowbase + (size_t)r * PATCHDIM + offs[t] + c * 8);
        }
    }
    cp_commit();
    cp_wait<0>();
    __syncthreads();

    float acc[4][4][4];
#pragma unroll
    for (int i = 0; i < 4; i++)
#pragma unroll
        for (int j = 0; j < 4; j++)
#pragma unroll
            for (int q = 0; q < 4; q++) acc[i][j][q] = 0.f;

    uint32_t sA  = sbase;
    uint32_t sB  = sbase + (uint32_t)QK_TILE * 2;
    const int arow = wm * 64 + (lane & 15);
    const int acolb = (lane >> 4) * 8;
    const int brow = wn * 32 + ((lane >> 4) * 8) + (lane & 7);
    const int bcolb = ((lane >> 3) & 1) * 8;

#pragma unroll
    for (int ks = 0; ks < 4; ks++) {
        const int acol = ks * 16 + acolb;
        const int bcol = ks * 16 + bcolb;
        uint32_t ah[4][4], bh[4][2];
#pragma unroll
        for (int mi = 0; mi < 4; mi++)
            ldsm4(ah[mi], sA + (uint32_t)((arow + mi * 16) * QKLD + acol) * 2);
#pragma unroll
        for (int gp = 0; gp < 2; gp++) {
            uint32_t rh[4];
            ldsm4(rh, sB + (uint32_t)((brow + gp * 16) * QKLD + bcol) * 2);
            bh[gp*2][0] = rh[0]; bh[gp*2][1] = rh[1];
            bh[gp*2+1][0] = rh[2]; bh[gp*2+1][1] = rh[3];
        }
#pragma unroll
        for (int mi = 0; mi < 4; mi++)
#pragma unroll
            for (int nj = 0; nj < 4; nj++)
                mma16816(acc[mi][nj], ah[mi], bh[nj]);
    }

    float* Wb = W + (size_t)blockIdx.x * (NTOK * NTOK);
#pragma unroll
    for (int mi = 0; mi < 4; mi++) {
        int i0 = wm * 64 + mi * 16 + (lane >> 2);
#pragma unroll
        for (int nj = 0; nj < 4; nj++) {
            int j0 = wn * 32 + nj * 8 + (lane & 3) * 2;
#pragma unroll
            for (int rr = 0; rr < 2; rr++) {
                int i = i0 + rr * 8;
                float vx = acc[mi][nj][rr*2], vy = acc[mi][nj][rr*2+1];
                Wb[i * 128 + j0]     = vx * 0.125f * (1.0f + dist[i * 128 + j0]);
                Wb[i * 128 + j0 + 1] = vy * 0.125f * (1.0f + dist[i * 128 + j0 + 1]);
            }
        }
    }
}

// ---------------------------------------------------------------------------
// Cross-head standardize (ddof=1) + softmax; emits fp16 P.
// ---------------------------------------------------------------------------
__global__ __launch_bounds__(128) void std_softmax_kernel(
    const float* __restrict__ W, __half* __restrict__ Ph)
{
    int b = blockIdx.x >> 7, i = blockIdx.x & 127;
    int j = threadIdx.x;
    __shared__ float sm[NHEADS][128];

    size_t base = (size_t)b * (NHEADS * NTOK * NTOK) + (size_t)i * 128 + j;
    float vals[NHEADS];
    float s = 0.f;
#pragma unroll
    for (int h = 0; h < NHEADS; h++) {
        float v = W[base + (size_t)h * (NTOK * NTOK)];
        vals[h] = v; s += v;
    }
    float mu = s * (1.0f / 16.0f);
    float d2 = 0.f;
#pragma unroll
    for (int h = 0; h < NHEADS; h++) {
        float d = vals[h] - mu;
        d2 += d * d;
    }
    float inv = rsqrtf(d2 * (1.0f / 15.0f));
#pragma unroll
    for (int h = 0; h < NHEADS; h++) sm[h][j] = (vals[h] - mu) * inv;
    __syncthreads();

    int warp = j >> 5, lane = j & 31;
#pragma unroll
    for (int r = 0; r < 4; r++) {
        int h = warp * 4 + r;
        float v0 = sm[h][lane], v1 = sm[h][lane + 32];
        float v2 = sm[h][lane + 64], v3 = sm[h][lane + 96];
        float m = fmaxf(fmaxf(v0, v1), fmaxf(v2, v3));
#pragma unroll
        for (int o = 16; o; o >>= 1) m = fmaxf(m, __shfl_xor_sync(0xffffffffu, m, o));
        float e0 = expf(v0 - m), e1 = expf(v1 - m);
        float e2 = expf(v2 - m), e3 = expf(v3 - m);
        float sum = e0 + e1 + e2 + e3;
#pragma unroll
        for (int o = 16; o; o >>= 1) sum += __shfl_xor_sync(0xffffffffu, sum, o);
        float rs = 1.0f / sum;
        size_t wb = (size_t)b * (NHEADS * NTOK * NTOK) + (size_t)h * (NTOK * NTOK)
                  + (size_t)i * 128;
        Ph[wb + lane]      = __float2half_rn(e0 * rs);
        Ph[wb + lane + 32] = __float2half_rn(e1 * rs);
        Ph[wb + lane + 64] = __float2half_rn(e2 * rs);
        Ph[wb + lane + 96] = __float2half_rn(e3 * rs);
    }
}

// ---------------------------------------------------------------------------
// av via HMMA: O[i,h*64+d] = sum_j Ph[i,j]*Vh[j,d]. CTA per (b,h).
// ---------------------------------------------------------------------------
#define AVPLD 136
#define AVVLD 72
#define AVP_TILE (128 * AVPLD)
#define AVV_TILE (128 * AVVLD)
#define AV_SMEM ((AVP_TILE + AVV_TILE) * 2)

__global__ __launch_bounds__(256, 2) void av_mma_kernel(
    const __half* __restrict__ Ph, const __half* __restrict__ qkvh,
    __half* __restrict__ Oh)
{
    extern __shared__ __half smem[];
    const uint32_t sbase = smem_u32(smem);
    const int tid = threadIdx.x, lane = tid & 31, warp = tid >> 5;
    const int wm = warp & 3, wn = warp >> 2;
    const int b = blockIdx.x >> 4, h = blockIdx.x & 15;
    const size_t pbase = (size_t)blockIdx.x * (NTOK * NTOK);
    const size_t vbase = (size_t)b * NTOK * PATCHDIM + 2 * DIMV + h * DHEAD;

#pragma unroll
    for (int p = 0; p < 8; p++) {
        int q = tid + p * 256;
        int r = q >> 4, c = q & 15;
        cpa16(sbase + (uint32_t)(r * AVPLD + c * 8) * 2,
              Ph + pbase + (size_t)r * 128 + c * 8);
    }
    {
        uint32_t dbase = sbase + (uint32_t)AVP_TILE * 2;
#pragma unroll
        for (int p = 0; p < 4; p++) {
            int q = tid + p * 256;
            int j = q >> 3, c = q & 7;
            cpa16(dbase + (uint32_t)(j * AVVLD + c * 8) * 2,
                  qkvh + vbase + (size_t)j * PATCHDIM + c * 8);
        }
    }
    cp_commit();
    cp_wait<0>();
    __syncthreads();

    float acc[2][4][4];
#pragma unroll
    for (int i = 0; i < 2; i++)
#pragma unroll
        for (int j = 0; j < 4; j++)
#pragma unroll
            for (int q = 0; q < 4; q++) acc[i][j][q] = 0.f;

    uint32_t sA  = sbase;
    uint32_t sB  = sbase + (uint32_t)AVP_TILE * 2;
    const int arow = wm * 32 + (lane & 15);
    const int acolb = (lane >> 4) * 8;
    const int bjrow = lane & 15;
    const int bdcol = (lane >> 4) * 8;

#pragma unroll
    for (int kc = 0; kc < 8; kc++) {
        const int acol = kc * 16 + acolb;
        uint32_t ah[2][4], bh[4][2];
#pragma unroll
        for (int mi = 0; mi < 2; mi++)
            ldsm4(ah[mi], sA + (uint32_t)((arow + mi * 16) * AVPLD + acol) * 2);
#pragma unroll
        for (int gp = 0; gp < 2; gp++) {
            uint32_t rh[4];
            uint32_t off = (uint32_t)((kc * 16 + bjrow) * AVVLD
                                      + wn * 32 + gp * 16 + bdcol) * 2;
            ldsm4t(rh, sB + off);
            bh[gp*2][0] = rh[0]; bh[gp*2][1] = rh[1];
            bh[gp*2+1][0] = rh[2]; bh[gp*2+1][1] = rh[3];
        }
#pragma unroll
        for (int mi = 0; mi < 2; mi++)
#pragma unroll
            for (int nj = 0; nj < 4; nj++)
                mma16816(acc[mi][nj], ah[mi], bh[nj]);
    }

#pragma unroll
    for (int mi = 0; mi < 2; mi++) {
        int i0 = wm * 32 + mi * 16 + (lane >> 2);
#pragma unroll
        for (int nj = 0; nj < 4; nj++) {
            int d0 = wn * 32 + nj * 8 + (lane & 3) * 2;
#pragma unroll
            for (int rr = 0; rr < 2; rr++) {
                int i = i0 + rr * 8;
                size_t o = (size_t)(b * 128 + i) * DIMV + h * DHEAD + d0;
                *(__half2*)(Oh + o) =
                    __halves2half2(__float2half_rn(acc[mi][nj][rr*2]),
                                   __float2half_rn(acc[mi][nj][rr*2 + 1]));
            }
        }
    }
}

// ---------------------------------------------------------------------------
// Weight prep: straight fp32 -> fp16 stream (no transpose).
// ---------------------------------------------------------------------------
__global__ void split_kernel(const float* __restrict__ X, __half* __restrict__ H) {
    size_t i = (size_t)blockIdx.x * 256 + threadIdx.x;
    H[i] = __float2half_rn(X[i]);
}

__global__ void extract_patches_kernel(const float* __restrict__ img,
                                       __half* __restrict__ H) {
    int idx = blockIdx.x * 256 + threadIdx.x;
    int col = idx % PATCHDIM;
    int row = idx / PATCHDIM;
    int b = row >> 7, t = row & 127;
    int h = t >> 4, w = t & 15;
    int c = col >> 10, r = col & 1023;
    int p = r >> 5, q = r & 31;
    float v = img[(((size_t)b * 3 + c) * 256 + h * 32 + p) * 512 + w * 32 + q];
    H[idx] = __float2half_rn(v);
}

// ---------------------------------------------------------------------------
// LayerNorm
// ---------------------------------------------------------------------------
__device__ __forceinline__ void ln_stats(const float* __restrict__ x, size_t base,
                                         int D, float& mu, float& rstd) {
    float s = 0.f, ss = 0.f;
    for (int i = threadIdx.x; i < D; i += 256) {
        float v = x[base + i];
        s += v; ss += v * v;
    }
#pragma unroll
    for (int o = 16; o; o >>= 1) {
        s  += __shfl_xor_sync(0xffffffffu, s, o);
        ss += __shfl_xor_sync(0xffffffffu, ss, o);
    }
    __shared__ float sh[2][8];
    int w = threadIdx.x >> 5;
    if ((threadIdx.x & 31) == 0) { sh[0][w] = s; sh[1][w] = ss; }
    __syncthreads();
    if (threadIdx.x < 32) {
        s  = (threadIdx.x < 8) ? sh[0][threadIdx.x] : 0.f;
        ss = (threadIdx.x < 8) ? sh[1][threadIdx.x] : 0.f;
#pragma unroll
        for (int o = 4; o; o >>= 1) {
            s  += __shfl_xor_sync(0xffffffffu, s, o);
            ss += __shfl_xor_sync(0xffffffffu, ss, o);
        }
        if (threadIdx.x == 0) { sh[0][0] = s; sh[1][0] = ss; }
    }
    __syncthreads();
    s = sh[0][0]; ss = sh[1][0];
    float invD = 1.0f / (float)D;
    mu = s * invD;
    float var = ss * invD - mu * mu;
    rstd = rsqrtf(var + LN_EPS);
}

__global__ void ln_kernel(const float* __restrict__ x, const float* __restrict__ g,
                          const float* __restrict__ beta, float* __restrict__ y, int D) {
    size_t base = (size_t)blockIdx.x * D;
    float mu, rstd;
    ln_stats(x, base, D, mu, rstd);
    for (int i = threadIdx.x; i < D; i += 256)
        y[base + i] = (x[base + i] - mu) * rstd * g[i] + beta[i];
}

__global__ void ln_addpos_kernel(const float* __restrict__ x, const float* __restrict__ g,
                                 const float* __restrict__ beta,
                                 const float* __restrict__ sph_pos,
                                 const float* __restrict__ pos_w,
                                 const float* __restrict__ pos_b,
                                 float* __restrict__ y, int D) {
    size_t base = (size_t)blockIdx.x * D;
    float mu, rstd;
    ln_stats(x, base, D, mu, rstd);
    int tok = blockIdx.x & 127;
    float p0 = sph_pos[tok * 2], p1 = sph_pos[tok * 2 + 1];
    for (int i = threadIdx.x; i < D; i += 256) {
        float v = (x[base + i] - mu) * rstd * g[i] + beta[i];
        y[base + i] = v + p0 * pos_w[i] + p1 * pos_w[1024 + i] + pos_b[i];
    }
}

__global__ void ln_half_kernel(const float* __restrict__ x, const float* __restrict__ g,
                               const float* __restrict__ beta,
                               __half* __restrict__ H, int D) {
    size_t base = (size_t)blockIdx.x * D;
    float mu, rstd;
    ln_stats(x, base, D, mu, rstd);
    for (int i = threadIdx.x; i < D; i += 256) {
        float v = (x[base + i] - mu) * rstd * g[i] + beta[i];
        H[base + i] = __float2half_rn(v);
    }
}

__global__ void reassemble_kernel(const float* __restrict__ Y, float* __restrict__ out) {
    int idx = blockIdx.x * 256 + threadIdx.x;
    int xq = idx & 511;
    int rest = idx >> 9;
    int yr = rest & 255;
    rest >>= 8;
    int c = rest % 3;
    int b = rest / 3;
    int h = yr >> 5, p1 = yr & 31, w = xq >> 5, p2 = xq & 31;
    out[idx] = Y[(size_t)(b * 128 + h * 16 + w) * PATCHDIM + (p1 * 32 + p2) * 3 + c];
}

// ---------------------------------------------------------------------------
// Host launcher
// ---------------------------------------------------------------------------
extern "C" void kernel_launch(void* const* d_in, const int* in_sizes, int n_in,
                              void* d_out, int out_size)
{
    const float* img      = (const float*)d_in[0];
    const float* sph_pos  = (const float*)d_in[1];
    const float* sph_dist = (const float*)d_in[2];
    const float* conv_w   = (const float*)d_in[3];
    const float* conv_b   = (const float*)d_in[4];
    const float* nl_ln1_g = (const float*)d_in[5];
    const float* nl_ln1_b = (const float*)d_in[6];
    const float* nl_w     = (const float*)d_in[7];
    const float* nl_b     = (const float*)d_in[8];
    const float* nl_ln2_g = (const float*)d_in[9];
    const float* nl_ln2_b = (const float*)d_in[10];
    const float* pos_w    = (const float*)d_in[11];
    const float* pos_b    = (const float*)d_in[12];
    const float* ln_g     = (const float*)d_in[13];
    const float* ln_b     = (const float*)d_in[14];
    const float* wqkv     = (const float*)d_in[15];
    const float* wo       = (const float*)d_in[16];
    const float* wo_b     = (const float*)d_in[17];
    const float* tr_ln_g  = (const float*)d_in[18];
    const float* tr_ln_b  = (const float*)d_in[19];
    const float* exp_w    = (const float*)d_in[20];
    const float* exp_b    = (const float*)d_in[21];
    const float* out_ln_g = (const float*)d_in[22];
    const float* out_ln_b = (const float*)d_in[23];

    float *big, *x, *w;
    cudaGetSymbolAddress((void**)&big, g_big);
    cudaGetSymbolAddress((void**)&x,   g_x);
    cudaGetSymbolAddress((void**)&w,   g_w);
    __half *Xph, *qkvh, *hh, *oh, *ph;
    __half *cwh, *nlwh, *qwh, *owh, *ewh;
    cudaGetSymbolAddress((void**)&Xph, g_Xph);
    cudaGetSymbolAddress((void**)&qkvh, g_qkvh);
    cudaGetSymbolAddress((void**)&hh,  g_hh);
    cudaGetSymbolAddress((void**)&oh,  g_oh);
    cudaGetSymbolAddress((void**)&ph,  g_ph);
    cudaGetSymbolAddress((void**)&cwh, g_cwh);
    cudaGetSymbolAddress((void**)&nlwh, g_nlwh);
    cudaGetSymbolAddress((void**)&qwh, g_qwh);
    cudaGetSymbolAddress((void**)&owh, g_owh);
    cudaGetSymbolAddress((void**)&ewh, g_ewh);

    cudaFuncSetAttribute(hmma_gemm_kernel<0, true>,
                         cudaFuncAttributeMaxDynamicSharedMemorySize, HG_SMEM);
    cudaFuncSetAttribute(hmma_gemm_kernel<0, false>,
                         cudaFuncAttributeMaxDynamicSharedMemorySize, HG_SMEM);
    cudaFuncSetAttribute(hmma_gemm256_kernel<0>,
                         cudaFuncAttributeMaxDynamicSharedMemorySize, HG2_SMEM);
    cudaFuncSetAttribute(hmma_gemm256_kernel<2>,
                         cudaFuncAttributeMaxDynamicSharedMemorySize, HG2_SMEM);
    cudaFuncSetAttribute(qk_mma_kernel,
                         cudaFuncAttributeMaxDynamicSharedMemorySize, QK_SMEM);
    cudaFuncSetAttribute(av_mma_kernel,
                         cudaFuncAttributeMaxDynamicSharedMemorySize, AV_SMEM);

    // ---- prep: stream-convert weights; no transposes ----
    split_kernel<<<DIMV * PATCHDIM / 256, 256>>>(conv_w, cwh);           // [N,K]
    extract_patches_kernel<<<ROWS * PATCHDIM / 256, 256>>>(img, Xph);
    split_kernel<<<DIMV * DIMV / 256, 256>>>(nl_w, nlwh);                // [K,N]
    split_kernel<<<DEPTH * DIMV * PATCHDIM / 256, 256>>>(wqkv, qwh);     // [K,N]
    split_kernel<<<DEPTH * DIMV * DIMV / 256, 256>>>(wo, owh);           // [K,N]
    hmma_gemm_kernel<0, true><<<dim3(DIMV/128, ROWS/128), 256, HG_SMEM>>>(
        Xph, cwh, conv_b, nullptr, x, nullptr, ROWS, DIMV, PATCHDIM);
    split_kernel<<<DIMV * PATCHDIM / 256, 256>>>(exp_w, ewh);            // [K,N]

    // ---- norm_linear + positional embedding ----
    ln_half_kernel<<<ROWS, 256>>>(x, nl_ln1_g, nl_ln1_b, hh, DIMV);
    hmma_gemm_kernel<0, false><<<dim3(DIMV/128, ROWS/128), 256, HG_SMEM>>>(
        hh, nlwh, nl_b, nullptr, x, nullptr, ROWS, DIMV, DIMV);
    ln_addpos_kernel<<<ROWS, 256>>>(x, nl_ln2_g, nl_ln2_b, sph_pos, pos_w, pos_b,
                                    x, DIMV);

    // ---- transformer layers ----
    for (int l = 0; l < DEPTH; l++) {
        ln_half_kernel<<<ROWS, 256>>>(x, ln_g + l * DIMV, ln_b + l * DIMV, hh, DIMV);
        hmma_gemm256_kernel<2><<<dim3(PATCHDIM/256, ROWS/128), 256, HG2_SMEM>>>(
            hh, qwh + (size_t)l * DIMV * PATCHDIM,
            nullptr, nullptr, nullptr, qkvh, ROWS, PATCHDIM, DIMV);
        qk_mma_kernel<<<BATCH * NHEADS, 256, QK_SMEM>>>(qkvh, sph_dist, w);
        std_softmax_kernel<<<BATCH * NTOK, 128>>>(w, ph);
        av_mma_kernel<<<BATCH * NHEADS, 256, AV_SMEM>>>(ph, qkvh, oh);
        hmma_gemm_kernel<0, false><<<dim3(DIMV/128, ROWS/128), 256, HG_SMEM>>>(
            oh, owh + (size_t)l * DIMV * DIMV,
            wo_b + l * DIMV, x, x, nullptr, ROWS, DIMV, DIMV);
    }

    // ---- final LN + expand + output LN + reassembly ----
    ln_half_kernel<<<ROWS, 256>>>(x, tr_ln_g, tr_ln_b, hh, DIMV);
    hmma_gemm256_kernel<0><<<dim3(PATCHDIM/256, ROWS/128), 256, HG2_SMEM>>>(
        hh, ewh, exp_b, nullptr, big, nullptr, ROWS, PATCHDIM, DIMV);
    ln_kernel<<<ROWS, 256>>>(big, out_ln_g, out_ln_b, big, PATCHDIM);
    reassemble_kernel<<<ROWS * PATCHDIM / 256, 256>>>(big, (float*)d_out);
}

// round 14
// speedup vs baseline: 3.5971x; 1.0430x over previous
#include <cuda_runtime.h>
#include <cuda_fp16.h>
#include <cstdint>

// ---------------------------------------------------------------------------
// SphereViT forward — pure-fp16 single-pass HMMA.
// R14: vectorized fp32->fp16 stream conversions (8 elems/thread, 16B stores).
// ---------------------------------------------------------------------------

#define BATCH     32
#define NTOK      128
#define ROWS      4096
#define DIMV      1024
#define PATCHDIM  3072
#define NHEADS    16
#define DHEAD     64
#define DEPTH     12
#define LN_EPS    1e-5f

// -------------------- scratch (device globals; no allocs) ------------------
__device__ float g_big[ROWS * PATCHDIM];
__device__ float g_x  [ROWS * DIMV];
__device__ float g_w  [BATCH * NHEADS * NTOK * NTOK];

__device__ __half g_Xph[ROWS * PATCHDIM];
__device__ __half g_qkvh[ROWS * PATCHDIM];
__device__ __half g_hh [ROWS * DIMV];
__device__ __half g_oh [ROWS * DIMV];
__device__ __half g_ph [BATCH*NHEADS*NTOK*NTOK];

// fp16 weights: conv in [N,K]; all others kept in native [K,N]
__device__ __half g_cwh[DIMV * PATCHDIM];
__device__ __half g_nlwh[DIMV * DIMV];
__device__ __half g_qwh[DEPTH * DIMV * PATCHDIM];
__device__ __half g_owh[DEPTH * DIMV * DIMV];
__device__ __half g_ewh[DIMV * PATCHDIM];

// ---------------------------------------------------------------------------
// PTX helpers
// ---------------------------------------------------------------------------
__device__ __forceinline__ uint32_t smem_u32(const void* p) {
    uint32_t a;
    asm("{ .reg .u64 t; cvta.to.shared.u64 t, %1; cvt.u32.u64 %0, t; }"
        : "=r"(a) : "l"(p));
    return a;
}
__device__ __forceinline__ void cpa16(uint32_t dst, const void* src) {
    asm volatile("cp.async.cg.shared.global [%0], [%1], 16;" :: "r"(dst), "l"(src));
}
__device__ __forceinline__ void cp_commit() { asm volatile("cp.async.commit_group;"); }
template <int NN>
__device__ __forceinline__ void cp_wait() {
    asm volatile("cp.async.wait_group %0;" :: "n"(NN));
}
__device__ __forceinline__ void ldsm4(uint32_t* r, uint32_t addr) {
    asm volatile("ldmatrix.sync.aligned.m8n8.x4.shared.b16 {%0,%1,%2,%3}, [%4];"
                 : "=r"(r[0]), "=r"(r[1]), "=r"(r[2]), "=r"(r[3]) : "r"(addr));
}
__device__ __forceinline__ void ldsm4t(uint32_t* r, uint32_t addr) {
    asm volatile("ldmatrix.sync.aligned.m8n8.x4.trans.shared.b16 {%0,%1,%2,%3}, [%4];"
                 : "=r"(r[0]), "=r"(r[1]), "=r"(r[2]), "=r"(r[3]) : "r"(addr));
}
__device__ __forceinline__ void mma16816(float* c, const uint32_t* a,
                                         const uint32_t* b) {
    asm volatile(
        "mma.sync.aligned.m16n8k16.row.col.f32.f16.f16.f32 "
        "{%0,%1,%2,%3}, {%4,%5,%6,%7}, {%8,%9}, {%0,%1,%2,%3};"
        : "+f"(c[0]), "+f"(c[1]), "+f"(c[2]), "+f"(c[3])
        : "r"(a[0]), "r"(a[1]), "r"(a[2]), "r"(a[3]), "r"(b[0]), "r"(b[1]));
}

__device__ __forceinline__ uint4 cvt8(float4 a, float4 b) {
    __half2 h0 = __halves2half2(__float2half_rn(a.x), __float2half_rn(a.y));
    __half2 h1 = __halves2half2(__float2half_rn(a.z), __float2half_rn(a.w));
    __half2 h2 = __halves2half2(__float2half_rn(b.x), __float2half_rn(b.y));
    __half2 h3 = __halves2half2(__float2half_rn(b.z), __float2half_rn(b.w));
    uint4 u;
    u.x = *(uint32_t*)&h0; u.y = *(uint32_t*)&h1;
    u.z = *(uint32_t*)&h2; u.w = *(uint32_t*)&h3;
    return u;
}

#define GLDS 40
#define A_ELEMS (128 * GLDS)             // 5120
#define BKN_LD 136                        // [32 k][128+8 n]
#define STG_ELEMS (A_ELEMS + 5120)       // 10240
#define HG_SMEM (3 * STG_ELEMS * 2)      // 61440 bytes, 3-stage

// ---------------------------------------------------------------------------
// 128x128 GEMM, 3-stage, 2 CTAs/SM.
// BT=true : B is [N,K] K-major (conv).  BT=false: B is [K,N] via ldsm.trans.
// OM: 0 = fp32 +bias +res, 2 = fp16 out.
// ---------------------------------------------------------------------------
template <int OM, bool BT>
__global__ __launch_bounds__(256, 2) void hmma_gemm_kernel(
    const __half* __restrict__ Ah, const __half* __restrict__ Bh,
    const float* __restrict__ bias, const float* __restrict__ res,
    float* __restrict__ C, __half* __restrict__ Ch, int M, int N, int K)
{
    extern __shared__ __half smem[];
    const uint32_t sbase = smem_u32(smem);
    const int tid  = threadIdx.x;
    const int lane = tid & 31, warp = tid >> 5;
    const int wm = warp & 1, wn = warp >> 1;
    const int m0 = blockIdx.y << 7, n0 = blockIdx.x << 7;

    const __half* gA = Ah + (size_t)m0 * K;
    const __half* gB = BT ? (Bh + (size_t)n0 * K) : (Bh + n0);

    const int r0c = tid >> 2, c0c = tid & 3;

    auto issue = [&](int stage, int k0) {
        uint32_t sA = sbase + (uint32_t)(stage * STG_ELEMS) * 2;
        uint32_t sB = sA + A_ELEMS * 2;
#pragma unroll
        for (int half_ = 0; half_ < 2; half_++) {
            int r = r0c + half_ * 64;
            cpa16(sA + (uint32_t)(r * GLDS + c0c * 8) * 2,
                  gA + (size_t)r * K + k0 + c0c * 8);
        }
        if (BT) {
#pragma unroll
            for (int half_ = 0; half_ < 2; half_++) {
                int r = r0c + half_ * 64;
                cpa16(sB + (uint32_t)(r * GLDS + c0c * 8) * 2,
                      gB + (size_t)r * K + k0 + c0c * 8);
            }
        } else {
#pragma unroll
            for (int p = 0; p < 2; p++) {
                int q = tid + p * 256;
                int r = q >> 4, c = q & 15;
                cpa16(sB + (uint32_t)(r * BKN_LD + c * 8) * 2,
                      gB + (size_t)(k0 + r) * N + c * 8);
            }
        }
    };

    float acc[4][4][4];
#pragma unroll
    for (int i = 0; i < 4; i++)
#pragma unroll
        for (int j = 0; j < 4; j++)
#pragma unroll
            for (int q = 0; q < 4; q++) acc[i][j][q] = 0.f;

    const int nk = K >> 5;
    issue(0, 0);  cp_commit();
    if (nk > 1) issue(1, 32);
    cp_commit();

    const int arow = wm * 64 + (lane & 15);
    const int acolb = (lane >> 4) * 8;
    const int brow = wn * 32 + ((lane >> 4) * 8) + (lane & 7);
    const int bcolb = ((lane >> 3) & 1) * 8;
    const int bjrow = lane & 15;
    const int bdcol = (lane >> 4) * 8;

    for (int it = 0; it < nk; ++it) {
        cp_wait<1>();
        __syncthreads();

        const int s = it % 3;
        uint32_t sA = sbase + (uint32_t)(s * STG_ELEMS) * 2;
        uint32_t sB = sA + A_ELEMS * 2;

#pragma unroll
        for (int ks = 0; ks < 2; ks++) {
            const int acol = ks * 16 + acolb;
            uint32_t ah[4][4], bh[4][2];
#pragma unroll
            for (int mi = 0; mi < 4; mi++)
                ldsm4(ah[mi], sA + (uint32_t)((arow + mi * 16) * GLDS + acol) * 2);
            if (BT) {
                const int bcol = ks * 16 + bcolb;
#pragma unroll
                for (int gp = 0; gp < 2; gp++) {
                    uint32_t rh[4];
                    ldsm4(rh, sB + (uint32_t)((brow + gp * 16) * GLDS + bcol) * 2);
                    bh[gp*2][0] = rh[0]; bh[gp*2][1] = rh[1];
                    bh[gp*2+1][0] = rh[2]; bh[gp*2+1][1] = rh[3];
                }
            } else {
#pragma unroll
                for (int gp = 0; gp < 2; gp++) {
                    uint32_t rh[4];
                    uint32_t off = (uint32_t)((ks * 16 + bjrow) * BKN_LD
                                              + wn * 32 + gp * 16 + bdcol) * 2;
                    ldsm4t(rh, sB + off);
                    bh[gp*2][0] = rh[0]; bh[gp*2][1] = rh[1];
                    bh[gp*2+1][0] = rh[2]; bh[gp*2+1][1] = rh[3];
                }
            }
#pragma unroll
            for (int mi = 0; mi < 4; mi++)
#pragma unroll
                for (int nj = 0; nj < 4; nj++)
                    mma16816(acc[mi][nj], ah[mi], bh[nj]);
        }

        if (it + 2 < nk) issue((it + 2) % 3, (it + 2) << 5);
        cp_commit();
    }

#pragma unroll
    for (int mi = 0; mi < 4; mi++) {
        int r0 = m0 + wm * 64 + mi * 16 + (lane >> 2);
#pragma unroll
        for (int nj = 0; nj < 4; nj++) {
            int c = n0 + wn * 32 + nj * 8 + (lane & 3) * 2;
            float v0x = acc[mi][nj][0], v0y = acc[mi][nj][1];
            float v1x = acc[mi][nj][2], v1y = acc[mi][nj][3];
            size_t o0 = (size_t)r0 * N + c;
            size_t o1 = o0 + (size_t)8 * N;
            if (OM == 2) {
                *(__half2*)(Ch + o0) =
                    __halves2half2(__float2half_rn(v0x), __float2half_rn(v0y));
                *(__half2*)(Ch + o1) =
                    __halves2half2(__float2half_rn(v1x), __float2half_rn(v1y));
            } else {
                if (bias) {
                    float bx = bias[c], by = bias[c + 1];
                    v0x += bx; v0y += by; v1x += bx; v1y += by;
                }
                if (res) {
                    float2 ra = *(const float2*)(res + o0);
                    float2 rb = *(const float2*)(res + o1);
                    v0x += ra.x; v0y += ra.y; v1x += rb.x; v1y += rb.y;
                }
                *(float2*)(C + o0) = make_float2(v0x, v0y);
                *(float2*)(C + o1) = make_float2(v1x, v1y);
            }
        }
    }
}

// ---------------------------------------------------------------------------
// 128x256 GEMM, 4-stage, 1 CTA/SM, B in [K,N] via ldsm.trans.
// ---------------------------------------------------------------------------
#define BKN2_LD 264
#define BF2_ELEMS (32 * BKN2_LD)
#define STG2_ELEMS (A_ELEMS + BF2_ELEMS)
#define HG2_SMEM (4 * STG2_ELEMS * 2)    // 108544 bytes

template <int OM>
__global__ __launch_bounds__(256, 1) void hmma_gemm256_kernel(
    const __half* __restrict__ Ah, const __half* __restrict__ Bh,
    const float* __restrict__ bias, const float* __restrict__ res,
    float* __restrict__ C, __half* __restrict__ Ch, int M, int N, int K)
{
    extern __shared__ __half smem[];
    const uint32_t sbase = smem_u32(smem);
    const int tid  = threadIdx.x;
    const int lane = tid & 31, warp = tid >> 5;
    const int wm = warp & 1, wn = warp >> 1;
    const int m0 = blockIdx.y << 7, n0 = blockIdx.x << 8;

    const __half* gA = Ah + (size_t)m0 * K;
    const __half* gB = Bh + n0;

    const int r0c = tid >> 2, c0c = tid & 3;

    auto issue = [&](int stage, int k0) {
        uint32_t sA = sbase + (uint32_t)(stage * STG2_ELEMS) * 2;
        uint32_t sB = sA + A_ELEMS * 2;
#pragma unroll
        for (int half_ = 0; half_ < 2; half_++) {
            int r = r0c + half_ * 64;
            cpa16(sA + (uint32_t)(r * GLDS + c0c * 8) * 2,
                  gA + (size_t)r * K + k0 + c0c * 8);
        }
#pragma unroll
        for (int p = 0; p < 4; p++) {
            int q = tid + p * 256;
            int r = q >> 5, c = q & 31;
            cpa16(sB + (uint32_t)(r * BKN2_LD + c * 8) * 2,
                  gB + (size_t)(k0 + r) * N + c * 8);
        }
    };

    float acc[4][8][4];
#pragma unroll
    for (int i = 0; i < 4; i++)
#pragma unroll
        for (int j = 0; j < 8; j++)
#pragma unroll
            for (int q = 0; q < 4; q++) acc[i][j][q] = 0.f;

    const int nk = K >> 5;
    issue(0, 0);              cp_commit();
    if (nk > 1) issue(1, 32); cp_commit();
    if (nk > 2) issue(2, 64); cp_commit();

    const int arow = wm * 64 + (lane & 15);
    const int acolb = (lane >> 4) * 8;
    const int bjrow = lane & 15;
    const int bdcol = (lane >> 4) * 8;

    for (int it = 0; it < nk; ++it) {
        cp_wait<2>();
        __syncthreads();

        const int s = it & 3;
        uint32_t sA = sbase + (uint32_t)(s * STG2_ELEMS) * 2;
        uint32_t sB = sA + A_ELEMS * 2;

#pragma unroll
        for (int ks = 0; ks < 2; ks++) {
            const int acol = ks * 16 + acolb;
            uint32_t ah[4][4], bh[8][2];
#pragma unroll
            for (int mi = 0; mi < 4; mi++)
                ldsm4(ah[mi], sA + (uint32_t)((arow + mi * 16) * GLDS + acol) * 2);
#pragma unroll
            for (int gp = 0; gp < 4; gp++) {
                uint32_t rh[4];
                uint32_t off = (uint32_t)((ks * 16 + bjrow) * BKN2_LD
                                          + wn * 64 + gp * 16 + bdcol) * 2;
                ldsm4t(rh, sB + off);
                bh[gp*2][0] = rh[0]; bh[gp*2][1] = rh[1];
                bh[gp*2+1][0] = rh[2]; bh[gp*2+1][1] = rh[3];
            }
#pragma unroll
            for (int mi = 0; mi < 4; mi++)
#pragma unroll
                for (int nj = 0; nj < 8; nj++)
                    mma16816(acc[mi][nj], ah[mi], bh[nj]);
        }

        if (it + 3 < nk) issue((it + 3) & 3, (it + 3) << 5);
        cp_commit();
    }

#pragma unroll
    for (int mi = 0; mi < 4; mi++) {
        int r0 = m0 + wm * 64 + mi * 16 + (lane >> 2);
#pragma unroll
        for (int nj = 0; nj < 8; nj++) {
            int c = n0 + wn * 64 + nj * 8 + (lane & 3) * 2;
            float v0x = acc[mi][nj][0], v0y = acc[mi][nj][1];
            float v1x = acc[mi][nj][2], v1y = acc[mi][nj][3];
            size_t o0 = (size_t)r0 * N + c;
            size_t o1 = o0 + (size_t)8 * N;
            if (OM == 2) {
                *(__half2*)(Ch + o0) =
                    __halves2half2(__float2half_rn(v0x), __float2half_rn(v0y));
                *(__half2*)(Ch + o1) =
                    __halves2half2(__float2half_rn(v1x), __float2half_rn(v1y));
            } else {
                if (bias) {
                    float bx = bias[c], by = bias[c + 1];
                    v0x += bx; v0y += by; v1x += bx; v1y += by;
                }
                if (res) {
                    float2 ra = *(const float2*)(res + o0);
                    float2 rb = *(const float2*)(res + o1);
                    v0x += ra.x; v0y += ra.y; v1x += rb.x; v1y += rb.y;
                }
                *(float2*)(C + o0) = make_float2(v0x, v0y);
                *(float2*)(C + o1) = make_float2(v1x, v1y);
            }
        }
    }
}

// ---------------------------------------------------------------------------
// qk via HMMA: W = (qh_i . kh_j)*0.125*(1+dist). CTA per (b,h).
// ---------------------------------------------------------------------------
#define QKLD 72
#define QK_TILE (128 * QKLD)
#define QK_SMEM (2 * QK_TILE * 2)

__global__ __launch_bounds__(256, 2) void qk_mma_kernel(
    const __half* __restrict__ qkvh,
    const float* __restrict__ dist, float* __restrict__ W)
{
    extern __shared__ __half smem[];
    const uint32_t sbase = smem_u32(smem);
    const int tid = threadIdx.x, lane = tid & 31, warp = tid >> 5;
    const int wm = warp & 1, wn = warp >> 1;
    const int b = blockIdx.x >> 4, h = blockIdx.x & 15;
    const size_t rowbase = (size_t)b * NTOK * PATCHDIM + h * DHEAD;

    const int offs[2] = { 0, DIMV };
#pragma unroll
    for (int t = 0; t < 2; t++) {
        uint32_t dbase = sbase + (uint32_t)(t * QK_TILE) * 2;
#pragma unroll
        for (int p = 0; p < 4; p++) {
            int q = tid + p * 256;
            int r = q >> 3, c = q & 7;
            cpa16(dbase + (uint32_t)(r * QKLD + c * 8) * 2,
                  qkvh + rowbase + (size_t)r * PATCHDIM + offs[t] + c * 8);
        }
    }
    cp_commit();
    cp_wait<0>();
    __syncthreads();

    float acc[4][4][4];
#pragma unroll
    for (int i = 0; i < 4; i++)
#pragma unroll
        for (int j = 0; j < 4; j++)
#pragma unroll
            for (int q = 0; q < 4; q++) acc[i][j][q] = 0.f;

    uint32_t sA  = sbase;
    uint32_t sB  = sbase + (uint32_t)QK_TILE * 2;
    const int arow = wm * 64 + (lane & 15);
    const int acolb = (lane >> 4) * 8;
    const int brow = wn * 32 + ((lane >> 4) * 8) + (lane & 7);
    const int bcolb = ((lane >> 3) & 1) * 8;

#pragma unroll
    for (int ks = 0; ks < 4; ks++) {
        const int acol = ks * 16 + acolb;
        const int bcol = ks * 16 + bcolb;
        uint32_t ah[4][4], bh[4][2];
#pragma unroll
        for (int mi = 0; mi < 4; mi++)
            ldsm4(ah[mi], sA + (uint32_t)((arow + mi * 16) * QKLD + acol) * 2);
#pragma unroll
        for (int gp = 0; gp < 2; gp++) {
            uint32_t rh[4];
            ldsm4(rh, sB + (uint32_t)((brow + gp * 16) * QKLD + bcol) * 2);
            bh[gp*2][0] = rh[0]; bh[gp*2][1] = rh[1];
            bh[gp*2+1][0] = rh[2]; bh[gp*2+1][1] = rh[3];
        }
#pragma unroll
        for (int mi = 0; mi < 4; mi++)
#pragma unroll
            for (int nj = 0; nj < 4; nj++)
                mma16816(acc[mi][nj], ah[mi], bh[nj]);
    }

    float* Wb = W + (size_t)blockIdx.x * (NTOK * NTOK);
#pragma unroll
    for (int mi = 0; mi < 4; mi++) {
        int i0 = wm * 64 + mi * 16 + (lane >> 2);
#pragma unroll
        for (int nj = 0; nj < 4; nj++) {
            int j0 = wn * 32 + nj * 8 + (lane & 3) * 2;
#pragma unroll
            for (int rr = 0; rr < 2; rr++) {
                int i = i0 + rr * 8;
                float vx = acc[mi][nj][rr*2], vy = acc[mi][nj][rr*2+1];
                Wb[i * 128 + j0]     = vx * 0.125f * (1.0f + dist[i * 128 + j0]);
                Wb[i * 128 + j0 + 1] = vy * 0.125f * (1.0f + dist[i * 128 + j0 + 1]);
            }
        }
    }
}

// ---------------------------------------------------------------------------
// Cross-head standardize (ddof=1) + softmax; emits fp16 P.
// ---------------------------------------------------------------------------
__global__ __launch_bounds__(128) void std_softmax_kernel(
    const float* __restrict__ W, __half* __restrict__ Ph)
{
    int b = blockIdx.x >> 7, i = blockIdx.x & 127;
    int j = threadIdx.x;
    __shared__ float sm[NHEADS][128];

    size_t base = (size_t)b * (NHEADS * NTOK * NTOK) + (size_t)i * 128 + j;
    float vals[NHEADS];
    float s = 0.f;
#pragma unroll
    for (int h = 0; h < NHEADS; h++) {
        float v = W[base + (size_t)h * (NTOK * NTOK)];
        vals[h] = v; s += v;
    }
    float mu = s * (1.0f / 16.0f);
    float d2 = 0.f;
#pragma unroll
    for (int h = 0; h < NHEADS; h++) {
        float d = vals[h] - mu;
        d2 += d * d;
    }
    float inv = rsqrtf(d2 * (1.0f / 15.0f));
#pragma unroll
    for (int h = 0; h < NHEADS; h++) sm[h][j] = (vals[h] - mu) * inv;
    __syncthreads();

    int warp = j >> 5, lane = j & 31;
#pragma unroll
    for (int r = 0; r < 4; r++) {
        int h = warp * 4 + r;
        float v0 = sm[h][lane], v1 = sm[h][lane + 32];
        float v2 = sm[h][lane + 64], v3 = sm[h][lane + 96];
        float m = fmaxf(fmaxf(v0, v1), fmaxf(v2, v3));
#pragma unroll
        for (int o = 16; o; o >>= 1) m = fmaxf(m, __shfl_xor_sync(0xffffffffu, m, o));
        float e0 = expf(v0 - m), e1 = expf(v1 - m);
        float e2 = expf(v2 - m), e3 = expf(v3 - m);
        float sum = e0 + e1 + e2 + e3;
#pragma unroll
        for (int o = 16; o; o >>= 1) sum += __shfl_xor_sync(0xffffffffu, sum, o);
        float rs = 1.0f / sum;
        size_t wb = (size_t)b * (NHEADS * NTOK * NTOK) + (size_t)h * (NTOK * NTOK)
                  + (size_t)i * 128;
        Ph[wb + lane]      = __float2half_rn(e0 * rs);
        Ph[wb + lane + 32] = __float2half_rn(e1 * rs);
        Ph[wb + lane + 64] = __float2half_rn(e2 * rs);
        Ph[wb + lane + 96] = __float2half_rn(e3 * rs);
    }
}

// ---------------------------------------------------------------------------
// av via HMMA: O[i,h*64+d] = sum_j Ph[i,j]*Vh[j,d]. CTA per (b,h).
// ---------------------------------------------------------------------------
#define AVPLD 136
#define AVVLD 72
#define AVP_TILE (128 * AVPLD)
#define AVV_TILE (128 * AVVLD)
#define AV_SMEM ((AVP_TILE + AVV_TILE) * 2)

__global__ __launch_bounds__(256, 2) void av_mma_kernel(
    const __half* __restrict__ Ph, const __half* __restrict__ qkvh,
    __half* __restrict__ Oh)
{
    extern __shared__ __half smem[];
    const uint32_t sbase = smem_u32(smem);
    const int tid = threadIdx.x, lane = tid & 31, warp = tid >> 5;
    const int wm = warp & 3, wn = warp >> 2;
    const int b = blockIdx.x >> 4, h = blockIdx.x & 15;
    const size_t pbase = (size_t)blockIdx.x * (NTOK * NTOK);
    const size_t vbase = (size_t)b * NTOK * PATCHDIM + 2 * DIMV + h * DHEAD;

#pragma unroll
    for (int p = 0; p < 8; p++) {
        int q = tid + p * 256;
        int r = q >> 4, c = q & 15;
        cpa16(sbase + (uint32_t)(r * AVPLD + c * 8) * 2,
              Ph + pbase + (size_t)r * 128 + c * 8);
    }
    {
        uint32_t dbase = sbase + (uint32_t)AVP_TILE * 2;
#pragma unroll
        for (int p = 0; p < 4; p++) {
            int q = tid + p * 256;
            int j = q >> 3, c = q & 7;
            cpa16(dbase + (uint32_t)(j * AVVLD + c * 8) * 2,
                  qkvh + vbase + (size_t)j * PATCHDIM + c * 8);
        }
    }
    cp_commit();
    cp_wait<0>();
    __syncthreads();

    float acc[2][4][4];
#pragma unroll
    for (int i = 0; i < 2; i++)
#pragma unroll
        for (int j = 0; j < 4; j++)
#pragma unroll
            for (int q = 0; q < 4; q++) acc[i][j][q] = 0.f;

    uint32_t sA  = sbase;
    uint32_t sB  = sbase + (uint32_t)AVP_TILE * 2;
    const int arow = wm * 32 + (lane & 15);
    const int acolb = (lane >> 4) * 8;
    const int bjrow = lane & 15;
    const int bdcol = (lane >> 4) * 8;

#pragma unroll
    for (int kc = 0; kc < 8; kc++) {
        const int acol = kc * 16 + acolb;
        uint32_t ah[2][4], bh[4][2];
#pragma unroll
        for (int mi = 0; mi < 2; mi++)
            ldsm4(ah[mi], sA + (uint32_t)((arow + mi * 16) * AVPLD + acol) * 2);
#pragma unroll
        for (int gp = 0; gp < 2; gp++) {
            uint32_t rh[4];
            uint32_t off = (uint32_t)((kc * 16 + bjrow) * AVVLD
                                      + wn * 32 + gp * 16 + bdcol) * 2;
            ldsm4t(rh, sB + off);
            bh[gp*2][0] = rh[0]; bh[gp*2][1] = rh[1];
            bh[gp*2+1][0] = rh[2]; bh[gp*2+1][1] = rh[3];
        }
#pragma unroll
        for (int mi = 0; mi < 2; mi++)
#pragma unroll
            for (int nj = 0; nj < 4; nj++)
                mma16816(acc[mi][nj], ah[mi], bh[nj]);
    }

#pragma unroll
    for (int mi = 0; mi < 2; mi++) {
        int i0 = wm * 32 + mi * 16 + (lane >> 2);
#pragma unroll
        for (int nj = 0; nj < 4; nj++) {
            int d0 = wn * 32 + nj * 8 + (lane & 3) * 2;
#pragma unroll
            for (int rr = 0; rr < 2; rr++) {
                int i = i0 + rr * 8;
                size_t o = (size_t)(b * 128 + i) * DIMV + h * DHEAD + d0;
                *(__half2*)(Oh + o) =
                    __halves2half2(__float2half_rn(acc[mi][nj][rr*2]),
                                   __float2half_rn(acc[mi][nj][rr*2 + 1]));
            }
        }
    }
}

// ---------------------------------------------------------------------------
// Vectorized weight prep: 8 elems/thread, 16B stores.
// ---------------------------------------------------------------------------
__global__ void split8_kernel(const float4* __restrict__ X, uint4* __restrict__ H) {
    size_t i = (size_t)blockIdx.x * 256 + threadIdx.x;
    float4 a = X[i * 2], b = X[i * 2 + 1];
    H[i] = cvt8(a, b);
}

__global__ void extract_patches8_kernel(const float* __restrict__ img,
                                        uint4* __restrict__ H) {
    int i = blockIdx.x * 256 + threadIdx.x;     // 8-elem chunk index
    int idx = i * 8;
    int col = idx % PATCHDIM;
    int row = idx / PATCHDIM;
    int b = row >> 7, t = row & 127;
    int h = t >> 4, w = t & 15;
    int c = col >> 10, r = col & 1023;
    int p = r >> 5, q = r & 31;                 // q multiple of 8
    const float* src = img + (((size_t)b * 3 + c) * 256 + h * 32 + p) * 512
                           + w * 32 + q;
    float4 a = *(const float4*)(src);
    float4 bb = *(const float4*)(src + 4);
    H[i] = cvt8(a, bb);
}

// ---------------------------------------------------------------------------
// LayerNorm
// ---------------------------------------------------------------------------
__device__ __forceinline__ void ln_stats(const float* __restrict__ x, size_t base,
                                         int D, float& mu, float& rstd) {
    float s = 0.f, ss = 0.f;
    for (int i = threadIdx.x; i < D; i += 256) {
        float v = x[base + i];
        s += v; ss += v * v;
    }
#pragma unroll
    for (int o = 16; o; o >>= 1) {
        s  += __shfl_xor_sync(0xffffffffu, s, o);
        ss += __shfl_xor_sync(0xffffffffu, ss, o);
    }
    __shared__ float sh[2][8];
    int w = threadIdx.x >> 5;
    if ((threadIdx.x & 31) == 0) { sh[0][w] = s; sh[1][w] = ss; }
    __syncthreads();
    if (threadIdx.x < 32) {
        s  = (threadIdx.x < 8) ? sh[0][threadIdx.x] : 0.f;
        ss = (threadIdx.x < 8) ? sh[1][threadIdx.x] : 0.f;
#pragma unroll
        for (int o = 4; o; o >>= 1) {
            s  += __shfl_xor_sync(0xffffffffu, s, o);
            ss += __shfl_xor_sync(0xffffffffu, ss, o);
        }
        if (threadIdx.x == 0) { sh[0][0] = s; sh[1][0] = ss; }
    }
    __syncthreads();
    s = sh[0][0]; ss = sh[1][0];
    float invD = 1.0f / (float)D;
    mu = s * invD;
    float var = ss * invD - mu * mu;
    rstd = rsqrtf(var + LN_EPS);
}

__global__ void ln_kernel(const float* __restrict__ x, const float* __restrict__ g,
                          const float* __restrict__ beta, float* __restrict__ y, int D) {
    size_t base = (size_t)blockIdx.x * D;
    float mu, rstd;
    ln_stats(x, base, D, mu, rstd);
    for (int i = threadIdx.x; i < D; i += 256)
        y[base + i] = (x[base + i] - mu) * rstd * g[i] + beta[i];
}

__global__ void ln_addpos_kernel(const float* __restrict__ x, const float* __restrict__ g,
                                 const float* __restrict__ beta,
                                 const float* __restrict__ sph_pos,
                                 const float* __restrict__ pos_w,
                                 const float* __restrict__ pos_b,
                                 float* __restrict__ y, int D) {
    size_t base = (size_t)blockIdx.x * D;
    float mu, rstd;
    ln_stats(x, base, D, mu, rstd);
    int tok = blockIdx.x & 127;
    float p0 = sph_pos[tok * 2], p1 = sph_pos[tok * 2 + 1];
    for (int i = threadIdx.x; i < D; i += 256) {
        float v = (x[base + i] - mu) * rstd * g[i] + beta[i];
        y[base + i] = v + p0 * pos_w[i] + p1 * pos_w[1024 + i] + pos_b[i];
    }
}

__global__ void ln_half_kernel(const float* __restrict__ x, const float* __restrict__ g,
                               const float* __restrict__ beta,
                               __half* __restrict__ H, int D) {
    size_t base = (size_t)blockIdx.x * D;
    float mu, rstd;
    ln_stats(x, base, D, mu, rstd);
    for (int i = threadIdx.x; i < D; i += 256) {
        float v = (x[base + i] - mu) * rstd * g[i] + beta[i];
        H[base + i] = __float2half_rn(v);
    }
}

__global__ void reassemble_kernel(const float* __restrict__ Y, float* __restrict__ out) {
    int idx = blockIdx.x * 256 + threadIdx.x;
    int xq = idx & 511;
    int rest = idx >> 9;
    int yr = rest & 255;
    rest >>= 8;
    int c = rest % 3;
    int b = rest / 3;
    int h = yr >> 5, p1 = yr & 31, w = xq >> 5, p2 = xq & 31;
    out[idx] = Y[(size_t)(b * 128 + h * 16 + w) * PATCHDIM + (p1 * 32 + p2) * 3 + c];
}

// ---------------------------------------------------------------------------
// Host launcher
// ---------------------------------------------------------------------------
extern "C" void kernel_launch(void* const* d_in, const int* in_sizes, int n_in,
                              void* d_out, int out_size)
{
    const float* img      = (const float*)d_in[0];
    const float* sph_pos  = (const float*)d_in[1];
    const float* sph_dist = (const float*)d_in[2];
    const float* conv_w   = (const float*)d_in[3];
    const float* conv_b   = (const float*)d_in[4];
    const float* nl_ln1_g = (const float*)d_in[5];
    const float* nl_ln1_b = (const float*)d_in[6];
    const float* nl_w     = (const float*)d_in[7];
    const float* nl_b     = (const float*)d_in[8];
    const float* nl_ln2_g = (const float*)d_in[9];
    const float* nl_ln2_b = (const float*)d_in[10];
    const float* pos_w    = (const float*)d_in[11];
    const float* pos_b    = (const float*)d_in[12];
    const float* ln_g     = (const float*)d_in[13];
    const float* ln_b     = (const float*)d_in[14];
    const float* wqkv     = (const float*)d_in[15];
    const float* wo       = (const float*)d_in[16];
    const float* wo_b     = (const float*)d_in[17];
    const float* tr_ln_g  = (const float*)d_in[18];
    const float* tr_ln_b  = (const float*)d_in[19];
    const float* exp_w    = (const float*)d_in[20];
    const float* exp_b    = (const float*)d_in[21];
    const float* out_ln_g = (const float*)d_in[22];
    const float* out_ln_b = (const float*)d_in[23];

    float *big, *x, *w;
    cudaGetSymbolAddress((void**)&big, g_big);
    cudaGetSymbolAddress((void**)&x,   g_x);
    cudaGetSymbolAddress((void**)&w,   g_w);
    __half *Xph, *qkvh, *hh, *oh, *ph;
    __half *cwh, *nlwh, *qwh, *owh, *ewh;
    cudaGetSymbolAddress((void**)&Xph, g_Xph);
    cudaGetSymbolAddress((void**)&qkvh, g_qkvh);
    cudaGetSymbolAddress((void**)&hh,  g_hh);
    cudaGetSymbolAddress((void**)&oh,  g_oh);
    cudaGetSymbolAddress((void**)&ph,  g_ph);
    cudaGetSymbolAddress((void**)&cwh, g_cwh);
    cudaGetSymbolAddress((void**)&nlwh, g_nlwh);
    cudaGetSymbolAddress((void**)&qwh, g_qwh);
    cudaGetSymbolAddress((void**)&owh, g_owh);
    cudaGetSymbolAddress((void**)&ewh, g_ewh);

    cudaFuncSetAttribute(hmma_gemm_kernel<0, true>,
                         cudaFuncAttributeMaxDynamicSharedMemorySize, HG_SMEM);
    cudaFuncSetAttribute(hmma_gemm_kernel<0, false>,
                         cudaFuncAttributeMaxDynamicSharedMemorySize, HG_SMEM);
    cudaFuncSetAttribute(hmma_gemm256_kernel<0>,
                         cudaFuncAttributeMaxDynamicSharedMemorySize, HG2_SMEM);
    cudaFuncSetAttribute(hmma_gemm256_kernel<2>,
                         cudaFuncAttributeMaxDynamicSharedMemorySize, HG2_SMEM);
    cudaFuncSetAttribute(qk_mma_kernel,
                         cudaFuncAttributeMaxDynamicSharedMemorySize, QK_SMEM);
    cudaFuncSetAttribute(av_mma_kernel,
                         cudaFuncAttributeMaxDynamicSharedMemorySize, AV_SMEM);

    // ---- prep: vectorized stream conversions ----
    split8_kernel<<<DIMV * PATCHDIM / 2048, 256>>>((const float4*)conv_w, (uint4*)cwh);
    extract_patches8_kernel<<<ROWS * PATCHDIM / 2048, 256>>>(img, (uint4*)Xph);
    split8_kernel<<<DIMV * DIMV / 2048, 256>>>((const float4*)nl_w, (uint4*)nlwh);
    split8_kernel<<<DEPTH * DIMV * PATCHDIM / 2048, 256>>>((const float4*)wqkv, (uint4*)qwh);
    split8_kernel<<<DEPTH * DIMV * DIMV / 2048, 256>>>((const float4*)wo, (uint4*)owh);
    hmma_gemm_kernel<0, true><<<dim3(DIMV/128, ROWS/128), 256, HG_SMEM>>>(
        Xph, cwh, conv_b, nullptr, x, nullptr, ROWS, DIMV, PATCHDIM);
    split8_kernel<<<DIMV * PATCHDIM / 2048, 256>>>((const float4*)exp_w, (uint4*)ewh);

    // ---- norm_linear + positional embedding ----
    ln_half_kernel<<<ROWS, 256>>>(x, nl_ln1_g, nl_ln1_b, hh, DIMV);
    hmma_gemm_kernel<0, false><<<dim3(DIMV/128, ROWS/128), 256, HG_SMEM>>>(
        hh, nlwh, nl_b, nullptr, x, nullptr, ROWS, DIMV, DIMV);
    ln_addpos_kernel<<<ROWS, 256>>>(x, nl_ln2_g, nl_ln2_b, sph_pos, pos_w, pos_b,
                                    x, DIMV);

    // ---- transformer layers ----
    for (int l = 0; l < DEPTH; l++) {
        ln_half_kernel<<<ROWS, 256>>>(x, ln_g + l * DIMV, ln_b + l * DIMV, hh, DIMV);
        hmma_gemm256_kernel<2><<<dim3(PATCHDIM/256, ROWS/128), 256, HG2_SMEM>>>(
            hh, qwh + (size_t)l * DIMV * PATCHDIM,
            nullptr, nullptr, nullptr, qkvh, ROWS, PATCHDIM, DIMV);
        qk_mma_kernel<<<BATCH * NHEADS, 256, QK_SMEM>>>(qkvh, sph_dist, w);
        std_softmax_kernel<<<BATCH * NTOK, 128>>>(w, ph);
        av_mma_kernel<<<BATCH * NHEADS, 256, AV_SMEM>>>(ph, qkvh, oh);
        hmma_gemm_kernel<0, false><<<dim3(DIMV/128, ROWS/128), 256, HG_SMEM>>>(
            oh, owh + (size_t)l * DIMV * DIMV,
            wo_b + l * DIMV, x, x, nullptr, ROWS, DIMV, DIMV);
    }

    // ---- final LN + expand + output LN + reassembly ----
    ln_half_kernel<<<ROWS, 256>>>(x, tr_ln_g, tr_ln_b, hh, DIMV);
    hmma_gemm256_kernel<0><<<dim3(PATCHDIM/256, ROWS/128), 256, HG2_SMEM>>>(
        hh, ewh, exp_b, nullptr, big, nullptr, ROWS, PATCHDIM, DIMV);
    ln_kernel<<<ROWS, 256>>>(big, out_ln_g, out_ln_b, big, PATCHDIM);
    reassemble_kernel<<<ROWS * PATCHDIM / 256, 256>>>(big, (float*)d_out);
}

// round 15
// speedup vs baseline: 3.6832x; 1.0239x over previous
#include <cuda_runtime.h>
#include <cuda_fp16.h>
#include <cstdint>

// ---------------------------------------------------------------------------
// SphereViT forward — pure-fp16 single-pass HMMA.
// R15: register-cached single-read LayerNorms (vectorized), smem-staged
//      reassemble (coalesced writes, conflict-free smem gather).
// ---------------------------------------------------------------------------

#define BATCH     32
#define NTOK      128
#define ROWS      4096
#define DIMV      1024
#define PATCHDIM  3072
#define NHEADS    16
#define DHEAD     64
#define DEPTH     12
#define LN_EPS    1e-5f

// -------------------- scratch (device globals; no allocs) ------------------
__device__ float g_big[ROWS * PATCHDIM];
__device__ float g_x  [ROWS * DIMV];
__device__ float g_w  [BATCH * NHEADS * NTOK * NTOK];

__device__ __half g_Xph[ROWS * PATCHDIM];
__device__ __half g_qkvh[ROWS * PATCHDIM];
__device__ __half g_hh [ROWS * DIMV];
__device__ __half g_oh [ROWS * DIMV];
__device__ __half g_ph [BATCH*NHEADS*NTOK*NTOK];

// fp16 weights: conv in [N,K]; all others kept in native [K,N]
__device__ __half g_cwh[DIMV * PATCHDIM];
__device__ __half g_nlwh[DIMV * DIMV];
__device__ __half g_qwh[DEPTH * DIMV * PATCHDIM];
__device__ __half g_owh[DEPTH * DIMV * DIMV];
__device__ __half g_ewh[DIMV * PATCHDIM];

// ---------------------------------------------------------------------------
// PTX helpers
// ---------------------------------------------------------------------------
__device__ __forceinline__ uint32_t smem_u32(const void* p) {
    uint32_t a;
    asm("{ .reg .u64 t; cvta.to.shared.u64 t, %1; cvt.u32.u64 %0, t; }"
        : "=r"(a) : "l"(p));
    return a;
}
__device__ __forceinline__ void cpa16(uint32_t dst, const void* src) {
    asm volatile("cp.async.cg.shared.global [%0], [%1], 16;" :: "r"(dst), "l"(src));
}
__device__ __forceinline__ void cp_commit() { asm volatile("cp.async.commit_group;"); }
template <int NN>
__device__ __forceinline__ void cp_wait() {
    asm volatile("cp.async.wait_group %0;" :: "n"(NN));
}
__device__ __forceinline__ void ldsm4(uint32_t* r, uint32_t addr) {
    asm volatile("ldmatrix.sync.aligned.m8n8.x4.shared.b16 {%0,%1,%2,%3}, [%4];"
                 : "=r"(r[0]), "=r"(r[1]), "=r"(r[2]), "=r"(r[3]) : "r"(addr));
}
__device__ __forceinline__ void ldsm4t(uint32_t* r, uint32_t addr) {
    asm volatile("ldmatrix.sync.aligned.m8n8.x4.trans.shared.b16 {%0,%1,%2,%3}, [%4];"
                 : "=r"(r[0]), "=r"(r[1]), "=r"(r[2]), "=r"(r[3]) : "r"(addr));
}
__device__ __forceinline__ void mma16816(float* c, const uint32_t* a,
                                         const uint32_t* b) {
    asm volatile(
        "mma.sync.aligned.m16n8k16.row.col.f32.f16.f16.f32 "
        "{%0,%1,%2,%3}, {%4,%5,%6,%7}, {%8,%9}, {%0,%1,%2,%3};"
        : "+f"(c[0]), "+f"(c[1]), "+f"(c[2]), "+f"(c[3])
        : "r"(a[0]), "r"(a[1]), "r"(a[2]), "r"(a[3]), "r"(b[0]), "r"(b[1]));
}

__device__ __forceinline__ uint4 cvt8(float4 a, float4 b) {
    __half2 h0 = __halves2half2(__float2half_rn(a.x), __float2half_rn(a.y));
    __half2 h1 = __halves2half2(__float2half_rn(a.z), __float2half_rn(a.w));
    __half2 h2 = __halves2half2(__float2half_rn(b.x), __float2half_rn(b.y));
    __half2 h3 = __halves2half2(__float2half_rn(b.z), __float2half_rn(b.w));
    uint4 u;
    u.x = *(uint32_t*)&h0; u.y = *(uint32_t*)&h1;
    u.z = *(uint32_t*)&h2; u.w = *(uint32_t*)&h3;
    return u;
}

#define GLDS 40
#define A_ELEMS (128 * GLDS)             // 5120
#define BKN_LD 136                        // [32 k][128+8 n]
#define STG_ELEMS (A_ELEMS + 5120)       // 10240
#define HG_SMEM (3 * STG_ELEMS * 2)      // 61440 bytes, 3-stage

// ---------------------------------------------------------------------------
// 128x128 GEMM, 3-stage, 2 CTAs/SM.
// ---------------------------------------------------------------------------
template <int OM, bool BT>
__global__ __launch_bounds__(256, 2) void hmma_gemm_kernel(
    const __half* __restrict__ Ah, const __half* __restrict__ Bh,
    const float* __restrict__ bias, const float* __restrict__ res,
    float* __restrict__ C, __half* __restrict__ Ch, int M, int N, int K)
{
    extern __shared__ __half smem[];
    const uint32_t sbase = smem_u32(smem);
    const int tid  = threadIdx.x;
    const int lane = tid & 31, warp = tid >> 5;
    const int wm = warp & 1, wn = warp >> 1;
    const int m0 = blockIdx.y << 7, n0 = blockIdx.x << 7;

    const __half* gA = Ah + (size_t)m0 * K;
    const __half* gB = BT ? (Bh + (size_t)n0 * K) : (Bh + n0);

    const int r0c = tid >> 2, c0c = tid & 3;

    auto issue = [&](int stage, int k0) {
        uint32_t sA = sbase + (uint32_t)(stage * STG_ELEMS) * 2;
        uint32_t sB = sA + A_ELEMS * 2;
#pragma unroll
        for (int half_ = 0; half_ < 2; half_++) {
            int r = r0c + half_ * 64;
            cpa16(sA + (uint32_t)(r * GLDS + c0c * 8) * 2,
                  gA + (size_t)r * K + k0 + c0c * 8);
        }
        if (BT) {
#pragma unroll
            for (int half_ = 0; half_ < 2; half_++) {
                int r = r0c + half_ * 64;
                cpa16(sB + (uint32_t)(r * GLDS + c0c * 8) * 2,
                      gB + (size_t)r * K + k0 + c0c * 8);
            }
        } else {
#pragma unroll
            for (int p = 0; p < 2; p++) {
                int q = tid + p * 256;
                int r = q >> 4, c = q & 15;
                cpa16(sB + (uint32_t)(r * BKN_LD + c * 8) * 2,
                      gB + (size_t)(k0 + r) * N + c * 8);
            }
        }
    };

    float acc[4][4][4];
#pragma unroll
    for (int i = 0; i < 4; i++)
#pragma unroll
        for (int j = 0; j < 4; j++)
#pragma unroll
            for (int q = 0; q < 4; q++) acc[i][j][q] = 0.f;

    const int nk = K >> 5;
    issue(0, 0);  cp_commit();
    if (nk > 1) issue(1, 32);
    cp_commit();

    const int arow = wm * 64 + (lane & 15);
    const int acolb = (lane >> 4) * 8;
    const int brow = wn * 32 + ((lane >> 4) * 8) + (lane & 7);
    const int bcolb = ((lane >> 3) & 1) * 8;
    const int bjrow = lane & 15;
    const int bdcol = (lane >> 4) * 8;

    for (int it = 0; it < nk; ++it) {
        cp_wait<1>();
        __syncthreads();

        const int s = it % 3;
        uint32_t sA = sbase + (uint32_t)(s * STG_ELEMS) * 2;
        uint32_t sB = sA + A_ELEMS * 2;

#pragma unroll
        for (int ks = 0; ks < 2; ks++) {
            const int acol = ks * 16 + acolb;
            uint32_t ah[4][4], bh[4][2];
#pragma unroll
            for (int mi = 0; mi < 4; mi++)
                ldsm4(ah[mi], sA + (uint32_t)((arow + mi * 16) * GLDS + acol) * 2);
            if (BT) {
                const int bcol = ks * 16 + bcolb;
#pragma unroll
                for (int gp = 0; gp < 2; gp++) {
                    uint32_t rh[4];
                    ldsm4(rh, sB + (uint32_t)((brow + gp * 16) * GLDS + bcol) * 2);
                    bh[gp*2][0] = rh[0]; bh[gp*2][1] = rh[1];
                    bh[gp*2+1][0] = rh[2]; bh[gp*2+1][1] = rh[3];
                }
            } else {
#pragma unroll
                for (int gp = 0; gp < 2; gp++) {
                    uint32_t rh[4];
                    uint32_t off = (uint32_t)((ks * 16 + bjrow) * BKN_LD
                                              + wn * 32 + gp * 16 + bdcol) * 2;
                    ldsm4t(rh, sB + off);
                    bh[gp*2][0] = rh[0]; bh[gp*2][1] = rh[1];
                    bh[gp*2+1][0] = rh[2]; bh[gp*2+1][1] = rh[3];
                }
            }
#pragma unroll
            for (int mi = 0; mi < 4; mi++)
#pragma unroll
                for (int nj = 0; nj < 4; nj++)
                    mma16816(acc[mi][nj], ah[mi], bh[nj]);
        }

        if (it + 2 < nk) issue((it + 2) % 3, (it + 2) << 5);
        cp_commit();
    }

#pragma unroll
    for (int mi = 0; mi < 4; mi++) {
        int r0 = m0 + wm * 64 + mi * 16 + (lane >> 2);
#pragma unroll
        for (int nj = 0; nj < 4; nj++) {
            int c = n0 + wn * 32 + nj * 8 + (lane & 3) * 2;
            float v0x = acc[mi][nj][0], v0y = acc[mi][nj][1];
            float v1x = acc[mi][nj][2], v1y = acc[mi][nj][3];
            size_t o0 = (size_t)r0 * N + c;
            size_t o1 = o0 + (size_t)8 * N;
            if (OM == 2) {
                *(__half2*)(Ch + o0) =
                    __halves2half2(__float2half_rn(v0x), __float2half_rn(v0y));
                *(__half2*)(Ch + o1) =
                    __halves2half2(__float2half_rn(v1x), __float2half_rn(v1y));
            } else {
                if (bias) {
                    float bx = bias[c], by = bias[c + 1];
                    v0x += bx; v0y += by; v1x += bx; v1y += by;
                }
                if (res) {
                    float2 ra = *(const float2*)(res + o0);
                    float2 rb = *(const float2*)(res + o1);
                    v0x += ra.x; v0y += ra.y; v1x += rb.x; v1y += rb.y;
                }
                *(float2*)(C + o0) = make_float2(v0x, v0y);
                *(float2*)(C + o1) = make_float2(v1x, v1y);
            }
        }
    }
}

// ---------------------------------------------------------------------------
// 128x256 GEMM, 4-stage, 1 CTA/SM, B in [K,N] via ldsm.trans.
// ---------------------------------------------------------------------------
#define BKN2_LD 264
#define BF2_ELEMS (32 * BKN2_LD)
#define STG2_ELEMS (A_ELEMS + BF2_ELEMS)
#define HG2_SMEM (4 * STG2_ELEMS * 2)    // 108544 bytes

template <int OM>
__global__ __launch_bounds__(256, 1) void hmma_gemm256_kernel(
    const __half* __restrict__ Ah, const __half* __restrict__ Bh,
    const float* __restrict__ bias, const float* __restrict__ res,
    float* __restrict__ C, __half* __restrict__ Ch, int M, int N, int K)
{
    extern __shared__ __half smem[];
    const uint32_t sbase = smem_u32(smem);
    const int tid  = threadIdx.x;
    const int lane = tid & 31, warp = tid >> 5;
    const int wm = warp & 1, wn = warp >> 1;
    const int m0 = blockIdx.y << 7, n0 = blockIdx.x << 8;

    const __half* gA = Ah + (size_t)m0 * K;
    const __half* gB = Bh + n0;

    const int r0c = tid >> 2, c0c = tid & 3;

    auto issue = [&](int stage, int k0) {
        uint32_t sA = sbase + (uint32_t)(stage * STG2_ELEMS) * 2;
        uint32_t sB = sA + A_ELEMS * 2;
#pragma unroll
        for (int half_ = 0; half_ < 2; half_++) {
            int r = r0c + half_ * 64;
            cpa16(sA + (uint32_t)(r * GLDS + c0c * 8) * 2,
                  gA + (size_t)r * K + k0 + c0c * 8);
        }
#pragma unroll
        for (int p = 0; p < 4; p++) {
            int q = tid + p * 256;
            int r = q >> 5, c = q & 31;
            cpa16(sB + (uint32_t)(r * BKN2_LD + c * 8) * 2,
                  gB + (size_t)(k0 + r) * N + c * 8);
        }
    };

    float acc[4][8][4];
#pragma unroll
    for (int i = 0; i < 4; i++)
#pragma unroll
        for (int j = 0; j < 8; j++)
#pragma unroll
            for (int q = 0; q < 4; q++) acc[i][j][q] = 0.f;

    const int nk = K >> 5;
    issue(0, 0);              cp_commit();
    if (nk > 1) issue(1, 32); cp_commit();
    if (nk > 2) issue(2, 64); cp_commit();

    const int arow = wm * 64 + (lane & 15);
    const int acolb = (lane >> 4) * 8;
    const int bjrow = lane & 15;
    const int bdcol = (lane >> 4) * 8;

    for (int it = 0; it < nk; ++it) {
        cp_wait<2>();
        __syncthreads();

        const int s = it & 3;
        uint32_t sA = sbase + (uint32_t)(s * STG2_ELEMS) * 2;
        uint32_t sB = sA + A_ELEMS * 2;

#pragma unroll
        for (int ks = 0; ks < 2; ks++) {
            const int acol = ks * 16 + acolb;
            uint32_t ah[4][4], bh[8][2];
#pragma unroll
            for (int mi = 0; mi < 4; mi++)
                ldsm4(ah[mi], sA + (uint32_t)((arow + mi * 16) * GLDS + acol) * 2);
#pragma unroll
            for (int gp = 0; gp < 4; gp++) {
                uint32_t rh[4];
                uint32_t off = (uint32_t)((ks * 16 + bjrow) * BKN2_LD
                                          + wn * 64 + gp * 16 + bdcol) * 2;
                ldsm4t(rh, sB + off);
                bh[gp*2][0] = rh[0]; bh[gp*2][1] = rh[1];
                bh[gp*2+1][0] = rh[2]; bh[gp*2+1][1] = rh[3];
            }
#pragma unroll
            for (int mi = 0; mi < 4; mi++)
#pragma unroll
                for (int nj = 0; nj < 8; nj++)
                    mma16816(acc[mi][nj], ah[mi], bh[nj]);
        }

        if (it + 3 < nk) issue((it + 3) & 3, (it + 3) << 5);
        cp_commit();
    }

#pragma unroll
    for (int mi = 0; mi < 4; mi++) {
        int r0 = m0 + wm * 64 + mi * 16 + (lane >> 2);
#pragma unroll
        for (int nj = 0; nj < 8; nj++) {
            int c = n0 + wn * 64 + nj * 8 + (lane & 3) * 2;
            float v0x = acc[mi][nj][0], v0y = acc[mi][nj][1];
            float v1x = acc[mi][nj][2], v1y = acc[mi][nj][3];
            size_t o0 = (size_t)r0 * N + c;
            size_t o1 = o0 + (size_t)8 * N;
            if (OM == 2) {
                *(__half2*)(Ch + o0) =
                    __halves2half2(__float2half_rn(v0x), __float2half_rn(v0y));
                *(__half2*)(Ch + o1) =
                    __halves2half2(__float2half_rn(v1x), __float2half_rn(v1y));
            } else {
                if (bias) {
                    float bx = bias[c], by = bias[c + 1];
                    v0x += bx; v0y += by; v1x += bx; v1y += by;
                }
                if (res) {
                    float2 ra = *(const float2*)(res + o0);
                    float2 rb = *(const float2*)(res + o1);
                    v0x += ra.x; v0y += ra.y; v1x += rb.x; v1y += rb.y;
                }
                *(float2*)(C + o0) = make_float2(v0x, v0y);
                *(float2*)(C + o1) = make_float2(v1x, v1y);
            }
        }
    }
}

// ---------------------------------------------------------------------------
// qk via HMMA: W = (qh_i . kh_j)*0.125*(1+dist). CTA per (b,h).
// ---------------------------------------------------------------------------
#define QKLD 72
#define QK_TILE (128 * QKLD)
#define QK_SMEM (2 * QK_TILE * 2)

__global__ __launch_bounds__(256, 2) void qk_mma_kernel(
    const __half* __restrict__ qkvh,
    const float* __restrict__ dist, float* __restrict__ W)
{
    extern __shared__ __half smem[];
    const uint32_t sbase = smem_u32(smem);
    const int tid = threadIdx.x, lane = tid & 31, warp = tid >> 5;
    const int wm = warp & 1, wn = warp >> 1;
    const int b = blockIdx.x >> 4, h = blockIdx.x & 15;
    const size_t rowbase = (size_t)b * NTOK * PATCHDIM + h * DHEAD;

    const int offs[2] = { 0, DIMV };
#pragma unroll
    for (int t = 0; t < 2; t++) {
        uint32_t dbase = sbase + (uint32_t)(t * QK_TILE) * 2;
#pragma unroll
        for (int p = 0; p < 4; p++) {
            int q = tid + p * 256;
            int r = q >> 3, c = q & 7;
            cpa16(dbase + (uint32_t)(r * QKLD + c * 8) * 2,
                  qkvh + rowbase + (size_t)r * PATCHDIM + offs[t] + c * 8);
        }
    }
    cp_commit();
    cp_wait<0>();
    __syncthreads();

    float acc[4][4][4];
#pragma unroll
    for (int i = 0; i < 4; i++)
#pragma unroll
        for (int j = 0; j < 4; j++)
#pragma unroll
            for (int q = 0; q < 4; q++) acc[i][j][q] = 0.f;

    uint32_t sA  = sbase;
    uint32_t sB  = sbase + (uint32_t)QK_TILE * 2;
    const int arow = wm * 64 + (lane & 15);
    const int acolb = (lane >> 4) * 8;
    const int brow = wn * 32 + ((lane >> 4) * 8) + (lane & 7);
    const int bcolb = ((lane >> 3) & 1) * 8;

#pragma unroll
    for (int ks = 0; ks < 4; ks++) {
        const int acol = ks * 16 + acolb;
        const int bcol = ks * 16 + bcolb;
        uint32_t ah[4][4], bh[4][2];
#pragma unroll
        for (int mi = 0; mi < 4; mi++)
            ldsm4(ah[mi], sA + (uint32_t)((arow + mi * 16) * QKLD + acol) * 2);
#pragma unroll
        for (int gp = 0; gp < 2; gp++) {
            uint32_t rh[4];
            ldsm4(rh, sB + (uint32_t)((brow + gp * 16) * QKLD + bcol) * 2);
            bh[gp*2][0] = rh[0]; bh[gp*2][1] = rh[1];
            bh[gp*2+1][0] = rh[2]; bh[gp*2+1][1] = rh[3];
        }
#pragma unroll
        for (int mi = 0; mi < 4; mi++)
#pragma unroll
            for (int nj = 0; nj < 4; nj++)
                mma16816(acc[mi][nj], ah[mi], bh[nj]);
    }

    float* Wb = W + (size_t)blockIdx.x * (NTOK * NTOK);
#pragma unroll
    for (int mi = 0; mi < 4; mi++) {
        int i0 = wm * 64 + mi * 16 + (lane >> 2);
#pragma unroll
        for (int nj = 0; nj < 4; nj++) {
            int j0 = wn * 32 + nj * 8 + (lane & 3) * 2;
#pragma unroll
            for (int rr = 0; rr < 2; rr++) {
                int i = i0 + rr * 8;
                float vx = acc[mi][nj][rr*2], vy = acc[mi][nj][rr*2+1];
                Wb[i * 128 + j0]     = vx * 0.125f * (1.0f + dist[i * 128 + j0]);
                Wb[i * 128 + j0 + 1] = vy * 0.125f * (1.0f + dist[i * 128 + j0 + 1]);
            }
        }
    }
}

// ---------------------------------------------------------------------------
// Cross-head standardize (ddof=1) + softmax; emits fp16 P.
// ---------------------------------------------------------------------------
__global__ __launch_bounds__(128) void std_softmax_kernel(
    const float* __restrict__ W, __half* __restrict__ Ph)
{
    int b = blockIdx.x >> 7, i = blockIdx.x & 127;
    int j = threadIdx.x;
    __shared__ float sm[NHEADS][128];

    size_t base = (size_t)b * (NHEADS * NTOK * NTOK) + (size_t)i * 128 + j;
    float vals[NHEADS];
    float s = 0.f;
#pragma unroll
    for (int h = 0; h < NHEADS; h++) {
        float v = W[base + (size_t)h * (NTOK * NTOK)];
        vals[h] = v; s += v;
    }
    float mu = s * (1.0f / 16.0f);
    float d2 = 0.f;
#pragma unroll
    for (int h = 0; h < NHEADS; h++) {
        float d = vals[h] - mu;
        d2 += d * d;
    }
    float inv = rsqrtf(d2 * (1.0f / 15.0f));
#pragma unroll
    for (int h = 0; h < NHEADS; h++) sm[h][j] = (vals[h] - mu) * inv;
    __syncthreads();

    int warp = j >> 5, lane = j & 31;
#pragma unroll
    for (int r = 0; r < 4; r++) {
        int h = warp * 4 + r;
        float v0 = sm[h][lane], v1 = sm[h][lane + 32];
        float v2 = sm[h][lane + 64], v3 = sm[h][lane + 96];
        float m = fmaxf(fmaxf(v0, v1), fmaxf(v2, v3));
#pragma unroll
        for (int o = 16; o; o >>= 1) m = fmaxf(m, __shfl_xor_sync(0xffffffffu, m, o));
        float e0 = expf(v0 - m), e1 = expf(v1 - m);
        float e2 = expf(v2 - m), e3 = expf(v3 - m);
        float sum = e0 + e1 + e2 + e3;
#pragma unroll
        for (int o = 16; o; o >>= 1) sum += __shfl_xor_sync(0xffffffffu, sum, o);
        float rs = 1.0f / sum;
        size_t wb = (size_t)b * (NHEADS * NTOK * NTOK) + (size_t)h * (NTOK * NTOK)
                  + (size_t)i * 128;
        Ph[wb + lane]      = __float2half_rn(e0 * rs);
        Ph[wb + lane + 32] = __float2half_rn(e1 * rs);
        Ph[wb + lane + 64] = __float2half_rn(e2 * rs);
        Ph[wb + lane + 96] = __float2half_rn(e3 * rs);
    }
}

// ---------------------------------------------------------------------------
// av via HMMA: O[i,h*64+d] = sum_j Ph[i,j]*Vh[j,d]. CTA per (b,h).
// ---------------------------------------------------------------------------
#define AVPLD 136
#define AVVLD 72
#define AVP_TILE (128 * AVPLD)
#define AVV_TILE (128 * AVVLD)
#define AV_SMEM ((AVP_TILE + AVV_TILE) * 2)

__global__ __launch_bounds__(256, 2) void av_mma_kernel(
    const __half* __restrict__ Ph, const __half* __restrict__ qkvh,
    __half* __restrict__ Oh)
{
    extern __shared__ __half smem[];
    const uint32_t sbase = smem_u32(smem);
    const int tid = threadIdx.x, lane = tid & 31, warp = tid >> 5;
    const int wm = warp & 3, wn = warp >> 2;
    const int b = blockIdx.x >> 4, h = blockIdx.x & 15;
    const size_t pbase = (size_t)blockIdx.x * (NTOK * NTOK);
    const size_t vbase = (size_t)b * NTOK * PATCHDIM + 2 * DIMV + h * DHEAD;

#pragma unroll
    for (int p = 0; p < 8; p++) {
        int q = tid + p * 256;
        int r = q >> 4, c = q & 15;
        cpa16(sbase + (uint32_t)(r * AVPLD + c * 8) * 2,
              Ph + pbase + (size_t)r * 128 + c * 8);
    }
    {
        uint32_t dbase = sbase + (uint32_t)AVP_TILE * 2;
#pragma unroll
        for (int p = 0; p < 4; p++) {
            int q = tid + p * 256;
            int j = q >> 3, c = q & 7;
            cpa16(dbase + (uint32_t)(j * AVVLD + c * 8) * 2,
                  qkvh + vbase + (size_t)j * PATCHDIM + c * 8);
        }
    }
    cp_commit();
    cp_wait<0>();
    __syncthreads();

    float acc[2][4][4];
#pragma unroll
    for (int i = 0; i < 2; i++)
#pragma unroll
        for (int j = 0; j < 4; j++)
#pragma unroll
            for (int q = 0; q < 4; q++) acc[i][j][q] = 0.f;

    uint32_t sA  = sbase;
    uint32_t sB  = sbase + (uint32_t)AVP_TILE * 2;
    const int arow = wm * 32 + (lane & 15);
    const int acolb = (lane >> 4) * 8;
    const int bjrow = lane & 15;
    const int bdcol = (lane >> 4) * 8;

#pragma unroll
    for (int kc = 0; kc < 8; kc++) {
        const int acol = kc * 16 + acolb;
        uint32_t ah[2][4], bh[4][2];
#pragma unroll
        for (int mi = 0; mi < 2; mi++)
            ldsm4(ah[mi], sA + (uint32_t)((arow + mi * 16) * AVPLD + acol) * 2);
#pragma unroll
        for (int gp = 0; gp < 2; gp++) {
            uint32_t rh[4];
            uint32_t off = (uint32_t)((kc * 16 + bjrow) * AVVLD
                                      + wn * 32 + gp * 16 + bdcol) * 2;
            ldsm4t(rh, sB + off);
            bh[gp*2][0] = rh[0]; bh[gp*2][1] = rh[1];
            bh[gp*2+1][0] = rh[2]; bh[gp*2+1][1] = rh[3];
        }
#pragma unroll
        for (int mi = 0; mi < 2; mi++)
#pragma unroll
            for (int nj = 0; nj < 4; nj++)
                mma16816(acc[mi][nj], ah[mi], bh[nj]);
    }

#pragma unroll
    for (int mi = 0; mi < 2; mi++) {
        int i0 = wm * 32 + mi * 16 + (lane >> 2);
#pragma unroll
        for (int nj = 0; nj < 4; nj++) {
            int d0 = wn * 32 + nj * 8 + (lane & 3) * 2;
#pragma unroll
            for (int rr = 0; rr < 2; rr++) {
                int i = i0 + rr * 8;
                size_t o = (size_t)(b * 128 + i) * DIMV + h * DHEAD + d0;
                *(__half2*)(Oh + o) =
                    __halves2half2(__float2half_rn(acc[mi][nj][rr*2]),
                                   __float2half_rn(acc[mi][nj][rr*2 + 1]));
            }
        }
    }
}

// ---------------------------------------------------------------------------
// Vectorized weight prep: 8 elems/thread, 16B stores.
// ---------------------------------------------------------------------------
__global__ void split8_kernel(const float4* __restrict__ X, uint4* __restrict__ H) {
    size_t i = (size_t)blockIdx.x * 256 + threadIdx.x;
    float4 a = X[i * 2], b = X[i * 2 + 1];
    H[i] = cvt8(a, b);
}

__global__ void extract_patches8_kernel(const float* __restrict__ img,
                                        uint4* __restrict__ H) {
    int i = blockIdx.x * 256 + threadIdx.x;
    int idx = i * 8;
    int col = idx % PATCHDIM;
    int row = idx / PATCHDIM;
    int b = row >> 7, t = row & 127;
    int h = t >> 4, w = t & 15;
    int c = col >> 10, r = col & 1023;
    int p = r >> 5, q = r & 31;
    const float* src = img + (((size_t)b * 3 + c) * 256 + h * 32 + p) * 512
                           + w * 32 + q;
    float4 a = *(const float4*)(src);
    float4 bb = *(const float4*)(src + 4);
    H[i] = cvt8(a, bb);
}

// ---------------------------------------------------------------------------
// Register-cached LayerNorms (single global read of x).
// Block reduce over 256 threads.
// ---------------------------------------------------------------------------
__device__ __forceinline__ void block_reduce2(float& s, float& ss) {
#pragma unroll
    for (int o = 16; o; o >>= 1) {
        s  += __shfl_xor_sync(0xffffffffu, s, o);
        ss += __shfl_xor_sync(0xffffffffu, ss, o);
    }
    __shared__ float sh[2][8];
    int w = threadIdx.x >> 5;
    if ((threadIdx.x & 31) == 0) { sh[0][w] = s; sh[1][w] = ss; }
    __syncthreads();
    if (threadIdx.x < 32) {
        float a = (threadIdx.x < 8) ? sh[0][threadIdx.x] : 0.f;
        float b = (threadIdx.x < 8) ? sh[1][threadIdx.x] : 0.f;
#pragma unroll
        for (int o = 4; o; o >>= 1) {
            a += __shfl_xor_sync(0xffffffffu, a, o);
            b += __shfl_xor_sync(0xffffffffu, b, o);
        }
        if (threadIdx.x == 0) { sh[0][0] = a; sh[1][0] = b; }
    }
    __syncthreads();
    s = sh[0][0]; ss = sh[1][0];
}

// LN over D=1024 -> fp16 out. 256 threads, 4 elems/thread.
__global__ __launch_bounds__(256) void ln_half_kernel(
    const float* __restrict__ x, const float* __restrict__ g,
    const float* __restrict__ beta, __half* __restrict__ H)
{
    size_t base = (size_t)blockIdx.x * DIMV;
    int t = threadIdx.x;
    float4 xv = *(const float4*)(x + base + t * 4);
    float s  = xv.x + xv.y + xv.z + xv.w;
    float ss = xv.x*xv.x + xv.y*xv.y + xv.z*xv.z + xv.w*xv.w;
    block_reduce2(s, ss);
    float mu = s * (1.0f / DIMV);
    float rstd = rsqrtf(ss * (1.0f / DIMV) - mu * mu + LN_EPS);
    float4 gv = *(const float4*)(g + t * 4);
    float4 bv = *(const float4*)(beta + t * 4);
    float o0 = (xv.x - mu) * rstd * gv.x + bv.x;
    float o1 = (xv.y - mu) * rstd * gv.y + bv.y;
    float o2 = (xv.z - mu) * rstd * gv.z + bv.z;
    float o3 = (xv.w - mu) * rstd * gv.w + bv.w;
    __half2 h0 = __halves2half2(__float2half_rn(o0), __float2half_rn(o1));
    __half2 h1 = __halves2half2(__float2half_rn(o2), __float2half_rn(o3));
    uint2 u; u.x = *(uint32_t*)&h0; u.y = *(uint32_t*)&h1;
    *(uint2*)(H + base + t * 4) = u;
}

// LN over D=1024 + positional embedding -> fp32 out.
__global__ __launch_bounds__(256) void ln_addpos_kernel(
    const float* __restrict__ x, const float* __restrict__ g,
    const float* __restrict__ beta, const float* __restrict__ sph_pos,
    const float* __restrict__ pos_w, const float* __restrict__ pos_b,
    float* __restrict__ y)
{
    size_t base = (size_t)blockIdx.x * DIMV;
    int t = threadIdx.x;
    float4 xv = *(const float4*)(x + base + t * 4);
    float s  = xv.x + xv.y + xv.z + xv.w;
    float ss = xv.x*xv.x + xv.y*xv.y + xv.z*xv.z + xv.w*xv.w;
    block_reduce2(s, ss);
    float mu = s * (1.0f / DIMV);
    float rstd = rsqrtf(ss * (1.0f / DIMV) - mu * mu + LN_EPS);
    int tok = blockIdx.x & 127;
    float p0 = sph_pos[tok * 2], p1 = sph_pos[tok * 2 + 1];
    float4 gv = *(const float4*)(g + t * 4);
    float4 bv = *(const float4*)(beta + t * 4);
    float4 w0 = *(const float4*)(pos_w + t * 4);
    float4 w1 = *(const float4*)(pos_w + 1024 + t * 4);
    float4 pb = *(const float4*)(pos_b + t * 4);
    float4 o;
    o.x = (xv.x - mu) * rstd * gv.x + bv.x + p0 * w0.x + p1 * w1.x + pb.x;
    o.y = (xv.y - mu) * rstd * gv.y + bv.y + p0 * w0.y + p1 * w1.y + pb.y;
    o.z = (xv.z - mu) * rstd * gv.z + bv.z + p0 * w0.z + p1 * w1.z + pb.z;
    o.w = (xv.w - mu) * rstd * gv.w + bv.w + p0 * w0.w + p1 * w1.w + pb.w;
    *(float4*)(y + base + t * 4) = o;
}

// LN over D=3072 -> fp32 out (out_ln). 256 threads, 12 elems/thread.
__global__ __launch_bounds__(256) void ln3072_kernel(
    const float* __restrict__ x, const float* __restrict__ g,
    const float* __restrict__ beta, float* __restrict__ y)
{
    size_t base = (size_t)blockIdx.x * PATCHDIM;
    int t = threadIdx.x;
    float4 xv[3];
    float s = 0.f, ss = 0.f;
#pragma unroll
    for (int k = 0; k < 3; k++) {
        xv[k] = *(const float4*)(x + base + k * 1024 + t * 4);
        s  += xv[k].x + xv[k].y + xv[k].z + xv[k].w;
        ss += xv[k].x*xv[k].x + xv[k].y*xv[k].y + xv[k].z*xv[k].z + xv[k].w*xv[k].w;
    }
    block_reduce2(s, ss);
    float mu = s * (1.0f / PATCHDIM);
    float rstd = rsqrtf(ss * (1.0f / PATCHDIM) - mu * mu + LN_EPS);
#pragma unroll
    for (int k = 0; k < 3; k++) {
        float4 gv = *(const float4*)(g + k * 1024 + t * 4);
        float4 bv = *(const float4*)(beta + k * 1024 + t * 4);
        float4 o;
        o.x = (xv[k].x - mu) * rstd * gv.x + bv.x;
        o.y = (xv[k].y - mu) * rstd * gv.y + bv.y;
        o.z = (xv[k].z - mu) * rstd * gv.z + bv.z;
        o.w = (xv[k].w - mu) * rstd * gv.w + bv.w;
        *(float4*)(y + base + k * 1024 + t * 4) = o;
    }
}

// ---------------------------------------------------------------------------
// Reassemble via smem staging: coalesced Y read, coalesced out write.
// One block per token row. smem gather stride-3 is bank-conflict-free.
// ---------------------------------------------------------------------------
__global__ __launch_bounds__(256) void reassemble_kernel(
    const float* __restrict__ Y, float* __restrict__ out)
{
    __shared__ float sy[PATCHDIM];
    int row = blockIdx.x;
    const float4* src = (const float4*)(Y + (size_t)row * PATCHDIM);
#pragma unroll
    for (int i = threadIdx.x; i < PATCHDIM / 4; i += 256)
        ((float4*)sy)[i] = src[i];
    __syncthreads();

    int b = row >> 7, t = row & 127;
    int h = t >> 4, w = t & 15;
    for (int oidx = threadIdx.x; oidx < PATCHDIM; oidx += 256) {
        int c  = oidx >> 10;
        int p1 = (oidx >> 5) & 31;
        int p2 = oidx & 31;
        float v = sy[(p1 * 32 + p2) * 3 + c];
        out[(((size_t)b * 3 + c) * 256 + h * 32 + p1) * 512 + w * 32 + p2] = v;
    }
}

// ---------------------------------------------------------------------------
// Host launcher
// ---------------------------------------------------------------------------
extern "C" void kernel_launch(void* const* d_in, const int* in_sizes, int n_in,
                              void* d_out, int out_size)
{
    const float* img      = (const float*)d_in[0];
    const float* sph_pos  = (const float*)d_in[1];
    const float* sph_dist = (const float*)d_in[2];
    const float* conv_w   = (const float*)d_in[3];
    const float* conv_b   = (const float*)d_in[4];
    const float* nl_ln1_g = (const float*)d_in[5];
    const float* nl_ln1_b = (const float*)d_in[6];
    const float* nl_w     = (const float*)d_in[7];
    const float* nl_b     = (const float*)d_in[8];
    const float* nl_ln2_g = (const float*)d_in[9];
    const float* nl_ln2_b = (const float*)d_in[10];
    const float* pos_w    = (const float*)d_in[11];
    const float* pos_b    = (const float*)d_in[12];
    const float* ln_g     = (const float*)d_in[13];
    const float* ln_b     = (const float*)d_in[14];
    const float* wqkv     = (const float*)d_in[15];
    const float* wo       = (const float*)d_in[16];
    const float* wo_b     = (const float*)d_in[17];
    const float* tr_ln_g  = (const float*)d_in[18];
    const float* tr_ln_b  = (const float*)d_in[19];
    const float* exp_w    = (const float*)d_in[20];
    const float* exp_b    = (const float*)d_in[21];
    const float* out_ln_g = (const float*)d_in[22];
    const float* out_ln_b = (const float*)d_in[23];

    float *big, *x, *w;
    cudaGetSymbolAddress((void**)&big, g_big);
    cudaGetSymbolAddress((void**)&x,   g_x);
    cudaGetSymbolAddress((void**)&w,   g_w);
    __half *Xph, *qkvh, *hh, *oh, *ph;
    __half *cwh, *nlwh, *qwh, *owh, *ewh;
    cudaGetSymbolAddress((void**)&Xph, g_Xph);
    cudaGetSymbolAddress((void**)&qkvh, g_qkvh);
    cudaGetSymbolAddress((void**)&hh,  g_hh);
    cudaGetSymbolAddress((void**)&oh,  g_oh);
    cudaGetSymbolAddress((void**)&ph,  g_ph);
    cudaGetSymbolAddress((void**)&cwh, g_cwh);
    cudaGetSymbolAddress((void**)&nlwh, g_nlwh);
    cudaGetSymbolAddress((void**)&qwh, g_qwh);
    cudaGetSymbolAddress((void**)&owh, g_owh);
    cudaGetSymbolAddress((void**)&ewh, g_ewh);

    cudaFuncSetAttribute(hmma_gemm_kernel<0, true>,
                         cudaFuncAttributeMaxDynamicSharedMemorySize, HG_SMEM);
    cudaFuncSetAttribute(hmma_gemm_kernel<0, false>,
                         cudaFuncAttributeMaxDynamicSharedMemorySize, HG_SMEM);
    cudaFuncSetAttribute(hmma_gemm256_kernel<0>,
                         cudaFuncAttributeMaxDynamicSharedMemorySize, HG2_SMEM);
    cudaFuncSetAttribute(hmma_gemm256_kernel<2>,
                         cudaFuncAttributeMaxDynamicSharedMemorySize, HG2_SMEM);
    cudaFuncSetAttribute(qk_mma_kernel,
                         cudaFuncAttributeMaxDynamicSharedMemorySize, QK_SMEM);
    cudaFuncSetAttribute(av_mma_kernel,
                         cudaFuncAttributeMaxDynamicSharedMemorySize, AV_SMEM);

    // ---- prep: vectorized stream conversions ----
    split8_kernel<<<DIMV * PATCHDIM / 2048, 256>>>((const float4*)conv_w, (uint4*)cwh);
    extract_patches8_kernel<<<ROWS * PATCHDIM / 2048, 256>>>(img, (uint4*)Xph);
    split8_kernel<<<DIMV * DIMV / 2048, 256>>>((const float4*)nl_w, (uint4*)nlwh);
    split8_kernel<<<DEPTH * DIMV * PATCHDIM / 2048, 256>>>((const float4*)wqkv, (uint4*)qwh);
    split8_kernel<<<DEPTH * DIMV * DIMV / 2048, 256>>>((const float4*)wo, (uint4*)owh);
    hmma_gemm_kernel<0, true><<<dim3(DIMV/128, ROWS/128), 256, HG_SMEM>>>(
        Xph, cwh, conv_b, nullptr, x, nullptr, ROWS, DIMV, PATCHDIM);
    split8_kernel<<<DIMV * PATCHDIM / 2048, 256>>>((const float4*)exp_w, (uint4*)ewh);

    // ---- norm_linear + positional embedding ----
    ln_half_kernel<<<ROWS, 256>>>(x, nl_ln1_g, nl_ln1_b, hh);
    hmma_gemm_kernel<0, false><<<dim3(DIMV/128, ROWS/128), 256, HG_SMEM>>>(
        hh, nlwh, nl_b, nullptr, x, nullptr, ROWS, DIMV, DIMV);
    ln_addpos_kernel<<<ROWS, 256>>>(x, nl_ln2_g, nl_ln2_b, sph_pos, pos_w, pos_b, x);

    // ---- transformer layers ----
    for (int l = 0; l < DEPTH; l++) {
        ln_half_kernel<<<ROWS, 256>>>(x, ln_g + l * DIMV, ln_b + l * DIMV, hh);
        hmma_gemm256_kernel<2><<<dim3(PATCHDIM/256, ROWS/128), 256, HG2_SMEM>>>(
            hh, qwh + (size_t)l * DIMV * PATCHDIM,
            nullptr, nullptr, nullptr, qkvh, ROWS, PATCHDIM, DIMV);
        qk_mma_kernel<<<BATCH * NHEADS, 256, QK_SMEM>>>(qkvh, sph_dist, w);
        std_softmax_kernel<<<BATCH * NTOK, 128>>>(w, ph);
        av_mma_kernel<<<BATCH * NHEADS, 256, AV_SMEM>>>(ph, qkvh, oh);
        hmma_gemm_kernel<0, false><<<dim3(DIMV/128, ROWS/128), 256, HG_SMEM>>>(
            oh, owh + (size_t)l * DIMV * DIMV,
            wo_b + l * DIMV, x, x, nullptr, ROWS, DIMV, DIMV);
    }

    // ---- final LN + expand + output LN + reassembly ----
    ln_half_kernel<<<ROWS, 256>>>(x, tr_ln_g, tr_ln_b, hh);
    hmma_gemm256_kernel<0><<<dim3(PATCHDIM/256, ROWS/128), 256, HG2_SMEM>>>(
        hh, ewh, exp_b, nullptr, big, nullptr, ROWS, PATCHDIM, DIMV);
    ln3072_kernel<<<ROWS, 256>>>(big, out_ln_g, out_ln_b, big);
    reassemble_kernel<<<ROWS, 256>>>(big, (float*)d_out);
}

// round 16
// speedup vs baseline: 3.8086x; 1.0341x over previous
#include <cuda_runtime.h>
#include <cuda_fp16.h>
#include <cstdint>

// ---------------------------------------------------------------------------
// SphereViT forward — pure-fp16 single-pass HMMA.
// R16: attention scores W stored fp16 (halves W traffic); out-LN fused into
//      reassemble (one fewer 96MB pass).
// ---------------------------------------------------------------------------

#define BATCH     32
#define NTOK      128
#define ROWS      4096
#define DIMV      1024
#define PATCHDIM  3072
#define NHEADS    16
#define DHEAD     64
#define DEPTH     12
#define LN_EPS    1e-5f

// -------------------- scratch (device globals; no allocs) ------------------
__device__ float g_big[ROWS * PATCHDIM];
__device__ float g_x  [ROWS * DIMV];
__device__ __half g_w [BATCH * NHEADS * NTOK * NTOK];   // scores fp16

__device__ __half g_Xph[ROWS * PATCHDIM];
__device__ __half g_qkvh[ROWS * PATCHDIM];
__device__ __half g_hh [ROWS * DIMV];
__device__ __half g_oh [ROWS * DIMV];
__device__ __half g_ph [BATCH*NHEADS*NTOK*NTOK];

// fp16 weights: conv in [N,K]; all others kept in native [K,N]
__device__ __half g_cwh[DIMV * PATCHDIM];
__device__ __half g_nlwh[DIMV * DIMV];
__device__ __half g_qwh[DEPTH * DIMV * PATCHDIM];
__device__ __half g_owh[DEPTH * DIMV * DIMV];
__device__ __half g_ewh[DIMV * PATCHDIM];

// ---------------------------------------------------------------------------
// PTX helpers
// ---------------------------------------------------------------------------
__device__ __forceinline__ uint32_t smem_u32(const void* p) {
    uint32_t a;
    asm("{ .reg .u64 t; cvta.to.shared.u64 t, %1; cvt.u32.u64 %0, t; }"
        : "=r"(a) : "l"(p));
    return a;
}
__device__ __forceinline__ void cpa16(uint32_t dst, const void* src) {
    asm volatile("cp.async.cg.shared.global [%0], [%1], 16;" :: "r"(dst), "l"(src));
}
__device__ __forceinline__ void cp_commit() { asm volatile("cp.async.commit_group;"); }
template <int NN>
__device__ __forceinline__ void cp_wait() {
    asm volatile("cp.async.wait_group %0;" :: "n"(NN));
}
__device__ __forceinline__ void ldsm4(uint32_t* r, uint32_t addr) {
    asm volatile("ldmatrix.sync.aligned.m8n8.x4.shared.b16 {%0,%1,%2,%3}, [%4];"
                 : "=r"(r[0]), "=r"(r[1]), "=r"(r[2]), "=r"(r[3]) : "r"(addr));
}
__device__ __forceinline__ void ldsm4t(uint32_t* r, uint32_t addr) {
    asm volatile("ldmatrix.sync.aligned.m8n8.x4.trans.shared.b16 {%0,%1,%2,%3}, [%4];"
                 : "=r"(r[0]), "=r"(r[1]), "=r"(r[2]), "=r"(r[3]) : "r"(addr));
}
__device__ __forceinline__ void mma16816(float* c, const uint32_t* a,
                                         const uint32_t* b) {
    asm volatile(
        "mma.sync.aligned.m16n8k16.row.col.f32.f16.f16.f32 "
        "{%0,%1,%2,%3}, {%4,%5,%6,%7}, {%8,%9}, {%0,%1,%2,%3};"
        : "+f"(c[0]), "+f"(c[1]), "+f"(c[2]), "+f"(c[3])
        : "r"(a[0]), "r"(a[1]), "r"(a[2]), "r"(a[3]), "r"(b[0]), "r"(b[1]));
}

__device__ __forceinline__ uint4 cvt8(float4 a, float4 b) {
    __half2 h0 = __halves2half2(__float2half_rn(a.x), __float2half_rn(a.y));
    __half2 h1 = __halves2half2(__float2half_rn(a.z), __float2half_rn(a.w));
    __half2 h2 = __halves2half2(__float2half_rn(b.x), __float2half_rn(b.y));
    __half2 h3 = __halves2half2(__float2half_rn(b.z), __float2half_rn(b.w));
    uint4 u;
    u.x = *(uint32_t*)&h0; u.y = *(uint32_t*)&h1;
    u.z = *(uint32_t*)&h2; u.w = *(uint32_t*)&h3;
    return u;
}

#define GLDS 40
#define A_ELEMS (128 * GLDS)             // 5120
#define BKN_LD 136
#define STG_ELEMS (A_ELEMS + 5120)       // 10240
#define HG_SMEM (3 * STG_ELEMS * 2)      // 61440 bytes, 3-stage

// ---------------------------------------------------------------------------
// 128x128 GEMM, 3-stage, 2 CTAs/SM.
// ---------------------------------------------------------------------------
template <int OM, bool BT>
__global__ __launch_bounds__(256, 2) void hmma_gemm_kernel(
    const __half* __restrict__ Ah, const __half* __restrict__ Bh,
    const float* __restrict__ bias, const float* __restrict__ res,
    float* __restrict__ C, __half* __restrict__ Ch, int M, int N, int K)
{
    extern __shared__ __half smem[];
    const uint32_t sbase = smem_u32(smem);
    const int tid  = threadIdx.x;
    const int lane = tid & 31, warp = tid >> 5;
    const int wm = warp & 1, wn = warp >> 1;
    const int m0 = blockIdx.y << 7, n0 = blockIdx.x << 7;

    const __half* gA = Ah + (size_t)m0 * K;
    const __half* gB = BT ? (Bh + (size_t)n0 * K) : (Bh + n0);

    const int r0c = tid >> 2, c0c = tid & 3;

    auto issue = [&](int stage, int k0) {
        uint32_t sA = sbase + (uint32_t)(stage * STG_ELEMS) * 2;
        uint32_t sB = sA + A_ELEMS * 2;
#pragma unroll
        for (int half_ = 0; half_ < 2; half_++) {
            int r = r0c + half_ * 64;
            cpa16(sA + (uint32_t)(r * GLDS + c0c * 8) * 2,
                  gA + (size_t)r * K + k0 + c0c * 8);
        }
        if (BT) {
#pragma unroll
            for (int half_ = 0; half_ < 2; half_++) {
                int r = r0c + half_ * 64;
                cpa16(sB + (uint32_t)(r * GLDS + c0c * 8) * 2,
                      gB + (size_t)r * K + k0 + c0c * 8);
            }
        } else {
#pragma unroll
            for (int p = 0; p < 2; p++) {
                int q = tid + p * 256;
                int r = q >> 4, c = q & 15;
                cpa16(sB + (uint32_t)(r * BKN_LD + c * 8) * 2,
                      gB + (size_t)(k0 + r) * N + c * 8);
            }
        }
    };

    float acc[4][4][4];
#pragma unroll
    for (int i = 0; i < 4; i++)
#pragma unroll
        for (int j = 0; j < 4; j++)
#pragma unroll
            for (int q = 0; q < 4; q++) acc[i][j][q] = 0.f;

    const int nk = K >> 5;
    issue(0, 0);  cp_commit();
    if (nk > 1) issue(1, 32);
    cp_commit();

    const int arow = wm * 64 + (lane & 15);
    const int acolb = (lane >> 4) * 8;
    const int brow = wn * 32 + ((lane >> 4) * 8) + (lane & 7);
    const int bcolb = ((lane >> 3) & 1) * 8;
    const int bjrow = lane & 15;
    const int bdcol = (lane >> 4) * 8;

    for (int it = 0; it < nk; ++it) {
        cp_wait<1>();
        __syncthreads();

        const int s = it % 3;
        uint32_t sA = sbase + (uint32_t)(s * STG_ELEMS) * 2;
        uint32_t sB = sA + A_ELEMS * 2;

#pragma unroll
        for (int ks = 0; ks < 2; ks++) {
            const int acol = ks * 16 + acolb;
            uint32_t ah[4][4], bh[4][2];
#pragma unroll
            for (int mi = 0; mi < 4; mi++)
                ldsm4(ah[mi], sA + (uint32_t)((arow + mi * 16) * GLDS + acol) * 2);
            if (BT) {
                const int bcol = ks * 16 + bcolb;
#pragma unroll
                for (int gp = 0; gp < 2; gp++) {
                    uint32_t rh[4];
                    ldsm4(rh, sB + (uint32_t)((brow + gp * 16) * GLDS + bcol) * 2);
                    bh[gp*2][0] = rh[0]; bh[gp*2][1] = rh[1];
                    bh[gp*2+1][0] = rh[2]; bh[gp*2+1][1] = rh[3];
                }
            } else {
#pragma unroll
                for (int gp = 0; gp < 2; gp++) {
                    uint32_t rh[4];
                    uint32_t off = (uint32_t)((ks * 16 + bjrow) * BKN_LD
                                              + wn * 32 + gp * 16 + bdcol) * 2;
                    ldsm4t(rh, sB + off);
                    bh[gp*2][0] = rh[0]; bh[gp*2][1] = rh[1];
                    bh[gp*2+1][0] = rh[2]; bh[gp*2+1][1] = rh[3];
                }
            }
#pragma unroll
            for (int mi = 0; mi < 4; mi++)
#pragma unroll
                for (int nj = 0; nj < 4; nj++)
                    mma16816(acc[mi][nj], ah[mi], bh[nj]);
        }

        if (it + 2 < nk) issue((it + 2) % 3, (it + 2) << 5);
        cp_commit();
    }

#pragma unroll
    for (int mi = 0; mi < 4; mi++) {
        int r0 = m0 + wm * 64 + mi * 16 + (lane >> 2);
#pragma unroll
        for (int nj = 0; nj < 4; nj++) {
            int c = n0 + wn * 32 + nj * 8 + (lane & 3) * 2;
            float v0x = acc[mi][nj][0], v0y = acc[mi][nj][1];
            float v1x = acc[mi][nj][2], v1y = acc[mi][nj][3];
            size_t o0 = (size_t)r0 * N + c;
            size_t o1 = o0 + (size_t)8 * N;
            if (OM == 2) {
                *(__half2*)(Ch + o0) =
                    __halves2half2(__float2half_rn(v0x), __float2half_rn(v0y));
                *(__half2*)(Ch + o1) =
                    __halves2half2(__float2half_rn(v1x), __float2half_rn(v1y));
            } else {
                if (bias) {
                    float bx = bias[c], by = bias[c + 1];
                    v0x += bx; v0y += by; v1x += bx; v1y += by;
                }
                if (res) {
                    float2 ra = *(const float2*)(res + o0);
                    float2 rb = *(const float2*)(res + o1);
                    v0x += ra.x; v0y += ra.y; v1x += rb.x; v1y += rb.y;
                }
                *(float2*)(C + o0) = make_float2(v0x, v0y);
                *(float2*)(C + o1) = make_float2(v1x, v1y);
            }
        }
    }
}

// ---------------------------------------------------------------------------
// 128x256 GEMM, 4-stage, 1 CTA/SM, B in [K,N] via ldsm.trans.
// ---------------------------------------------------------------------------
#define BKN2_LD 264
#define BF2_ELEMS (32 * BKN2_LD)
#define STG2_ELEMS (A_ELEMS + BF2_ELEMS)
#define HG2_SMEM (4 * STG2_ELEMS * 2)    // 108544 bytes

template <int OM>
__global__ __launch_bounds__(256, 1) void hmma_gemm256_kernel(
    const __half* __restrict__ Ah, const __half* __restrict__ Bh,
    const float* __restrict__ bias, const float* __restrict__ res,
    float* __restrict__ C, __half* __restrict__ Ch, int M, int N, int K)
{
    extern __shared__ __half smem[];
    const uint32_t sbase = smem_u32(smem);
    const int tid  = threadIdx.x;
    const int lane = tid & 31, warp = tid >> 5;
    const int wm = warp & 1, wn = warp >> 1;
    const int m0 = blockIdx.y << 7, n0 = blockIdx.x << 8;

    const __half* gA = Ah + (size_t)m0 * K;
    const __half* gB = Bh + n0;

    const int r0c = tid >> 2, c0c = tid & 3;

    auto issue = [&](int stage, int k0) {
        uint32_t sA = sbase + (uint32_t)(stage * STG2_ELEMS) * 2;
        uint32_t sB = sA + A_ELEMS * 2;
#pragma unroll
        for (int half_ = 0; half_ < 2; half_++) {
            int r = r0c + half_ * 64;
            cpa16(sA + (uint32_t)(r * GLDS + c0c * 8) * 2,
                  gA + (size_t)r * K + k0 + c0c * 8);
        }
#pragma unroll
        for (int p = 0; p < 4; p++) {
            int q = tid + p * 256;
            int r = q >> 5, c = q & 31;
            cpa16(sB + (uint32_t)(r * BKN2_LD + c * 8) * 2,
                  gB + (size_t)(k0 + r) * N + c * 8);
        }
    };

    float acc[4][8][4];
#pragma unroll
    for (int i = 0; i < 4; i++)
#pragma unroll
        for (int j = 0; j < 8; j++)
#pragma unroll
            for (int q = 0; q < 4; q++) acc[i][j][q] = 0.f;

    const int nk = K >> 5;
    issue(0, 0);              cp_commit();
    if (nk > 1) issue(1, 32); cp_commit();
    if (nk > 2) issue(2, 64); cp_commit();

    const int arow = wm * 64 + (lane & 15);
    const int acolb = (lane >> 4) * 8;
    const int bjrow = lane & 15;
    const int bdcol = (lane >> 4) * 8;

    for (int it = 0; it < nk; ++it) {
        cp_wait<2>();
        __syncthreads();

        const int s = it & 3;
        uint32_t sA = sbase + (uint32_t)(s * STG2_ELEMS) * 2;
        uint32_t sB = sA + A_ELEMS * 2;

#pragma unroll
        for (int ks = 0; ks < 2; ks++) {
            const int acol = ks * 16 + acolb;
            uint32_t ah[4][4], bh[8][2];
#pragma unroll
            for (int mi = 0; mi < 4; mi++)
                ldsm4(ah[mi], sA + (uint32_t)((arow + mi * 16) * GLDS + acol) * 2);
#pragma unroll
            for (int gp = 0; gp < 4; gp++) {
                uint32_t rh[4];
                uint32_t off = (uint32_t)((ks * 16 + bjrow) * BKN2_LD
                                          + wn * 64 + gp * 16 + bdcol) * 2;
                ldsm4t(rh, sB + off);
                bh[gp*2][0] = rh[0]; bh[gp*2][1] = rh[1];
                bh[gp*2+1][0] = rh[2]; bh[gp*2+1][1] = rh[3];
            }
#pragma unroll
            for (int mi = 0; mi < 4; mi++)
#pragma unroll
                for (int nj = 0; nj < 8; nj++)
                    mma16816(acc[mi][nj], ah[mi], bh[nj]);
        }

        if (it + 3 < nk) issue((it + 3) & 3, (it + 3) << 5);
        cp_commit();
    }

#pragma unroll
    for (int mi = 0; mi < 4; mi++) {
        int r0 = m0 + wm * 64 + mi * 16 + (lane >> 2);
#pragma unroll
        for (int nj = 0; nj < 8; nj++) {
            int c = n0 + wn * 64 + nj * 8 + (lane & 3) * 2;
            float v0x = acc[mi][nj][0], v0y = acc[mi][nj][1];
            float v1x = acc[mi][nj][2], v1y = acc[mi][nj][3];
            size_t o0 = (size_t)r0 * N + c;
            size_t o1 = o0 + (size_t)8 * N;
            if (OM == 2) {
                *(__half2*)(Ch + o0) =
                    __halves2half2(__float2half_rn(v0x), __float2half_rn(v0y));
                *(__half2*)(Ch + o1) =
                    __halves2half2(__float2half_rn(v1x), __float2half_rn(v1y));
            } else {
                if (bias) {
                    float bx = bias[c], by = bias[c + 1];
                    v0x += bx; v0y += by; v1x += bx; v1y += by;
                }
                if (res) {
                    float2 ra = *(const float2*)(res + o0);
                    float2 rb = *(const float2*)(res + o1);
                    v0x += ra.x; v0y += ra.y; v1x += rb.x; v1y += rb.y;
                }
                *(float2*)(C + o0) = make_float2(v0x, v0y);
                *(float2*)(C + o1) = make_float2(v1x, v1y);
            }
        }
    }
}

// ---------------------------------------------------------------------------
// qk via HMMA: W(fp16) = (qh_i . kh_j)*0.125*(1+dist). CTA per (b,h).
// ---------------------------------------------------------------------------
#define QKLD 72
#define QK_TILE (128 * QKLD)
#define QK_SMEM (2 * QK_TILE * 2)

__global__ __launch_bounds__(256, 2) void qk_mma_kernel(
    const __half* __restrict__ qkvh,
    const float* __restrict__ dist, __half* __restrict__ W)
{
    extern __shared__ __half smem[];
    const uint32_t sbase = smem_u32(smem);
    const int tid = threadIdx.x, lane = tid & 31, warp = tid >> 5;
    const int wm = warp & 1, wn = warp >> 1;
    const int b = blockIdx.x >> 4, h = blockIdx.x & 15;
    const size_t rowbase = (size_t)b * NTOK * PATCHDIM + h * DHEAD;

    const int offs[2] = { 0, DIMV };
#pragma unroll
    for (int t = 0; t < 2; t++) {
        uint32_t dbase = sbase + (uint32_t)(t * QK_TILE) * 2;
#pragma unroll
        for (int p = 0; p < 4; p++) {
            int q = tid + p * 256;
            int r = q >> 3, c = q & 7;
            cpa16(dbase + (uint32_t)(r * QKLD + c * 8) * 2,
                  qkvh + rowbase + (size_t)r * PATCHDIM + offs[t] + c * 8);
        }
    }
    cp_commit();
    cp_wait<0>();
    __syncthreads();

    float acc[4][4][4];
#pragma unroll
    for (int i = 0; i < 4; i++)
#pragma unroll
        for (int j = 0; j < 4; j++)
#pragma unroll
            for (int q = 0; q < 4; q++) acc[i][j][q] = 0.f;

    uint32_t sA  = sbase;
    uint32_t sB  = sbase + (uint32_t)QK_TILE * 2;
    const int arow = wm * 64 + (lane & 15);
    const int acolb = (lane >> 4) * 8;
    const int brow = wn * 32 + ((lane >> 4) * 8) + (lane & 7);
    const int bcolb = ((lane >> 3) & 1) * 8;

#pragma unroll
    for (int ks = 0; ks < 4; ks++) {
        const int acol = ks * 16 + acolb;
        const int bcol = ks * 16 + bcolb;
        uint32_t ah[4][4], bh[4][2];
#pragma unroll
        for (int mi = 0; mi < 4; mi++)
            ldsm4(ah[mi], sA + (uint32_t)((arow + mi * 16) * QKLD + acol) * 2);
#pragma unroll
        for (int gp = 0; gp < 2; gp++) {
            uint32_t rh[4];
            ldsm4(rh, sB + (uint32_t)((brow + gp * 16) * QKLD + bcol) * 2);
            bh[gp*2][0] = rh[0]; bh[gp*2][1] = rh[1];
            bh[gp*2+1][0] = rh[2]; bh[gp*2+1][1] = rh[3];
        }
#pragma unroll
        for (int mi = 0; mi < 4; mi++)
#pragma unroll
            for (int nj = 0; nj < 4; nj++)
                mma16816(acc[mi][nj], ah[mi], bh[nj]);
    }

    __half* Wb = W + (size_t)blockIdx.x * (NTOK * NTOK);
#pragma unroll
    for (int mi = 0; mi < 4; mi++) {
        int i0 = wm * 64 + mi * 16 + (lane >> 2);
#pragma unroll
        for (int nj = 0; nj < 4; nj++) {
            int j0 = wn * 32 + nj * 8 + (lane & 3) * 2;
#pragma unroll
            for (int rr = 0; rr < 2; rr++) {
                int i = i0 + rr * 8;
                float vx = acc[mi][nj][rr*2]   * 0.125f * (1.0f + dist[i * 128 + j0]);
                float vy = acc[mi][nj][rr*2+1] * 0.125f * (1.0f + dist[i * 128 + j0 + 1]);
                *(__half2*)(Wb + i * 128 + j0) =
                    __halves2half2(__float2half_rn(vx), __float2half_rn(vy));
            }
        }
    }
}

// ---------------------------------------------------------------------------
// Cross-head standardize (ddof=1) + softmax; reads fp16 W, emits fp16 P.
// ---------------------------------------------------------------------------
__global__ __launch_bounds__(128) void std_softmax_kernel(
    const __half* __restrict__ W, __half* __restrict__ Ph)
{
    int b = blockIdx.x >> 7, i = blockIdx.x & 127;
    int j = threadIdx.x;
    __shared__ float sm[NHEADS][128];

    size_t base = (size_t)b * (NHEADS * NTOK * NTOK) + (size_t)i * 128 + j;
    float vals[NHEADS];
    float s = 0.f;
#pragma unroll
    for (int h = 0; h < NHEADS; h++) {
        float v = __half2float(W[base + (size_t)h * (NTOK * NTOK)]);
        vals[h] = v; s += v;
    }
    float mu = s * (1.0f / 16.0f);
    float d2 = 0.f;
#pragma unroll
    for (int h = 0; h < NHEADS; h++) {
        float d = vals[h] - mu;
        d2 += d * d;
    }
    float inv = rsqrtf(d2 * (1.0f / 15.0f));
#pragma unroll
    for (int h = 0; h < NHEADS; h++) sm[h][j] = (vals[h] - mu) * inv;
    __syncthreads();

    int warp = j >> 5, lane = j & 31;
#pragma unroll
    for (int r = 0; r < 4; r++) {
        int h = warp * 4 + r;
        float v0 = sm[h][lane], v1 = sm[h][lane + 32];
        float v2 = sm[h][lane + 64], v3 = sm[h][lane + 96];
        float m = fmaxf(fmaxf(v0, v1), fmaxf(v2, v3));
#pragma unroll
        for (int o = 16; o; o >>= 1) m = fmaxf(m, __shfl_xor_sync(0xffffffffu, m, o));
        float e0 = expf(v0 - m), e1 = expf(v1 - m);
        float e2 = expf(v2 - m), e3 = expf(v3 - m);
        float sum = e0 + e1 + e2 + e3;
#pragma unroll
        for (int o = 16; o; o >>= 1) sum += __shfl_xor_sync(0xffffffffu, sum, o);
        float rs = 1.0f / sum;
        size_t wb = (size_t)b * (NHEADS * NTOK * NTOK) + (size_t)h * (NTOK * NTOK)
                  + (size_t)i * 128;
        Ph[wb + lane]      = __float2half_rn(e0 * rs);
        Ph[wb + lane + 32] = __float2half_rn(e1 * rs);
        Ph[wb + lane + 64] = __float2half_rn(e2 * rs);
        Ph[wb + lane + 96] = __float2half_rn(e3 * rs);
    }
}

// ---------------------------------------------------------------------------
// av via HMMA: O[i,h*64+d] = sum_j Ph[i,j]*Vh[j,d]. CTA per (b,h).
// ---------------------------------------------------------------------------
#define AVPLD 136
#define AVVLD 72
#define AVP_TILE (128 * AVPLD)
#define AVV_TILE (128 * AVVLD)
#define AV_SMEM ((AVP_TILE + AVV_TILE) * 2)

__global__ __launch_bounds__(256, 2) void av_mma_kernel(
    const __half* __restrict__ Ph, const __half* __restrict__ qkvh,
    __half* __restrict__ Oh)
{
    extern __shared__ __half smem[];
    const uint32_t sbase = smem_u32(smem);
    const int tid = threadIdx.x, lane = tid & 31, warp = tid >> 5;
    const int wm = warp & 3, wn = warp >> 2;
    const int b = blockIdx.x >> 4, h = blockIdx.x & 15;
    const size_t pbase = (size_t)blockIdx.x * (NTOK * NTOK);
    const size_t vbase = (size_t)b * NTOK * PATCHDIM + 2 * DIMV + h * DHEAD;

#pragma unroll
    for (int p = 0; p < 8; p++) {
        int q = tid + p * 256;
        int r = q >> 4, c = q & 15;
        cpa16(sbase + (uint32_t)(r * AVPLD + c * 8) * 2,
              Ph + pbase + (size_t)r * 128 + c * 8);
    }
    {
        uint32_t dbase = sbase + (uint32_t)AVP_TILE * 2;
#pragma unroll
        for (int p = 0; p < 4; p++) {
            int q = tid + p * 256;
            int j = q >> 3, c = q & 7;
            cpa16(dbase + (uint32_t)(j * AVVLD + c * 8) * 2,
                  qkvh + vbase + (size_t)j * PATCHDIM + c * 8);
        }
    }
    cp_commit();
    cp_wait<0>();
    __syncthreads();

    float acc[2][4][4];
#pragma unroll
    for (int i = 0; i < 2; i++)
#pragma unroll
        for (int j = 0; j < 4; j++)
#pragma unroll
            for (int q = 0; q < 4; q++) acc[i][j][q] = 0.f;

    uint32_t sA  = sbase;
    uint32_t sB  = sbase + (uint32_t)AVP_TILE * 2;
    const int arow = wm * 32 + (lane & 15);
    const int acolb = (lane >> 4) * 8;
    const int bjrow = lane & 15;
    const int bdcol = (lane >> 4) * 8;

#pragma unroll
    for (int kc = 0; kc < 8; kc++) {
        const int acol = kc * 16 + acolb;
        uint32_t ah[2][4], bh[4][2];
#pragma unroll
        for (int mi = 0; mi < 2; mi++)
            ldsm4(ah[mi], sA + (uint32_t)((arow + mi * 16) * AVPLD + acol) * 2);
#pragma unroll
        for (int gp = 0; gp < 2; gp++) {
            uint32_t rh[4];
            uint32_t off = (uint32_t)((kc * 16 + bjrow) * AVVLD
                                      + wn * 32 + gp * 16 + bdcol) * 2;
            ldsm4t(rh, sB + off);
            bh[gp*2][0] = rh[0]; bh[gp*2][1] = rh[1];
            bh[gp*2+1][0] = rh[2]; bh[gp*2+1][1] = rh[3];
        }
#pragma unroll
        for (int mi = 0; mi < 2; mi++)
#pragma unroll
            for (int nj = 0; nj < 4; nj++)
                mma16816(acc[mi][nj], ah[mi], bh[nj]);
    }

#pragma unroll
    for (int mi = 0; mi < 2; mi++) {
        int i0 = wm * 32 + mi * 16 + (lane >> 2);
#pragma unroll
        for (int nj = 0; nj < 4; nj++) {
            int d0 = wn * 32 + nj * 8 + (lane & 3) * 2;
#pragma unroll
            for (int rr = 0; rr < 2; rr++) {
                int i = i0 + rr * 8;
                size_t o = (size_t)(b * 128 + i) * DIMV + h * DHEAD + d0;
                *(__half2*)(Oh + o) =
                    __halves2half2(__float2half_rn(acc[mi][nj][rr*2]),
                                   __float2half_rn(acc[mi][nj][rr*2 + 1]));
            }
        }
    }
}

// ---------------------------------------------------------------------------
// Vectorized weight prep: 8 elems/thread, 16B stores.
// ---------------------------------------------------------------------------
__global__ void split8_kernel(const float4* __restrict__ X, uint4* __restrict__ H) {
    size_t i = (size_t)blockIdx.x * 256 + threadIdx.x;
    float4 a = X[i * 2], b = X[i * 2 + 1];
    H[i] = cvt8(a, b);
}

__global__ void extract_patches8_kernel(const float* __restrict__ img,
                                        uint4* __restrict__ H) {
    int i = blockIdx.x * 256 + threadIdx.x;
    int idx = i * 8;
    int col = idx % PATCHDIM;
    int row = idx / PATCHDIM;
    int b = row >> 7, t = row & 127;
    int h = t >> 4, w = t & 15;
    int c = col >> 10, r = col & 1023;
    int p = r >> 5, q = r & 31;
    const float* src = img + (((size_t)b * 3 + c) * 256 + h * 32 + p) * 512
                           + w * 32 + q;
    float4 a = *(const float4*)(src);
    float4 bb = *(const float4*)(src + 4);
    H[i] = cvt8(a, bb);
}

// ---------------------------------------------------------------------------
// Register-cached LayerNorms.
// ---------------------------------------------------------------------------
__device__ __forceinline__ void block_reduce2(float& s, float& ss) {
#pragma unroll
    for (int o = 16; o; o >>= 1) {
        s  += __shfl_xor_sync(0xffffffffu, s, o);
        ss += __shfl_xor_sync(0xffffffffu, ss, o);
    }
    __shared__ float sh[2][8];
    int w = threadIdx.x >> 5;
    if ((threadIdx.x & 31) == 0) { sh[0][w] = s; sh[1][w] = ss; }
    __syncthreads();
    if (threadIdx.x < 32) {
        float a = (threadIdx.x < 8) ? sh[0][threadIdx.x] : 0.f;
        float b = (threadIdx.x < 8) ? sh[1][threadIdx.x] : 0.f;
#pragma unroll
        for (int o = 4; o; o >>= 1) {
            a += __shfl_xor_sync(0xffffffffu, a, o);
            b += __shfl_xor_sync(0xffffffffu, b, o);
        }
        if (threadIdx.x == 0) { sh[0][0] = a; sh[1][0] = b; }
    }
    __syncthreads();
    s = sh[0][0]; ss = sh[1][0];
}

__global__ __launch_bounds__(256) void ln_half_kernel(
    const float* __restrict__ x, const float* __restrict__ g,
    const float* __restrict__ beta, __half* __restrict__ H)
{
    size_t base = (size_t)blockIdx.x * DIMV;
    int t = threadIdx.x;
    float4 xv = *(const float4*)(x + base + t * 4);
    float s  = xv.x + xv.y + xv.z + xv.w;
    float ss = xv.x*xv.x + xv.y*xv.y + xv.z*xv.z + xv.w*xv.w;
    block_reduce2(s, ss);
    float mu = s * (1.0f / DIMV);
    float rstd = rsqrtf(ss * (1.0f / DIMV) - mu * mu + LN_EPS);
    float4 gv = *(const float4*)(g + t * 4);
    float4 bv = *(const float4*)(beta + t * 4);
    float o0 = (xv.x - mu) * rstd * gv.x + bv.x;
    float o1 = (xv.y - mu) * rstd * gv.y + bv.y;
    float o2 = (xv.z - mu) * rstd * gv.z + bv.z;
    float o3 = (xv.w - mu) * rstd * gv.w + bv.w;
    __half2 h0 = __halves2half2(__float2half_rn(o0), __float2half_rn(o1));
    __half2 h1 = __halves2half2(__float2half_rn(o2), __float2half_rn(o3));
    uint2 u; u.x = *(uint32_t*)&h0; u.y = *(uint32_t*)&h1;
    *(uint2*)(H + base + t * 4) = u;
}

__global__ __launch_bounds__(256) void ln_addpos_kernel(
    const float* __restrict__ x, const float* __restrict__ g,
    const float* __restrict__ beta, const float* __restrict__ sph_pos,
    const float* __restrict__ pos_w, const float* __restrict__ pos_b,
    float* __restrict__ y)
{
    size_t base = (size_t)blockIdx.x * DIMV;
    int t = threadIdx.x;
    float4 xv = *(const float4*)(x + base + t * 4);
    float s  = xv.x + xv.y + xv.z + xv.w;
    float ss = xv.x*xv.x + xv.y*xv.y + xv.z*xv.z + xv.w*xv.w;
    block_reduce2(s, ss);
    float mu = s * (1.0f / DIMV);
    float rstd = rsqrtf(ss * (1.0f / DIMV) - mu * mu + LN_EPS);
    int tok = blockIdx.x & 127;
    float p0 = sph_pos[tok * 2], p1 = sph_pos[tok * 2 + 1];
    float4 gv = *(const float4*)(g + t * 4);
    float4 bv = *(const float4*)(beta + t * 4);
    float4 w0 = *(const float4*)(pos_w + t * 4);
    float4 w1 = *(const float4*)(pos_w + 1024 + t * 4);
    float4 pb = *(const float4*)(pos_b + t * 4);
    float4 o;
    o.x = (xv.x - mu) * rstd * gv.x + bv.x + p0 * w0.x + p1 * w1.x + pb.x;
    o.y = (xv.y - mu) * rstd * gv.y + bv.y + p0 * w0.y + p1 * w1.y + pb.y;
    o.z = (xv.z - mu) * rstd * gv.z + bv.z + p0 * w0.z + p1 * w1.z + pb.z;
    o.w = (xv.w - mu) * rstd * gv.w + bv.w + p0 * w0.w + p1 * w1.w + pb.w;
    *(float4*)(y + base + t * 4) = o;
}

// ---------------------------------------------------------------------------
// Fused out-LN (D=3072) + reassemble. One block per token row.
// ---------------------------------------------------------------------------
__global__ __launch_bounds__(256) void ln_reassemble_kernel(
    const float* __restrict__ x, const float* __restrict__ g,
    const float* __restrict__ beta, float* __restrict__ out)
{
    __shared__ float sy[PATCHDIM];
    int row = blockIdx.x;
    size_t base = (size_t)row * PATCHDIM;
    int t = threadIdx.x;
    float4 xv[3];
    float s = 0.f, ss = 0.f;
#pragma unroll
    for (int k = 0; k < 3; k++) {
        xv[k] = *(const float4*)(x + base + k * 1024 + t * 4);
        s  += xv[k].x + xv[k].y + xv[k].z + xv[k].w;
        ss += xv[k].x*xv[k].x + xv[k].y*xv[k].y + xv[k].z*xv[k].z + xv[k].w*xv[k].w;
    }
    block_reduce2(s, ss);
    float mu = s * (1.0f / PATCHDIM);
    float rstd = rsqrtf(ss * (1.0f / PATCHDIM) - mu * mu + LN_EPS);
#pragma unroll
    for (int k = 0; k < 3; k++) {
        float4 gv = *(const float4*)(g + k * 1024 + t * 4);
        float4 bv = *(const float4*)(beta + k * 1024 + t * 4);
        float4 o;
        o.x = (xv[k].x - mu) * rstd * gv.x + bv.x;
        o.y = (xv[k].y - mu) * rstd * gv.y + bv.y;
        o.z = (xv[k].z - mu) * rstd * gv.z + bv.z;
        o.w = (xv[k].w - mu) * rstd * gv.w + bv.w;
        *(float4*)(sy + k * 1024 + t * 4) = o;
    }
    __syncthreads();

    int b = row >> 7, tk = row & 127;
    int h = tk >> 4, w = tk & 15;
    for (int oidx = t; oidx < PATCHDIM; oidx += 256) {
        int c  = oidx >> 10;
        int p1 = (oidx >> 5) & 31;
        int p2 = oidx & 31;
        float v = sy[(p1 * 32 + p2) * 3 + c];
        out[(((size_t)b * 3 + c) * 256 + h * 32 + p1) * 512 + w * 32 + p2] = v;
    }
}

// ---------------------------------------------------------------------------
// Host launcher
// ---------------------------------------------------------------------------
extern "C" void kernel_launch(void* const* d_in, const int* in_sizes, int n_in,
                              void* d_out, int out_size)
{
    const float* img      = (const float*)d_in[0];
    const float* sph_pos  = (const float*)d_in[1];
    const float* sph_dist = (const float*)d_in[2];
    const float* conv_w   = (const float*)d_in[3];
    const float* conv_b   = (const float*)d_in[4];
    const float* nl_ln1_g = (const float*)d_in[5];
    const float* nl_ln1_b = (const float*)d_in[6];
    const float* nl_w     = (const float*)d_in[7];
    const float* nl_b     = (const float*)d_in[8];
    const float* nl_ln2_g = (const float*)d_in[9];
    const float* nl_ln2_b = (const float*)d_in[10];
    const float* pos_w    = (const float*)d_in[11];
    const float* pos_b    = (const float*)d_in[12];
    const float* ln_g     = (const float*)d_in[13];
    const float* ln_b     = (const float*)d_in[14];
    const float* wqkv     = (const float*)d_in[15];
    const float* wo       = (const float*)d_in[16];
    const float* wo_b     = (const float*)d_in[17];
    const float* tr_ln_g  = (const float*)d_in[18];
    const float* tr_ln_b  = (const float*)d_in[19];
    const float* exp_w    = (const float*)d_in[20];
    const float* exp_b    = (const float*)d_in[21];
    const float* out_ln_g = (const float*)d_in[22];
    const float* out_ln_b = (const float*)d_in[23];

    float *big, *x;
    __half *w;
    cudaGetSymbolAddress((void**)&big, g_big);
    cudaGetSymbolAddress((void**)&x,   g_x);
    cudaGetSymbolAddress((void**)&w,   g_w);
    __half *Xph, *qkvh, *hh, *oh, *ph;
    __half *cwh, *nlwh, *qwh, *owh, *ewh;
    cudaGetSymbolAddress((void**)&Xph, g_Xph);
    cudaGetSymbolAddress((void**)&qkvh, g_qkvh);
    cudaGetSymbolAddress((void**)&hh,  g_hh);
    cudaGetSymbolAddress((void**)&oh,  g_oh);
    cudaGetSymbolAddress((void**)&ph,  g_ph);
    cudaGetSymbolAddress((void**)&cwh, g_cwh);
    cudaGetSymbolAddress((void**)&nlwh, g_nlwh);
    cudaGetSymbolAddress((void**)&qwh, g_qwh);
    cudaGetSymbolAddress((void**)&owh, g_owh);
    cudaGetSymbolAddress((void**)&ewh, g_ewh);

    cudaFuncSetAttribute(hmma_gemm_kernel<0, true>,
                         cudaFuncAttributeMaxDynamicSharedMemorySize, HG_SMEM);
    cudaFuncSetAttribute(hmma_gemm_kernel<0, false>,
                         cudaFuncAttributeMaxDynamicSharedMemorySize, HG_SMEM);
    cudaFuncSetAttribute(hmma_gemm256_kernel<0>,
                         cudaFuncAttributeMaxDynamicSharedMemorySize, HG2_SMEM);
    cudaFuncSetAttribute(hmma_gemm256_kernel<2>,
                         cudaFuncAttributeMaxDynamicSharedMemorySize, HG2_SMEM);
    cudaFuncSetAttribute(qk_mma_kernel,
                         cudaFuncAttributeMaxDynamicSharedMemorySize, QK_SMEM);
    cudaFuncSetAttribute(av_mma_kernel,
                         cudaFuncAttributeMaxDynamicSharedMemorySize, AV_SMEM);

    // ---- prep: vectorized stream conversions ----
    split8_kernel<<<DIMV * PATCHDIM / 2048, 256>>>((const float4*)conv_w, (uint4*)cwh);
    extract_patches8_kernel<<<ROWS * PATCHDIM / 2048, 256>>>(img, (uint4*)Xph);
    split8_kernel<<<DIMV * DIMV / 2048, 256>>>((const float4*)nl_w, (uint4*)nlwh);
    split8_kernel<<<DEPTH * DIMV * PATCHDIM / 2048, 256>>>((const float4*)wqkv, (uint4*)qwh);
    split8_kernel<<<DEPTH * DIMV * DIMV / 2048, 256>>>((const float4*)wo, (uint4*)owh);
    hmma_gemm_kernel<0, true><<<dim3(DIMV/128, ROWS/128), 256, HG_SMEM>>>(
        Xph, cwh, conv_b, nullptr, x, nullptr, ROWS, DIMV, PATCHDIM);
    split8_kernel<<<DIMV * PATCHDIM / 2048, 256>>>((const float4*)exp_w, (uint4*)ewh);

    // ---- norm_linear + positional embedding ----
    ln_half_kernel<<<ROWS, 256>>>(x, nl_ln1_g, nl_ln1_b, hh);
    hmma_gemm_kernel<0, false><<<dim3(DIMV/128, ROWS/128), 256, HG_SMEM>>>(
        hh, nlwh, nl_b, nullptr, x, nullptr, ROWS, DIMV, DIMV);
    ln_addpos_kernel<<<ROWS, 256>>>(x, nl_ln2_g, nl_ln2_b, sph_pos, pos_w, pos_b, x);

    // ---- transformer layers ----
    for (int l = 0; l < DEPTH; l++) {
        ln_half_kernel<<<ROWS, 256>>>(x, ln_g + l * DIMV, ln_b + l * DIMV, hh);
        hmma_gemm256_kernel<2><<<dim3(PATCHDIM/256, ROWS/128), 256, HG2_SMEM>>>(
            hh, qwh + (size_t)l * DIMV * PATCHDIM,
            nullptr, nullptr, nullptr, qkvh, ROWS, PATCHDIM, DIMV);
        qk_mma_kernel<<<BATCH * NHEADS, 256, QK_SMEM>>>(qkvh, sph_dist, w);
        std_softmax_kernel<<<BATCH * NTOK, 128>>>(w, ph);
        av_mma_kernel<<<BATCH * NHEADS, 256, AV_SMEM>>>(ph, qkvh, oh);
        hmma_gemm_kernel<0, false><<<dim3(DIMV/128, ROWS/128), 256, HG_SMEM>>>(
            oh, owh + (size_t)l * DIMV * DIMV,
            wo_b + l * DIMV, x, x, nullptr, ROWS, DIMV, DIMV);
    }

    // ---- final LN + expand + fused out-LN/reassembly ----
    ln_half_kernel<<<ROWS, 256>>>(x, tr_ln_g, tr_ln_b, hh);
    hmma_gemm256_kernel<0><<<dim3(PATCHDIM/256, ROWS/128), 256, HG2_SMEM>>>(
        hh, ewh, exp_b, nullptr, big, nullptr, ROWS, PATCHDIM, DIMV);
    ln_reassemble_kernel<<<ROWS, 256>>>(big, out_ln_g, out_ln_b, (float*)d_out);
}